// round 11
// baseline (speedup 1.0000x reference)
#include <cuda_runtime.h>
#include <cuda_bf16.h>
#include <math.h>

#define BSZ 1000
#define TSZ 100
#define ISZ 264
#define HSZ 100
#define G4  400   // 4*H
#define KPA 272   // padded K for phase A (264 -> 17*16)
#define KPL 112   // padded K for loss GEMMs (100 -> 7*16)

// ---------------- device scratch (static: no allocation allowed) ----------
__device__ float g_X[(size_t)BSZ * TSZ * G4];       // encoder gate inputs fp32
__device__ float g_henc[BSZ * HSZ];
__device__ float g_cenc[BSZ * HSZ];
__device__ float g_G0[2][BSZ * G4];                 // decoder step-0 gates
__device__ float g_Weff[2][G4 * HSZ];
__device__ float g_beff[2][G4];
__device__ float g_loss[2];

// bf16 split operands
__device__ __nv_bfloat16 g_srch[(size_t)BSZ * TSZ * KPA];
__device__ __nv_bfloat16 g_srcl[(size_t)BSZ * TSZ * KPA];
__device__ __nv_bfloat16 g_wihh[G4 * KPA];
__device__ __nv_bfloat16 g_wihl[G4 * KPA];
__device__ __nv_bfloat16 g_fcwh[2][ISZ * KPL];
__device__ __nv_bfloat16 g_fcwl[2][ISZ * KPL];
__device__ __nv_bfloat16 g_hdh[2][(size_t)BSZ * TSZ * KPL];  // decoder h, split
__device__ __nv_bfloat16 g_hdl[2][(size_t)BSZ * TSZ * KPL];

// ---------------- fast activations (ex2/rcp approx: ~2^-22 rel err) --------
__device__ __forceinline__ float ex2f(float x) {
    float r; asm("ex2.approx.f32 %0, %1;" : "=f"(r) : "f"(x)); return r;
}
__device__ __forceinline__ float rcpf(float x) {
    float r; asm("rcp.approx.f32 %0, %1;" : "=f"(r) : "f"(x)); return r;
}
__device__ __forceinline__ float sigf(float x) {
    return rcpf(1.f + ex2f(-1.4426950408889634f * x));
}
__device__ __forceinline__ float tanhf_fast(float x) {
    return fmaf(2.f, rcpf(1.f + ex2f(-2.8853900817779268f * x)), -1.f);
}

// ---------------- small kernels -------------------------------------------
__global__ void finalize_kernel(const float* loss, float* out, float inv) {
    out[0] = loss[0] * inv;
    out[1] = loss[1] * inv;
}

// fp32 -> (bf16 hi, bf16 lo), K padded to Kp, templated, float4 vectorized.
template <int K, int Kp>
__global__ __launch_bounds__(256) void cvt_split_t(
    const float* __restrict__ x, __nv_bfloat16* __restrict__ h,
    __nv_bfloat16* __restrict__ l, int rows)
{
    const int Kp4 = Kp / 4;
    int idx = blockIdx.x * 256 + threadIdx.x;
    if (idx >= rows * Kp4) return;
    int r = idx / Kp4;
    int k4 = (idx - r * Kp4) * 4;
    float4 v;
    if (k4 + 3 < K) {
        v = *(const float4*)(x + (size_t)r * K + k4);
    } else {
        float tmp[4] = {0.f, 0.f, 0.f, 0.f};
        #pragma unroll
        for (int e = 0; e < 4; ++e)
            if (k4 + e < K) tmp[e] = x[(size_t)r * K + k4 + e];
        v = make_float4(tmp[0], tmp[1], tmp[2], tmp[3]);
    }
    float vv[4] = {v.x, v.y, v.z, v.w};
    __nv_bfloat16 hh[4], ll[4];
    #pragma unroll
    for (int e = 0; e < 4; ++e) {
        hh[e] = __float2bfloat16(vv[e]);
        ll[e] = __float2bfloat16(vv[e] - __bfloat162float(hh[e]));
    }
    *(uint2*)(h + (size_t)idx * 4) = *(const uint2*)hh;
    *(uint2*)(l + (size_t)idx * 4) = *(const uint2*)ll;
}

// Both decoder folds in one launch: blockIdx.y selects decoder.
__global__ __launch_bounds__(128) void fold2_kernel(
    const float* __restrict__ pd_Wih, const float* __restrict__ pd_Whh,
    const float* __restrict__ pd_fcW, const float* __restrict__ pd_fcb,
    const float* __restrict__ pd_bih, const float* __restrict__ pd_bhh,
    const float* __restrict__ rd_Wih, const float* __restrict__ rd_Whh,
    const float* __restrict__ rd_fcW, const float* __restrict__ rd_fcb,
    const float* __restrict__ rd_bih, const float* __restrict__ rd_bhh,
    float* __restrict__ Weff, float* __restrict__ beff, float* __restrict__ loss)
{
    const int did = blockIdx.y;
    const float* Wih = did ? rd_Wih : pd_Wih;
    const float* Whh = did ? rd_Whh : pd_Whh;
    const float* fcW = did ? rd_fcW : pd_fcW;
    const float* fcb = did ? rd_fcb : pd_fcb;
    const float* bih = did ? rd_bih : pd_bih;
    const float* bhh = did ? rd_bhh : pd_bhh;
    float* We = Weff + (size_t)did * G4 * HSZ;
    float* be = beff + (size_t)did * G4;

    int j = blockIdx.x;
    int tid = threadIdx.x;
    if (blockIdx.x == 0 && did == 0 && tid < 2) loss[tid] = 0.f;

    __shared__ float swih[ISZ];
    __shared__ float red[128];
    for (int i = tid; i < ISZ; i += 128) swih[i] = Wih[j * ISZ + i];
    __syncthreads();
    if (tid < HSZ) {
        float acc = Whh[j * HSZ + tid];
        #pragma unroll 4
        for (int i = 0; i < ISZ; ++i)
            acc = fmaf(swih[i], fcW[i * HSZ + tid], acc);
        We[j * HSZ + tid] = acc;
    }
    float p = 0.f;
    for (int i = tid; i < ISZ; i += 128) p = fmaf(swih[i], fcb[i], p);
    red[tid] = p;
    __syncthreads();
    for (int s = 64; s > 0; s >>= 1) {
        if (tid < s) red[tid] += red[tid + s];
        __syncthreads();
    }
    if (tid == 0) be[j] = bih[j] + bhh[j] + red[0];
}

// ---------------- SIMT NT GEMM for the two small G0 GEMMs ------------------
#define AP 264
#define BP 68
__global__ __launch_bounds__(256) void gemm_g0(
    const float* __restrict__ A,
    const float* __restrict__ B0, const float* __restrict__ B1,
    const float* __restrict__ b10, const float* __restrict__ b11,
    const float* __restrict__ b20, const float* __restrict__ b21,
    float* __restrict__ Cbase, int M, int N, int K)
{
    const int did = blockIdx.z;
    const float* B = did ? B1 : B0;
    const float* bias1 = did ? b11 : b10;
    const float* bias2 = did ? b21 : b20;
    float* C = Cbase + (size_t)did * M * N;

    __shared__ float As[8 * AP];
    __shared__ float Bs[8 * BP];
    const int tid = threadIdx.x;
    const int tx = tid & 7;
    const int ty = tid >> 3;
    const int m0 = blockIdx.y * 256, n0 = blockIdx.x * 64;

    float acc[8][8];
    #pragma unroll
    for (int i = 0; i < 8; ++i)
        #pragma unroll
        for (int j = 0; j < 8; ++j) acc[i][j] = 0.f;

    const int am = m0 + tid;
    const int br = tid >> 2;
    const int bc = (tid & 3) * 2;

    for (int k0 = 0; k0 < K; k0 += 8) {
        #pragma unroll
        for (int j = 0; j < 8; ++j) {
            int k = k0 + j;
            As[j * AP + tid] = (am < M && k < K) ? A[(size_t)am * K + k] : 0.f;
        }
        {
            int n = n0 + br;
            #pragma unroll
            for (int j = 0; j < 2; ++j) {
                int k = k0 + bc + j;
                Bs[(bc + j) * BP + br] = (n < N && k < K) ? B[(size_t)n * K + k] : 0.f;
            }
        }
        __syncthreads();
        #pragma unroll
        for (int kk = 0; kk < 8; ++kk) {
            float4 a0 = *(const float4*)(As + kk * AP + ty * 8);
            float4 a1 = *(const float4*)(As + kk * AP + ty * 8 + 4);
            float4 b0 = *(const float4*)(Bs + kk * BP + tx * 8);
            float4 b1 = *(const float4*)(Bs + kk * BP + tx * 8 + 4);
            float av[8] = {a0.x, a0.y, a0.z, a0.w, a1.x, a1.y, a1.z, a1.w};
            float bv[8] = {b0.x, b0.y, b0.z, b0.w, b1.x, b1.y, b1.z, b1.w};
            #pragma unroll
            for (int i = 0; i < 8; ++i)
                #pragma unroll
                for (int j = 0; j < 8; ++j)
                    acc[i][j] = fmaf(av[i], bv[j], acc[i][j]);
        }
        __syncthreads();
    }

    #pragma unroll
    for (int i = 0; i < 8; ++i) {
        int m = m0 + ty * 8 + i;
        if (m < M) {
            #pragma unroll
            for (int j = 0; j < 8; ++j) {
                int n = n0 + tx * 8 + j;
                if (n < N) C[(size_t)m * N + n] = acc[i][j] + bias1[n] + bias2[n];
            }
        }
    }
}

// ---------------- tensor-core split-bf16 NT GEMM core ----------------------
// CTA tile 256m x 64n, 8 warps stacked in m; each warp 32m x 64n.
// Per warp-iter: 12 LDSM.x4 vs 48 HMMA (L1-traffic/MMA reduced 1.4x vs R10).
#define SAP 24

__device__ __forceinline__ void mma16816(float* d, const unsigned* a, const unsigned* b) {
    asm volatile(
        "mma.sync.aligned.m16n8k16.row.col.f32.bf16.bf16.f32 "
        "{%0,%1,%2,%3},{%4,%5,%6,%7},{%8,%9},{%0,%1,%2,%3};"
        : "+f"(d[0]), "+f"(d[1]), "+f"(d[2]), "+f"(d[3])
        : "r"(a[0]), "r"(a[1]), "r"(a[2]), "r"(a[3]), "r"(b[0]), "r"(b[1]));
}

__device__ __forceinline__ void ldsm_x4(unsigned* r, unsigned addr) {
    asm volatile(
        "ldmatrix.sync.aligned.m8n8.x4.shared.b16 {%0,%1,%2,%3}, [%4];"
        : "=r"(r[0]), "=r"(r[1]), "=r"(r[2]), "=r"(r[3]) : "r"(addr));
}

struct Bf16GemmSmem {
    __nv_bfloat16 Ash[2][256 * SAP];
    __nv_bfloat16 Asl[2][256 * SAP];
    __nv_bfloat16 Bsh[2][64 * SAP];
    __nv_bfloat16 Bsl[2][64 * SAP];
    float red[256];
};

__device__ __forceinline__ void bf16_mainloop(
    Bf16GemmSmem* sm, float d[2][8][4],
    const __nv_bfloat16* Ah, const __nv_bfloat16* Al, int lda,
    const __nv_bfloat16* Bh, const __nv_bfloat16* Bl, int ldb,
    int m0, int n0, int M, int N, int Kp)
{
    const int tid = threadIdx.x;
    const int lane = tid & 31;
    const int wy = tid >> 5;           // 0..7, warp owns rows [wy*32, wy*32+32)

    // A load: thread -> one row, full 16-k slice (2x uint4 each for hi/lo)
    const int ar = tid;                // 0..255
    const int gm = m0 + ar;
    // B load: 64 rows x 2 halves x {hi,lo} = 256 slots
    const int brow = tid >> 2;
    const int bsel = (tid >> 1) & 1;   // 0 = hi, 1 = lo
    const int bh8 = (tid & 1) * 8;
    const int gn = n0 + brow;
    const __nv_bfloat16* srcB = bsel ? Bl : Bh;

    // ldmatrix lane-address offsets (bytes)
    const unsigned aoff =
        ((unsigned)((wy * 32 + ((lane >> 3) & 1) * 8 + (lane & 7)) * SAP
                    + (lane >> 4) * 8)) * 2u;
    const unsigned boff =
        ((unsigned)((((lane >> 4) & 1) * 8 + (lane & 7)) * SAP
                    + ((lane >> 3) & 1) * 8)) * 2u;

    const unsigned ashb = (unsigned)__cvta_generic_to_shared(sm->Ash[0]);
    const unsigned aslb = (unsigned)__cvta_generic_to_shared(sm->Asl[0]);
    const unsigned bshb = (unsigned)__cvta_generic_to_shared(sm->Bsh[0]);
    const unsigned bslb = (unsigned)__cvta_generic_to_shared(sm->Bsl[0]);
    const unsigned abuf = 256 * SAP * 2;
    const unsigned bbuf = 64 * SAP * 2;
    const unsigned ni2step = 16 * SAP * 2;   // two ni strips (16 n rows)
    const unsigned mistep = 16 * SAP * 2;    // one mi strip (16 m rows)

    const uint4 zv = make_uint4(0, 0, 0, 0);
    uint4 vh0 = zv, vh1 = zv, vl0 = zv, vl1 = zv, vb = zv;
    if (gm < M) {
        const __nv_bfloat16* ap = Ah + (size_t)gm * lda;
        const __nv_bfloat16* lp = Al + (size_t)gm * lda;
        vh0 = *(const uint4*)(ap);
        vh1 = *(const uint4*)(ap + 8);
        vl0 = *(const uint4*)(lp);
        vl1 = *(const uint4*)(lp + 8);
    }
    if (gn < N) vb = *(const uint4*)(srcB + (size_t)gn * ldb + bh8);

    const int niter = Kp / 16;
    for (int i = 0; i < niter; ++i) {
        const unsigned cur = (unsigned)(i & 1);
        *(uint4*)&sm->Ash[cur][ar * SAP] = vh0;
        *(uint4*)&sm->Ash[cur][ar * SAP + 8] = vh1;
        *(uint4*)&sm->Asl[cur][ar * SAP] = vl0;
        *(uint4*)&sm->Asl[cur][ar * SAP + 8] = vl1;
        __nv_bfloat16* dstB = bsel ? sm->Bsl[cur] : sm->Bsh[cur];
        *(uint4*)&dstB[brow * SAP + bh8] = vb;
        __syncthreads();

        if (i + 1 < niter) {
            int kn = (i + 1) * 16;
            vh0 = zv; vh1 = zv; vl0 = zv; vl1 = zv; vb = zv;
            if (gm < M) {
                const __nv_bfloat16* ap = Ah + (size_t)gm * lda + kn;
                const __nv_bfloat16* lp = Al + (size_t)gm * lda + kn;
                vh0 = *(const uint4*)(ap);
                vh1 = *(const uint4*)(ap + 8);
                vl0 = *(const uint4*)(lp);
                vl1 = *(const uint4*)(lp + 8);
            }
            if (gn < N) vb = *(const uint4*)(srcB + (size_t)gn * ldb + kn + bh8);
        }

        // B fragments: 4 LDSM.x4 per hi/lo cover all 8 ni strips
        unsigned bhf[8][2], blf[8][2];
        #pragma unroll
        for (int p = 0; p < 4; ++p) {
            unsigned r[4];
            ldsm_x4(r, bshb + cur * bbuf + boff + p * ni2step);
            bhf[2 * p][0] = r[0]; bhf[2 * p][1] = r[1];
            bhf[2 * p + 1][0] = r[2]; bhf[2 * p + 1][1] = r[3];
        }
        #pragma unroll
        for (int p = 0; p < 4; ++p) {
            unsigned r[4];
            ldsm_x4(r, bslb + cur * bbuf + boff + p * ni2step);
            blf[2 * p][0] = r[0]; blf[2 * p][1] = r[1];
            blf[2 * p + 1][0] = r[2]; blf[2 * p + 1][1] = r[3];
        }
        #pragma unroll
        for (int mi = 0; mi < 2; ++mi) {
            unsigned ahf[4], alf[4];
            ldsm_x4(ahf, ashb + cur * abuf + aoff + mi * mistep);
            ldsm_x4(alf, aslb + cur * abuf + aoff + mi * mistep);
            #pragma unroll
            for (int ni = 0; ni < 8; ++ni) {
                mma16816(d[mi][ni], ahf, bhf[ni]);
                mma16816(d[mi][ni], ahf, blf[ni]);
                mma16816(d[mi][ni], alf, bhf[ni]);
            }
        }
    }
    __syncthreads();
}

// Phase-A variant: stores C with two biases.
__global__ __launch_bounds__(256, 2) void gemm_bf16_store(
    const __nv_bfloat16* __restrict__ Ah, const __nv_bfloat16* __restrict__ Al, int lda,
    const __nv_bfloat16* __restrict__ Bh, const __nv_bfloat16* __restrict__ Bl, int ldb,
    const float* __restrict__ bias1, const float* __restrict__ bias2,
    float* __restrict__ C, int M, int N, int Kp)
{
    extern __shared__ char smraw[];
    Bf16GemmSmem* sm = (Bf16GemmSmem*)smraw;
    const int tid = threadIdx.x;
    const int lane = tid & 31;
    const int wy = tid >> 5;
    const int g = lane >> 2, t = lane & 3;
    const int m0 = blockIdx.y * 256, n0 = blockIdx.x * 64;

    float d[2][8][4];
    #pragma unroll
    for (int mi = 0; mi < 2; ++mi)
        #pragma unroll
        for (int ni = 0; ni < 8; ++ni)
            #pragma unroll
            for (int e = 0; e < 4; ++e) d[mi][ni][e] = 0.f;

    bf16_mainloop(sm, d, Ah, Al, lda, Bh, Bl, ldb, m0, n0, M, N, Kp);

    #pragma unroll
    for (int mi = 0; mi < 2; ++mi) {
        #pragma unroll
        for (int rr = 0; rr < 2; ++rr) {
            int m = m0 + wy * 32 + mi * 16 + rr * 8 + g;
            if (m >= M) continue;
            #pragma unroll
            for (int ni = 0; ni < 8; ++ni) {
                int n = n0 + ni * 8 + 2 * t;
                if (n + 1 < N) {
                    float v0 = d[mi][ni][rr * 2 + 0] + bias1[n] + bias2[n];
                    float v1 = d[mi][ni][rr * 2 + 1] + bias1[n + 1] + bias2[n + 1];
                    *(float2*)(C + (size_t)m * N + n) = make_float2(v0, v1);
                } else if (n < N) {
                    C[(size_t)m * N + n] = d[mi][ni][rr * 2 + 0] + bias1[n] + bias2[n];
                }
            }
        }
    }
}

// Merged loss variant: blockIdx.z selects decoder stream; fused MSE epilogue.
__global__ __launch_bounds__(256, 2) void gemm_bf16_loss2(
    const __nv_bfloat16* __restrict__ Ahb, const __nv_bfloat16* __restrict__ Alb,
    const __nv_bfloat16* __restrict__ Bhb, const __nv_bfloat16* __restrict__ Blb,
    const float* __restrict__ fcb0, const float* __restrict__ fcb1,
    const float* __restrict__ trg, const float* __restrict__ src,
    float* __restrict__ loss, int M, int N)
{
    extern __shared__ char smraw[];
    Bf16GemmSmem* sm = (Bf16GemmSmem*)smraw;
    const int did = blockIdx.z;
    const __nv_bfloat16* Ah = Ahb + (size_t)did * M * KPL;
    const __nv_bfloat16* Al = Alb + (size_t)did * M * KPL;
    const __nv_bfloat16* Bh = Bhb + (size_t)did * N * KPL;
    const __nv_bfloat16* Bl = Blb + (size_t)did * N * KPL;
    const float* bias = did ? fcb1 : fcb0;
    const float* ref = did ? src : trg;
    float* lossOut = did ? (loss + 0) : (loss + 1);
    const int revT = did ? TSZ : 0;

    const int tid = threadIdx.x;
    const int lane = tid & 31;
    const int wy = tid >> 5;
    const int g = lane >> 2, t = lane & 3;
    const int m0 = blockIdx.y * 256, n0 = blockIdx.x * 64;

    float d[2][8][4];
    #pragma unroll
    for (int mi = 0; mi < 2; ++mi)
        #pragma unroll
        for (int ni = 0; ni < 8; ++ni)
            #pragma unroll
            for (int e = 0; e < 4; ++e) d[mi][ni][e] = 0.f;

    bf16_mainloop(sm, d, Ah, Al, KPL, Bh, Bl, KPL, m0, n0, M, N, KPL);

    float ls = 0.f;
    #pragma unroll
    for (int mi = 0; mi < 2; ++mi) {
        #pragma unroll
        for (int rr = 0; rr < 2; ++rr) {
            int m = m0 + wy * 32 + mi * 16 + rr * 8 + g;
            if (m >= M) continue;
            const float* rrow;
            if (revT > 0) {
                int b = m / revT, tt = m - b * revT;
                rrow = ref + ((size_t)b * revT + (revT - 1 - tt)) * N;
            } else {
                rrow = ref + (size_t)m * N;
            }
            #pragma unroll
            for (int ni = 0; ni < 8; ++ni) {
                int n = n0 + ni * 8 + 2 * t;
                #pragma unroll
                for (int e = 0; e < 2; ++e) {
                    if (n + e < N) {
                        float v = d[mi][ni][rr * 2 + e] + bias[n + e];
                        float diff = v - rrow[n + e];
                        ls = fmaf(diff, diff, ls);
                    }
                }
            }
        }
    }
    sm->red[tid] = ls;
    __syncthreads();
    for (int s = 128; s > 0; s >>= 1) {
        if (tid < s) sm->red[tid] += sm->red[tid + s];
        __syncthreads();
    }
    if (tid == 0) atomicAdd(lossOut, sm->red[0]);
}

// ---------------- LSTM recurrence kernels ----------------------------------
#define NB 7
#define NT_RNN 416
#define RNN_SMEM_F (40000 + 800 + 800 + 3600)

__global__ __launch_bounds__(NT_RNN, 1) void rnn_enc(
    const float* __restrict__ X, const float* __restrict__ Whh,
    float* __restrict__ hf, float* __restrict__ cf)
{
    extern __shared__ float s[];
    float* sW  = s;
    float* sHa = s + 40000;
    float* sHb = sHa + 800;
    float* sG  = sHb + 800;
    const int tid = threadIdx.x;
    const int b0 = blockIdx.x * NB;

    for (int i = tid; i < 10000; i += NT_RNN)
        ((float4*)sW)[i] = ((const float4*)Whh)[i];
    for (int i = tid; i < 800; i += NT_RNN) sHa[i] = 0.f;
    __syncthreads();

    const int i0 = tid, i1 = tid + NT_RNN;
    const int k0c = i0 % 100, b0c = i0 / 100;
    const int k1c = i1 % 100, b1c = i1 / 100;
    const bool v0 = (i0 < NB * 100), v1 = (i1 < NB * 100);
    float c0r = 0.f, c1r = 0.f, h0r = 0.f, h1r = 0.f;

    int bidx[NB];
    #pragma unroll
    for (int b = 0; b < NB; ++b) {
        int bb = b0 + b; if (bb > BSZ - 1) bb = BSZ - 1;
        bidx[b] = bb;
    }

    for (int t = 0; t < TSZ; ++t) {
        const float* hin = (t & 1) ? sHb : sHa;
        float* hout = (t & 1) ? sHa : sHb;
        if (tid < 400) {
            const int j = tid;
            float xr[NB];
            #pragma unroll
            for (int b = 0; b < NB; ++b)
                xr[b] = X[((size_t)bidx[b] * TSZ + t) * G4 + j];
            float acc[NB];
            #pragma unroll
            for (int b = 0; b < NB; ++b) acc[b] = 0.f;
            const float4* wj = (const float4*)(sW + j * 100);
            const float* hp = hin;
            #pragma unroll 5
            for (int k4 = 0; k4 < 25; ++k4) {
                float4 w = wj[k4];
                #pragma unroll
                for (int dd = 0; dd < 4; ++dd) {
                    float wv = (dd == 0) ? w.x : (dd == 1) ? w.y : (dd == 2) ? w.z : w.w;
                    float4 ha = *(const float4*)(hp + (k4 * 4 + dd) * 8);
                    float4 hb = *(const float4*)(hp + (k4 * 4 + dd) * 8 + 4);
                    acc[0] = fmaf(wv, ha.x, acc[0]);
                    acc[1] = fmaf(wv, ha.y, acc[1]);
                    acc[2] = fmaf(wv, ha.z, acc[2]);
                    acc[3] = fmaf(wv, ha.w, acc[3]);
                    acc[4] = fmaf(wv, hb.x, acc[4]);
                    acc[5] = fmaf(wv, hb.y, acc[5]);
                    acc[6] = fmaf(wv, hb.z, acc[6]);
                }
            }
            float* gp = sG + j * 9;
            #pragma unroll
            for (int b = 0; b < NB; ++b) gp[b] = acc[b] + xr[b];
        }
        __syncthreads();
        if (v0) {
            float gi = sigf(sG[(k0c) * 9 + b0c]);
            float gf = sigf(sG[(100 + k0c) * 9 + b0c]);
            float gg = tanhf_fast(sG[(200 + k0c) * 9 + b0c]);
            float go = sigf(sG[(300 + k0c) * 9 + b0c]);
            c0r = fmaf(gf, c0r, gi * gg);
            h0r = go * tanhf_fast(c0r);
            hout[k0c * 8 + b0c] = h0r;
        }
        if (v1) {
            float gi = sigf(sG[(k1c) * 9 + b1c]);
            float gf = sigf(sG[(100 + k1c) * 9 + b1c]);
            float gg = tanhf_fast(sG[(200 + k1c) * 9 + b1c]);
            float go = sigf(sG[(300 + k1c) * 9 + b1c]);
            c1r = fmaf(gf, c1r, gi * gg);
            h1r = go * tanhf_fast(c1r);
            hout[k1c * 8 + b1c] = h1r;
        }
        __syncthreads();
    }

    if (v0 && b0 + b0c < BSZ) {
        hf[(b0 + b0c) * HSZ + k0c] = h0r;
        cf[(b0 + b0c) * HSZ + k0c] = c0r;
    }
    if (v1 && b0 + b1c < BSZ) {
        hf[(b0 + b1c) * HSZ + k1c] = h1r;
        cf[(b0 + b1c) * HSZ + k1c] = c1r;
    }
}

// ---- merged decoders, NB=14 per CTA: grid (72, 2) = 144 CTAs = ONE wave ----
#define NBD 14
#define HP 16
#define GP 15
#define DEC_SMEM_F (40000 + 1600 + 1600 + 6000)

__global__ __launch_bounds__(NT_RNN, 1) void rnn_dec2(
    const float* __restrict__ G0base, const float* __restrict__ Weffbase,
    const float* __restrict__ beffbase,
    const float* __restrict__ h0, const float* __restrict__ c0,
    __nv_bfloat16* __restrict__ hdhb, __nv_bfloat16* __restrict__ hdlb)
{
    extern __shared__ float s[];
    float* sW  = s;
    float* sHa = s + 40000;
    float* sHb = sHa + 1600;
    float* sG  = sHb + 1600;
    const int tid = threadIdx.x;
    const int b0 = blockIdx.x * NBD;
    const int did = blockIdx.y;

    const float* G0   = G0base + (size_t)did * BSZ * G4;
    const float* Weff = Weffbase + (size_t)did * G4 * HSZ;
    const float* beff = beffbase + (size_t)did * G4;
    const size_t hdoff = (size_t)did * BSZ * TSZ * KPL;
    __nv_bfloat16* hdh = hdhb + hdoff;
    __nv_bfloat16* hdl = hdlb + hdoff;

    for (int i = tid; i < 10000; i += NT_RNN)
        ((float4*)sW)[i] = ((const float4*)Weff)[i];
    for (int i = tid; i < 3200; i += NT_RNN) sHa[i] = 0.f;

    const float bq = (tid < 400) ? beff[tid] : 0.f;

    int bidx[NBD];
    #pragma unroll
    for (int b = 0; b < NBD; ++b) {
        int bb = b0 + b; if (bb > BSZ - 1) bb = BSZ - 1;
        bidx[b] = bb;
    }

    int ck[4], cb[4];
    bool cv[4], cw[4];
    float cc[4];
    __nv_bfloat16* outh[4];
    __nv_bfloat16* outl[4];
    #pragma unroll
    for (int q = 0; q < 4; ++q) {
        int item = q * NT_RNN + tid;
        bool v = item < NBD * 100;
        int k = v ? (item % 100) : 0;
        int b = v ? (item / 100) : 0;
        ck[q] = k; cb[q] = b; cv[q] = v;
        cw[q] = v && (b0 + b < BSZ);
        cc[q] = 0.f;
        outh[q] = hdh + ((size_t)(b0 + b) * TSZ) * KPL + k;
        outl[q] = hdl + ((size_t)(b0 + b) * TSZ) * KPL + k;
    }
    __syncthreads();

    #pragma unroll
    for (int q = 0; q < 4; ++q) {
        if (cv[q]) {
            sHa[ck[q] * HP + cb[q]] = h0[bidx[cb[q]] * HSZ + ck[q]];
            cc[q] = c0[bidx[cb[q]] * HSZ + ck[q]];
        }
    }
    __syncthreads();

    for (int t = 0; t < TSZ; ++t) {
        const float* hin = (t & 1) ? sHb : sHa;
        float* hout = (t & 1) ? sHa : sHb;
        if (tid < 400) {
            const int j = tid;
            float* gp = sG + j * GP;
            if (t == 0) {
                #pragma unroll
                for (int b = 0; b < NBD; ++b)
                    gp[b] = G0[(size_t)bidx[b] * G4 + j];
            } else {
                float acc[NBD];
                #pragma unroll
                for (int b = 0; b < NBD; ++b) acc[b] = 0.f;
                const float4* wj = (const float4*)(sW + j * 100);
                const float* hp = hin;
                #pragma unroll 5
                for (int k4 = 0; k4 < 25; ++k4) {
                    float4 w = wj[k4];
                    #pragma unroll
                    for (int dd = 0; dd < 4; ++dd) {
                        float wv = (dd == 0) ? w.x : (dd == 1) ? w.y : (dd == 2) ? w.z : w.w;
                        const float* hr = hp + (k4 * 4 + dd) * HP;
                        float4 h0v = *(const float4*)(hr);
                        float4 h1v = *(const float4*)(hr + 4);
                        float4 h2v = *(const float4*)(hr + 8);
                        float2 h3v = *(const float2*)(hr + 12);
                        acc[0]  = fmaf(wv, h0v.x, acc[0]);
                        acc[1]  = fmaf(wv, h0v.y, acc[1]);
                        acc[2]  = fmaf(wv, h0v.z, acc[2]);
                        acc[3]  = fmaf(wv, h0v.w, acc[3]);
                        acc[4]  = fmaf(wv, h1v.x, acc[4]);
                        acc[5]  = fmaf(wv, h1v.y, acc[5]);
                        acc[6]  = fmaf(wv, h1v.z, acc[6]);
                        acc[7]  = fmaf(wv, h1v.w, acc[7]);
                        acc[8]  = fmaf(wv, h2v.x, acc[8]);
                        acc[9]  = fmaf(wv, h2v.y, acc[9]);
                        acc[10] = fmaf(wv, h2v.z, acc[10]);
                        acc[11] = fmaf(wv, h2v.w, acc[11]);
                        acc[12] = fmaf(wv, h3v.x, acc[12]);
                        acc[13] = fmaf(wv, h3v.y, acc[13]);
                    }
                }
                #pragma unroll
                for (int b = 0; b < NBD; ++b) gp[b] = acc[b] + bq;
            }
        }
        __syncthreads();
        #pragma unroll
        for (int q = 0; q < 4; ++q) {
            if (cv[q]) {
                int k = ck[q], b = cb[q];
                float gi = sigf(sG[(k) * GP + b]);
                float gf = sigf(sG[(100 + k) * GP + b]);
                float gg = tanhf_fast(sG[(200 + k) * GP + b]);
                float go = sigf(sG[(300 + k) * GP + b]);
                float c = fmaf(gf, cc[q], gi * gg);
                cc[q] = c;
                float h = go * tanhf_fast(c);
                hout[k * HP + b] = h;
                if (cw[q]) {
                    __nv_bfloat16 hi = __float2bfloat16(h);
                    outh[q][(size_t)t * KPL] = hi;
                    outl[q][(size_t)t * KPL] = __float2bfloat16(h - __bfloat162float(hi));
                }
            }
        }
        __syncthreads();
    }
}

// ---------------- launch ----------------------------------------------------
extern "C" void kernel_launch(void* const* d_in, const int* in_sizes, int n_in,
                              void* d_out, int out_size)
{
    const float* src     = (const float*)d_in[0];
    const float* trg     = (const float*)d_in[1];
    const float* enc_Wih = (const float*)d_in[2];
    const float* enc_Whh = (const float*)d_in[3];
    const float* enc_bih = (const float*)d_in[4];
    const float* enc_bhh = (const float*)d_in[5];
    const float* pd_Wih  = (const float*)d_in[6];
    const float* pd_Whh  = (const float*)d_in[7];
    const float* pd_bih  = (const float*)d_in[8];
    const float* pd_bhh  = (const float*)d_in[9];
    const float* pd_fcW  = (const float*)d_in[10];
    const float* pd_fcb  = (const float*)d_in[11];
    const float* rd_Wih  = (const float*)d_in[12];
    const float* rd_Whh  = (const float*)d_in[13];
    const float* rd_bih  = (const float*)d_in[14];
    const float* rd_bhh  = (const float*)d_in[15];
    const float* rd_fcW  = (const float*)d_in[16];
    const float* rd_fcb  = (const float*)d_in[17];
    float* out = (float*)d_out;

    float *pX, *pHenc, *pCenc, *pG0, *pWeff, *pBeff, *pLoss;
    __nv_bfloat16 *pSrch, *pSrcl, *pWihh, *pWihl, *pFcwh, *pFcwl, *pHdh, *pHdl;
    cudaGetSymbolAddress((void**)&pX,    g_X);
    cudaGetSymbolAddress((void**)&pHenc, g_henc);
    cudaGetSymbolAddress((void**)&pCenc, g_cenc);
    cudaGetSymbolAddress((void**)&pG0,   g_G0);
    cudaGetSymbolAddress((void**)&pWeff, g_Weff);
    cudaGetSymbolAddress((void**)&pBeff, g_beff);
    cudaGetSymbolAddress((void**)&pLoss, g_loss);
    cudaGetSymbolAddress((void**)&pSrch, g_srch);
    cudaGetSymbolAddress((void**)&pSrcl, g_srcl);
    cudaGetSymbolAddress((void**)&pWihh, g_wihh);
    cudaGetSymbolAddress((void**)&pWihl, g_wihl);
    cudaGetSymbolAddress((void**)&pFcwh, g_fcwh);
    cudaGetSymbolAddress((void**)&pFcwl, g_fcwl);
    cudaGetSymbolAddress((void**)&pHdh,  g_hdh);
    cudaGetSymbolAddress((void**)&pHdl,  g_hdl);

    const int SMEM_RNN = RNN_SMEM_F * 4;
    const int SMEM_DEC = DEC_SMEM_F * 4;
    const int SMEM_GEMM = (int)sizeof(Bf16GemmSmem);
    cudaFuncSetAttribute(rnn_enc,  cudaFuncAttributeMaxDynamicSharedMemorySize, SMEM_RNN);
    cudaFuncSetAttribute(rnn_dec2, cudaFuncAttributeMaxDynamicSharedMemorySize, SMEM_DEC);
    cudaFuncSetAttribute(gemm_bf16_store, cudaFuncAttributeMaxDynamicSharedMemorySize, SMEM_GEMM);
    cudaFuncSetAttribute(gemm_bf16_loss2, cudaFuncAttributeMaxDynamicSharedMemorySize, SMEM_GEMM);

    const int RNN_BLOCKS = (BSZ + NB - 1) / NB;     // 143
    const int DEC_BLOCKS = (BSZ + NBD - 1) / NBD;   // 72
    const int MROWS = BSZ * TSZ;                    // 100000

    // launches 1-3: prep (launch #4 = phase-A tensor GEMM, the profiled slot)
    cvt_split_t<ISZ, KPA><<<(MROWS * (KPA / 4) + 255) / 256, 256>>>(src, pSrch, pSrcl, MROWS);
    cvt_split_t<ISZ, KPA><<<(G4 * (KPA / 4) + 255) / 256, 256>>>(enc_Wih, pWihh, pWihl, G4);
    {
        dim3 grid(G4, 2);
        fold2_kernel<<<grid, 128>>>(pd_Wih, pd_Whh, pd_fcW, pd_fcb, pd_bih, pd_bhh,
                                    rd_Wih, rd_Whh, rd_fcW, rd_fcb, rd_bih, rd_bhh,
                                    pWeff, pBeff, pLoss);
    }

    // launch 4: phase A (tensor cores, 256x64 CTA tile)
    {
        dim3 grid((G4 + 63) / 64, (MROWS + 255) / 256);
        gemm_bf16_store<<<grid, 256, SMEM_GEMM>>>(pSrch, pSrcl, KPA, pWihh, pWihl, KPA,
                                                  enc_bih, enc_bhh, pX, MROWS, G4, KPA);
    }

    // encoder recurrence
    rnn_enc<<<RNN_BLOCKS, NT_RNN, SMEM_RNN>>>(pX, enc_Whh, pHenc, pCenc);

    // fcW splits (only needed by loss GEMMs)
    cvt_split_t<HSZ, KPL><<<(ISZ * (KPL / 4) + 255) / 256, 256>>>(pd_fcW, pFcwh, pFcwl, ISZ);
    cvt_split_t<HSZ, KPL><<<(ISZ * (KPL / 4) + 255) / 256, 256>>>(rd_fcW, pFcwh + ISZ * KPL,
                                                                  pFcwl + ISZ * KPL, ISZ);

    // decoder step-0 gates (both decoders, one launch)
    {
        dim3 grid((G4 + 63) / 64, (BSZ + 255) / 256, 2);
        gemm_g0<<<grid, 256>>>(pHenc, pd_Whh, rd_Whh, pd_bih, rd_bih,
                               pd_bhh, rd_bhh, pG0, BSZ, G4, HSZ);
    }

    // merged decoders: 144 CTAs = one full wave
    {
        dim3 grid(DEC_BLOCKS, 2);
        rnn_dec2<<<grid, NT_RNN, SMEM_DEC>>>(pG0, pWeff, pBeff, pHenc, pCenc,
                                             pHdh, pHdl);
    }

    // merged losses (tensor cores, fused MSE epilogue)
    {
        dim3 grid((ISZ + 63) / 64, (MROWS + 255) / 256, 2);
        gemm_bf16_loss2<<<grid, 256, SMEM_GEMM>>>(pHdh, pHdl, pFcwh, pFcwl,
                                                  pd_fcb, rd_fcb, trg, src,
                                                  pLoss, MROWS, ISZ);
    }

    finalize_kernel<<<1, 1>>>(pLoss, out, 1.0f / (float)(BSZ * TSZ * ISZ));
}

// round 12
// speedup vs baseline: 1.0895x; 1.0895x over previous
#include <cuda_runtime.h>
#include <cuda_bf16.h>
#include <math.h>

#define BSZ 1000
#define TSZ 100
#define ISZ 264
#define HSZ 100
#define G4  400   // 4*H
#define KPA 272   // padded K for phase A (264 -> 17*16)
#define KPL 112   // padded K for loss GEMMs (100 -> 7*16)

// ---------------- device scratch (static: no allocation allowed) ----------
__device__ float g_X[(size_t)BSZ * TSZ * G4];       // encoder gate inputs fp32
__device__ float g_henc[BSZ * HSZ];
__device__ float g_cenc[BSZ * HSZ];
__device__ float g_G0[2][BSZ * G4];                 // decoder step-0 gates
__device__ float g_Weff[2][G4 * HSZ];
__device__ float g_beff[2][G4];
__device__ float g_loss[2];

// bf16 split operands
__device__ __nv_bfloat16 g_srch[(size_t)BSZ * TSZ * KPA];
__device__ __nv_bfloat16 g_srcl[(size_t)BSZ * TSZ * KPA];
__device__ __nv_bfloat16 g_wihh[G4 * KPA];
__device__ __nv_bfloat16 g_wihl[G4 * KPA];
__device__ __nv_bfloat16 g_fcwh[2][ISZ * KPL];
__device__ __nv_bfloat16 g_fcwl[2][ISZ * KPL];
__device__ __nv_bfloat16 g_hdh[2][(size_t)BSZ * TSZ * KPL];  // decoder h (bf16 hi only)

// ---------------- fast activations (ex2/rcp approx: ~2^-22 rel err) --------
__device__ __forceinline__ float ex2f(float x) {
    float r; asm("ex2.approx.f32 %0, %1;" : "=f"(r) : "f"(x)); return r;
}
__device__ __forceinline__ float rcpf(float x) {
    float r; asm("rcp.approx.f32 %0, %1;" : "=f"(r) : "f"(x)); return r;
}
__device__ __forceinline__ float sigf(float x) {
    return rcpf(1.f + ex2f(-1.4426950408889634f * x));
}
__device__ __forceinline__ float tanhf_fast(float x) {
    return fmaf(2.f, rcpf(1.f + ex2f(-2.8853900817779268f * x)), -1.f);
}

// ---------------- small kernels -------------------------------------------
__global__ void finalize_kernel(const float* loss, float* out, float inv) {
    out[0] = loss[0] * inv;
    out[1] = loss[1] * inv;
}

// fp32 -> (bf16 hi, bf16 lo), K padded to Kp, templated, float4 vectorized.
template <int K, int Kp>
__global__ __launch_bounds__(256) void cvt_split_t(
    const float* __restrict__ x, __nv_bfloat16* __restrict__ h,
    __nv_bfloat16* __restrict__ l, int rows)
{
    const int Kp4 = Kp / 4;
    int idx = blockIdx.x * 256 + threadIdx.x;
    if (idx >= rows * Kp4) return;
    int r = idx / Kp4;
    int k4 = (idx - r * Kp4) * 4;
    float4 v;
    if (k4 + 3 < K) {
        v = *(const float4*)(x + (size_t)r * K + k4);
    } else {
        float tmp[4] = {0.f, 0.f, 0.f, 0.f};
        #pragma unroll
        for (int e = 0; e < 4; ++e)
            if (k4 + e < K) tmp[e] = x[(size_t)r * K + k4 + e];
        v = make_float4(tmp[0], tmp[1], tmp[2], tmp[3]);
    }
    float vv[4] = {v.x, v.y, v.z, v.w};
    __nv_bfloat16 hh[4], ll[4];
    #pragma unroll
    for (int e = 0; e < 4; ++e) {
        hh[e] = __float2bfloat16(vv[e]);
        ll[e] = __float2bfloat16(vv[e] - __bfloat162float(hh[e]));
    }
    *(uint2*)(h + (size_t)idx * 4) = *(const uint2*)hh;
    *(uint2*)(l + (size_t)idx * 4) = *(const uint2*)ll;
}

// Both decoder folds in one launch: blockIdx.y selects decoder.
__global__ __launch_bounds__(128) void fold2_kernel(
    const float* __restrict__ pd_Wih, const float* __restrict__ pd_Whh,
    const float* __restrict__ pd_fcW, const float* __restrict__ pd_fcb,
    const float* __restrict__ pd_bih, const float* __restrict__ pd_bhh,
    const float* __restrict__ rd_Wih, const float* __restrict__ rd_Whh,
    const float* __restrict__ rd_fcW, const float* __restrict__ rd_fcb,
    const float* __restrict__ rd_bih, const float* __restrict__ rd_bhh,
    float* __restrict__ Weff, float* __restrict__ beff, float* __restrict__ loss)
{
    const int did = blockIdx.y;
    const float* Wih = did ? rd_Wih : pd_Wih;
    const float* Whh = did ? rd_Whh : pd_Whh;
    const float* fcW = did ? rd_fcW : pd_fcW;
    const float* fcb = did ? rd_fcb : pd_fcb;
    const float* bih = did ? rd_bih : pd_bih;
    const float* bhh = did ? rd_bhh : pd_bhh;
    float* We = Weff + (size_t)did * G4 * HSZ;
    float* be = beff + (size_t)did * G4;

    int j = blockIdx.x;
    int tid = threadIdx.x;
    if (blockIdx.x == 0 && did == 0 && tid < 2) loss[tid] = 0.f;

    __shared__ float swih[ISZ];
    __shared__ float red[128];
    for (int i = tid; i < ISZ; i += 128) swih[i] = Wih[j * ISZ + i];
    __syncthreads();
    if (tid < HSZ) {
        float acc = Whh[j * HSZ + tid];
        #pragma unroll 4
        for (int i = 0; i < ISZ; ++i)
            acc = fmaf(swih[i], fcW[i * HSZ + tid], acc);
        We[j * HSZ + tid] = acc;
    }
    float p = 0.f;
    for (int i = tid; i < ISZ; i += 128) p = fmaf(swih[i], fcb[i], p);
    red[tid] = p;
    __syncthreads();
    for (int s = 64; s > 0; s >>= 1) {
        if (tid < s) red[tid] += red[tid + s];
        __syncthreads();
    }
    if (tid == 0) be[j] = bih[j] + bhh[j] + red[0];
}

// ---------------- SIMT NT GEMM for the two small G0 GEMMs ------------------
#define AP 264
#define BP 68
__global__ __launch_bounds__(256) void gemm_g0(
    const float* __restrict__ A,
    const float* __restrict__ B0, const float* __restrict__ B1,
    const float* __restrict__ b10, const float* __restrict__ b11,
    const float* __restrict__ b20, const float* __restrict__ b21,
    float* __restrict__ Cbase, int M, int N, int K)
{
    const int did = blockIdx.z;
    const float* B = did ? B1 : B0;
    const float* bias1 = did ? b11 : b10;
    const float* bias2 = did ? b21 : b20;
    float* C = Cbase + (size_t)did * M * N;

    __shared__ float As[8 * AP];
    __shared__ float Bs[8 * BP];
    const int tid = threadIdx.x;
    const int tx = tid & 7;
    const int ty = tid >> 3;
    const int m0 = blockIdx.y * 256, n0 = blockIdx.x * 64;

    float acc[8][8];
    #pragma unroll
    for (int i = 0; i < 8; ++i)
        #pragma unroll
        for (int j = 0; j < 8; ++j) acc[i][j] = 0.f;

    const int am = m0 + tid;
    const int br = tid >> 2;
    const int bc = (tid & 3) * 2;

    for (int k0 = 0; k0 < K; k0 += 8) {
        #pragma unroll
        for (int j = 0; j < 8; ++j) {
            int k = k0 + j;
            As[j * AP + tid] = (am < M && k < K) ? A[(size_t)am * K + k] : 0.f;
        }
        {
            int n = n0 + br;
            #pragma unroll
            for (int j = 0; j < 2; ++j) {
                int k = k0 + bc + j;
                Bs[(bc + j) * BP + br] = (n < N && k < K) ? B[(size_t)n * K + k] : 0.f;
            }
        }
        __syncthreads();
        #pragma unroll
        for (int kk = 0; kk < 8; ++kk) {
            float4 a0 = *(const float4*)(As + kk * AP + ty * 8);
            float4 a1 = *(const float4*)(As + kk * AP + ty * 8 + 4);
            float4 b0 = *(const float4*)(Bs + kk * BP + tx * 8);
            float4 b1 = *(const float4*)(Bs + kk * BP + tx * 8 + 4);
            float av[8] = {a0.x, a0.y, a0.z, a0.w, a1.x, a1.y, a1.z, a1.w};
            float bv[8] = {b0.x, b0.y, b0.z, b0.w, b1.x, b1.y, b1.z, b1.w};
            #pragma unroll
            for (int i = 0; i < 8; ++i)
                #pragma unroll
                for (int j = 0; j < 8; ++j)
                    acc[i][j] = fmaf(av[i], bv[j], acc[i][j]);
        }
        __syncthreads();
    }

    #pragma unroll
    for (int i = 0; i < 8; ++i) {
        int m = m0 + ty * 8 + i;
        if (m < M) {
            #pragma unroll
            for (int j = 0; j < 8; ++j) {
                int n = n0 + tx * 8 + j;
                if (n < N) C[(size_t)m * N + n] = acc[i][j] + bias1[n] + bias2[n];
            }
        }
    }
}

// ---------------- tensor-core split-bf16 NT GEMM core (R10 config) ---------
// CTA 128m x 64n, warps 4m x 2n, warp tile 32x32. LDSM fragment loads.
#define SAP 24

__device__ __forceinline__ void mma16816(float* d, const unsigned* a, const unsigned* b) {
    asm volatile(
        "mma.sync.aligned.m16n8k16.row.col.f32.bf16.bf16.f32 "
        "{%0,%1,%2,%3},{%4,%5,%6,%7},{%8,%9},{%0,%1,%2,%3};"
        : "+f"(d[0]), "+f"(d[1]), "+f"(d[2]), "+f"(d[3])
        : "r"(a[0]), "r"(a[1]), "r"(a[2]), "r"(a[3]), "r"(b[0]), "r"(b[1]));
}

__device__ __forceinline__ void ldsm_x4(unsigned* r, unsigned addr) {
    asm volatile(
        "ldmatrix.sync.aligned.m8n8.x4.shared.b16 {%0,%1,%2,%3}, [%4];"
        : "=r"(r[0]), "=r"(r[1]), "=r"(r[2]), "=r"(r[3]) : "r"(addr));
}

struct Bf16GemmSmem {
    __nv_bfloat16 Ash[2][128 * SAP];
    __nv_bfloat16 Asl[2][128 * SAP];
    __nv_bfloat16 Bsh[2][64 * SAP];
    __nv_bfloat16 Bsl[2][64 * SAP];
    float red[256];
};

// Full split mainloop (A hi+lo, B hi+lo): 3 MMAs per fragment pair.
__device__ __forceinline__ void bf16_mainloop(
    Bf16GemmSmem* sm, float d[2][4][4],
    const __nv_bfloat16* Ah, const __nv_bfloat16* Al, int lda,
    const __nv_bfloat16* Bh, const __nv_bfloat16* Bl, int ldb,
    int m0, int n0, int M, int N, int Kp)
{
    const int tid = threadIdx.x;
    const int lane = tid & 31;
    const int wid = tid >> 5;
    const int wy = wid & 3;
    const int wx = wid >> 2;

    const int ar = tid >> 1;
    const int ah8 = (tid & 1) * 8;
    const int bs = tid & 127;
    const int brow = bs >> 1;
    const int bh8 = (bs & 1) * 8;
    const int gm = m0 + ar;
    const int gn = n0 + brow;
    const __nv_bfloat16* srcB = (tid < 128) ? Bh : Bl;

    const unsigned aoff =
        ((unsigned)((wy * 32 + ((lane >> 3) & 1) * 8 + (lane & 7)) * SAP
                    + (lane >> 4) * 8)) * 2u;
    const unsigned boff =
        ((unsigned)((wx * 32 + ((lane >> 4) & 1) * 8 + (lane & 7)) * SAP
                    + ((lane >> 3) & 1) * 8)) * 2u;

    const unsigned ashb = (unsigned)__cvta_generic_to_shared(sm->Ash[0]);
    const unsigned aslb = (unsigned)__cvta_generic_to_shared(sm->Asl[0]);
    const unsigned bshb = (unsigned)__cvta_generic_to_shared(sm->Bsh[0]);
    const unsigned bslb = (unsigned)__cvta_generic_to_shared(sm->Bsl[0]);
    const unsigned abuf = 128 * SAP * 2;
    const unsigned bbuf = 64 * SAP * 2;
    const unsigned ni2step = 16 * SAP * 2;
    const unsigned mistep = 16 * SAP * 2;

    const uint4 zv = make_uint4(0, 0, 0, 0);
    uint4 vh = zv, vl = zv, vb = zv;
    if (gm < M) {
        vh = *(const uint4*)(Ah + (size_t)gm * lda + ah8);
        vl = *(const uint4*)(Al + (size_t)gm * lda + ah8);
    }
    if (gn < N) vb = *(const uint4*)(srcB + (size_t)gn * ldb + bh8);

    const int niter = Kp / 16;
    for (int i = 0; i < niter; ++i) {
        const unsigned cur = (unsigned)(i & 1);
        *(uint4*)&sm->Ash[cur][ar * SAP + ah8] = vh;
        *(uint4*)&sm->Asl[cur][ar * SAP + ah8] = vl;
        __nv_bfloat16* dstB = (tid < 128) ? sm->Bsh[cur] : sm->Bsl[cur];
        *(uint4*)&dstB[brow * SAP + bh8] = vb;
        __syncthreads();

        if (i + 1 < niter) {
            int kn = (i + 1) * 16;
            vh = zv; vl = zv; vb = zv;
            if (gm < M) {
                vh = *(const uint4*)(Ah + (size_t)gm * lda + kn + ah8);
                vl = *(const uint4*)(Al + (size_t)gm * lda + kn + ah8);
            }
            if (gn < N) vb = *(const uint4*)(srcB + (size_t)gn * ldb + kn + bh8);
        }

        unsigned bhf[4][2], blf[4][2];
        {
            unsigned r[4];
            unsigned b0 = bshb + cur * bbuf + boff;
            ldsm_x4(r, b0);
            bhf[0][0] = r[0]; bhf[0][1] = r[1]; bhf[1][0] = r[2]; bhf[1][1] = r[3];
            ldsm_x4(r, b0 + ni2step);
            bhf[2][0] = r[0]; bhf[2][1] = r[1]; bhf[3][0] = r[2]; bhf[3][1] = r[3];
            unsigned b1 = bslb + cur * bbuf + boff;
            ldsm_x4(r, b1);
            blf[0][0] = r[0]; blf[0][1] = r[1]; blf[1][0] = r[2]; blf[1][1] = r[3];
            ldsm_x4(r, b1 + ni2step);
            blf[2][0] = r[0]; blf[2][1] = r[1]; blf[3][0] = r[2]; blf[3][1] = r[3];
        }
        #pragma unroll
        for (int mi = 0; mi < 2; ++mi) {
            unsigned ahf[4], alf[4];
            ldsm_x4(ahf, ashb + cur * abuf + aoff + mi * mistep);
            ldsm_x4(alf, aslb + cur * abuf + aoff + mi * mistep);
            #pragma unroll
            for (int ni = 0; ni < 4; ++ni) {
                mma16816(d[mi][ni], ahf, bhf[ni]);
                mma16816(d[mi][ni], ahf, blf[ni]);
                mma16816(d[mi][ni], alf, bhf[ni]);
            }
        }
    }
    __syncthreads();
}

// A-hi-only mainloop (A plain bf16, B hi+lo): 2 MMAs per fragment pair.
__device__ __forceinline__ void bf16_mainloop_a1(
    Bf16GemmSmem* sm, float d[2][4][4],
    const __nv_bfloat16* Ah, int lda,
    const __nv_bfloat16* Bh, const __nv_bfloat16* Bl, int ldb,
    int m0, int n0, int M, int N, int Kp)
{
    const int tid = threadIdx.x;
    const int lane = tid & 31;
    const int wid = tid >> 5;
    const int wy = wid & 3;
    const int wx = wid >> 2;

    const int ar = tid >> 1;
    const int ah8 = (tid & 1) * 8;
    const int bs = tid & 127;
    const int brow = bs >> 1;
    const int bh8 = (bs & 1) * 8;
    const int gm = m0 + ar;
    const int gn = n0 + brow;
    const __nv_bfloat16* srcB = (tid < 128) ? Bh : Bl;

    const unsigned aoff =
        ((unsigned)((wy * 32 + ((lane >> 3) & 1) * 8 + (lane & 7)) * SAP
                    + (lane >> 4) * 8)) * 2u;
    const unsigned boff =
        ((unsigned)((wx * 32 + ((lane >> 4) & 1) * 8 + (lane & 7)) * SAP
                    + ((lane >> 3) & 1) * 8)) * 2u;

    const unsigned ashb = (unsigned)__cvta_generic_to_shared(sm->Ash[0]);
    const unsigned bshb = (unsigned)__cvta_generic_to_shared(sm->Bsh[0]);
    const unsigned bslb = (unsigned)__cvta_generic_to_shared(sm->Bsl[0]);
    const unsigned abuf = 128 * SAP * 2;
    const unsigned bbuf = 64 * SAP * 2;
    const unsigned ni2step = 16 * SAP * 2;
    const unsigned mistep = 16 * SAP * 2;

    const uint4 zv = make_uint4(0, 0, 0, 0);
    uint4 vh = zv, vb = zv;
    if (gm < M) vh = *(const uint4*)(Ah + (size_t)gm * lda + ah8);
    if (gn < N) vb = *(const uint4*)(srcB + (size_t)gn * ldb + bh8);

    const int niter = Kp / 16;
    for (int i = 0; i < niter; ++i) {
        const unsigned cur = (unsigned)(i & 1);
        *(uint4*)&sm->Ash[cur][ar * SAP + ah8] = vh;
        __nv_bfloat16* dstB = (tid < 128) ? sm->Bsh[cur] : sm->Bsl[cur];
        *(uint4*)&dstB[brow * SAP + bh8] = vb;
        __syncthreads();

        if (i + 1 < niter) {
            int kn = (i + 1) * 16;
            vh = zv; vb = zv;
            if (gm < M) vh = *(const uint4*)(Ah + (size_t)gm * lda + kn + ah8);
            if (gn < N) vb = *(const uint4*)(srcB + (size_t)gn * ldb + kn + bh8);
        }

        unsigned bhf[4][2], blf[4][2];
        {
            unsigned r[4];
            unsigned b0 = bshb + cur * bbuf + boff;
            ldsm_x4(r, b0);
            bhf[0][0] = r[0]; bhf[0][1] = r[1]; bhf[1][0] = r[2]; bhf[1][1] = r[3];
            ldsm_x4(r, b0 + ni2step);
            bhf[2][0] = r[0]; bhf[2][1] = r[1]; bhf[3][0] = r[2]; bhf[3][1] = r[3];
            unsigned b1 = bslb + cur * bbuf + boff;
            ldsm_x4(r, b1);
            blf[0][0] = r[0]; blf[0][1] = r[1]; blf[1][0] = r[2]; blf[1][1] = r[3];
            ldsm_x4(r, b1 + ni2step);
            blf[2][0] = r[0]; blf[2][1] = r[1]; blf[3][0] = r[2]; blf[3][1] = r[3];
        }
        #pragma unroll
        for (int mi = 0; mi < 2; ++mi) {
            unsigned ahf[4];
            ldsm_x4(ahf, ashb + cur * abuf + aoff + mi * mistep);
            #pragma unroll
            for (int ni = 0; ni < 4; ++ni) {
                mma16816(d[mi][ni], ahf, bhf[ni]);
                mma16816(d[mi][ni], ahf, blf[ni]);
            }
        }
    }
    __syncthreads();
}

// Phase-A variant: stores C with two biases.
__global__ __launch_bounds__(256, 3) void gemm_bf16_store(
    const __nv_bfloat16* __restrict__ Ah, const __nv_bfloat16* __restrict__ Al, int lda,
    const __nv_bfloat16* __restrict__ Bh, const __nv_bfloat16* __restrict__ Bl, int ldb,
    const float* __restrict__ bias1, const float* __restrict__ bias2,
    float* __restrict__ C, int M, int N, int Kp)
{
    extern __shared__ char smraw[];
    Bf16GemmSmem* sm = (Bf16GemmSmem*)smraw;
    const int tid = threadIdx.x;
    const int lane = tid & 31;
    const int wid = tid >> 5;
    const int wy = wid & 3, wx = wid >> 2;
    const int g = lane >> 2, t = lane & 3;
    const int m0 = blockIdx.y * 128, n0 = blockIdx.x * 64;

    float d[2][4][4];
    #pragma unroll
    for (int mi = 0; mi < 2; ++mi)
        #pragma unroll
        for (int ni = 0; ni < 4; ++ni)
            #pragma unroll
            for (int e = 0; e < 4; ++e) d[mi][ni][e] = 0.f;

    bf16_mainloop(sm, d, Ah, Al, lda, Bh, Bl, ldb, m0, n0, M, N, Kp);

    #pragma unroll
    for (int mi = 0; mi < 2; ++mi) {
        #pragma unroll
        for (int rr = 0; rr < 2; ++rr) {
            int m = m0 + wy * 32 + mi * 16 + rr * 8 + g;
            if (m >= M) continue;
            #pragma unroll
            for (int ni = 0; ni < 4; ++ni) {
                int n = n0 + wx * 32 + ni * 8 + 2 * t;
                if (n + 1 < N) {
                    float v0 = d[mi][ni][rr * 2 + 0] + bias1[n] + bias2[n];
                    float v1 = d[mi][ni][rr * 2 + 1] + bias1[n + 1] + bias2[n + 1];
                    *(float2*)(C + (size_t)m * N + n) = make_float2(v0, v1);
                } else if (n < N) {
                    C[(size_t)m * N + n] = d[mi][ni][rr * 2 + 0] + bias1[n] + bias2[n];
                }
            }
        }
    }
}

// Merged loss variant: A = decoder h (bf16 hi only); fused MSE epilogue.
__global__ __launch_bounds__(256, 3) void gemm_bf16_loss2(
    const __nv_bfloat16* __restrict__ Ahb,
    const __nv_bfloat16* __restrict__ Bhb, const __nv_bfloat16* __restrict__ Blb,
    const float* __restrict__ fcb0, const float* __restrict__ fcb1,
    const float* __restrict__ trg, const float* __restrict__ src,
    float* __restrict__ loss, int M, int N)
{
    extern __shared__ char smraw[];
    Bf16GemmSmem* sm = (Bf16GemmSmem*)smraw;
    const int did = blockIdx.z;
    const __nv_bfloat16* Ah = Ahb + (size_t)did * M * KPL;
    const __nv_bfloat16* Bh = Bhb + (size_t)did * N * KPL;
    const __nv_bfloat16* Bl = Blb + (size_t)did * N * KPL;
    const float* bias = did ? fcb1 : fcb0;
    const float* ref = did ? src : trg;
    float* lossOut = did ? (loss + 0) : (loss + 1);
    const int revT = did ? TSZ : 0;

    const int tid = threadIdx.x;
    const int lane = tid & 31;
    const int wid = tid >> 5;
    const int wy = wid & 3, wx = wid >> 2;
    const int g = lane >> 2, t = lane & 3;
    const int m0 = blockIdx.y * 128, n0 = blockIdx.x * 64;

    float d[2][4][4];
    #pragma unroll
    for (int mi = 0; mi < 2; ++mi)
        #pragma unroll
        for (int ni = 0; ni < 4; ++ni)
            #pragma unroll
            for (int e = 0; e < 4; ++e) d[mi][ni][e] = 0.f;

    bf16_mainloop_a1(sm, d, Ah, KPL, Bh, Bl, KPL, m0, n0, M, N, KPL);

    float ls = 0.f;
    #pragma unroll
    for (int mi = 0; mi < 2; ++mi) {
        #pragma unroll
        for (int rr = 0; rr < 2; ++rr) {
            int m = m0 + wy * 32 + mi * 16 + rr * 8 + g;
            if (m >= M) continue;
            const float* rrow;
            if (revT > 0) {
                int b = m / revT, tt = m - b * revT;
                rrow = ref + ((size_t)b * revT + (revT - 1 - tt)) * N;
            } else {
                rrow = ref + (size_t)m * N;
            }
            #pragma unroll
            for (int ni = 0; ni < 4; ++ni) {
                int n = n0 + wx * 32 + ni * 8 + 2 * t;
                #pragma unroll
                for (int e = 0; e < 2; ++e) {
                    if (n + e < N) {
                        float v = d[mi][ni][rr * 2 + e] + bias[n + e];
                        float diff = v - rrow[n + e];
                        ls = fmaf(diff, diff, ls);
                    }
                }
            }
        }
    }
    sm->red[tid] = ls;
    __syncthreads();
    for (int s = 128; s > 0; s >>= 1) {
        if (tid < s) sm->red[tid] += sm->red[tid + s];
        __syncthreads();
    }
    if (tid == 0) atomicAdd(lossOut, sm->red[0]);
}

// ---------------- LSTM recurrence kernels ----------------------------------
#define NB 7
#define NT_RNN 416
#define RNN_SMEM_F (40000 + 800 + 800 + 3600)

__global__ __launch_bounds__(NT_RNN, 1) void rnn_enc(
    const float* __restrict__ X, const float* __restrict__ Whh,
    float* __restrict__ hf, float* __restrict__ cf)
{
    extern __shared__ float s[];
    float* sW  = s;
    float* sHa = s + 40000;
    float* sHb = sHa + 800;
    float* sG  = sHb + 800;
    const int tid = threadIdx.x;
    const int b0 = blockIdx.x * NB;

    for (int i = tid; i < 10000; i += NT_RNN)
        ((float4*)sW)[i] = ((const float4*)Whh)[i];
    for (int i = tid; i < 800; i += NT_RNN) sHa[i] = 0.f;
    __syncthreads();

    const int i0 = tid, i1 = tid + NT_RNN;
    const int k0c = i0 % 100, b0c = i0 / 100;
    const int k1c = i1 % 100, b1c = i1 / 100;
    const bool v0 = (i0 < NB * 100), v1 = (i1 < NB * 100);
    float c0r = 0.f, c1r = 0.f, h0r = 0.f, h1r = 0.f;

    int bidx[NB];
    #pragma unroll
    for (int b = 0; b < NB; ++b) {
        int bb = b0 + b; if (bb > BSZ - 1) bb = BSZ - 1;
        bidx[b] = bb;
    }

    for (int t = 0; t < TSZ; ++t) {
        const float* hin = (t & 1) ? sHb : sHa;
        float* hout = (t & 1) ? sHa : sHb;
        if (tid < 400) {
            const int j = tid;
            float xr[NB];
            #pragma unroll
            for (int b = 0; b < NB; ++b)
                xr[b] = X[((size_t)bidx[b] * TSZ + t) * G4 + j];
            float acc[NB];
            #pragma unroll
            for (int b = 0; b < NB; ++b) acc[b] = 0.f;
            const float4* wj = (const float4*)(sW + j * 100);
            const float* hp = hin;
            #pragma unroll 5
            for (int k4 = 0; k4 < 25; ++k4) {
                float4 w = wj[k4];
                #pragma unroll
                for (int dd = 0; dd < 4; ++dd) {
                    float wv = (dd == 0) ? w.x : (dd == 1) ? w.y : (dd == 2) ? w.z : w.w;
                    float4 ha = *(const float4*)(hp + (k4 * 4 + dd) * 8);
                    float4 hb = *(const float4*)(hp + (k4 * 4 + dd) * 8 + 4);
                    acc[0] = fmaf(wv, ha.x, acc[0]);
                    acc[1] = fmaf(wv, ha.y, acc[1]);
                    acc[2] = fmaf(wv, ha.z, acc[2]);
                    acc[3] = fmaf(wv, ha.w, acc[3]);
                    acc[4] = fmaf(wv, hb.x, acc[4]);
                    acc[5] = fmaf(wv, hb.y, acc[5]);
                    acc[6] = fmaf(wv, hb.z, acc[6]);
                }
            }
            float* gp = sG + j * 9;
            #pragma unroll
            for (int b = 0; b < NB; ++b) gp[b] = acc[b] + xr[b];
        }
        __syncthreads();
        if (v0) {
            float gi = sigf(sG[(k0c) * 9 + b0c]);
            float gf = sigf(sG[(100 + k0c) * 9 + b0c]);
            float gg = tanhf_fast(sG[(200 + k0c) * 9 + b0c]);
            float go = sigf(sG[(300 + k0c) * 9 + b0c]);
            c0r = fmaf(gf, c0r, gi * gg);
            h0r = go * tanhf_fast(c0r);
            hout[k0c * 8 + b0c] = h0r;
        }
        if (v1) {
            float gi = sigf(sG[(k1c) * 9 + b1c]);
            float gf = sigf(sG[(100 + k1c) * 9 + b1c]);
            float gg = tanhf_fast(sG[(200 + k1c) * 9 + b1c]);
            float go = sigf(sG[(300 + k1c) * 9 + b1c]);
            c1r = fmaf(gf, c1r, gi * gg);
            h1r = go * tanhf_fast(c1r);
            hout[k1c * 8 + b1c] = h1r;
        }
        __syncthreads();
    }

    if (v0 && b0 + b0c < BSZ) {
        hf[(b0 + b0c) * HSZ + k0c] = h0r;
        cf[(b0 + b0c) * HSZ + k0c] = c0r;
    }
    if (v1 && b0 + b1c < BSZ) {
        hf[(b0 + b1c) * HSZ + k1c] = h1r;
        cf[(b0 + b1c) * HSZ + k1c] = c1r;
    }
}

// ---- merged decoders, NB=14 per CTA: grid (72, 2) = 144 CTAs = ONE wave ----
#define NBD 14
#define HP 16
#define GP 15
#define DEC_SMEM_F (40000 + 1600 + 1600 + 6000)

__global__ __launch_bounds__(NT_RNN, 1) void rnn_dec2(
    const float* __restrict__ G0base, const float* __restrict__ Weffbase,
    const float* __restrict__ beffbase,
    const float* __restrict__ h0, const float* __restrict__ c0,
    __nv_bfloat16* __restrict__ hdhb)
{
    extern __shared__ float s[];
    float* sW  = s;
    float* sHa = s + 40000;
    float* sHb = sHa + 1600;
    float* sG  = sHb + 1600;
    const int tid = threadIdx.x;
    const int b0 = blockIdx.x * NBD;
    const int did = blockIdx.y;

    const float* G0   = G0base + (size_t)did * BSZ * G4;
    const float* Weff = Weffbase + (size_t)did * G4 * HSZ;
    const float* beff = beffbase + (size_t)did * G4;
    __nv_bfloat16* hdh = hdhb + (size_t)did * BSZ * TSZ * KPL;

    for (int i = tid; i < 10000; i += NT_RNN)
        ((float4*)sW)[i] = ((const float4*)Weff)[i];
    for (int i = tid; i < 3200; i += NT_RNN) sHa[i] = 0.f;

    const float bq = (tid < 400) ? beff[tid] : 0.f;

    int bidx[NBD];
    #pragma unroll
    for (int b = 0; b < NBD; ++b) {
        int bb = b0 + b; if (bb > BSZ - 1) bb = BSZ - 1;
        bidx[b] = bb;
    }

    int ck[4], cb[4];
    bool cv[4], cw[4];
    float cc[4];
    __nv_bfloat16* outh[4];
    #pragma unroll
    for (int q = 0; q < 4; ++q) {
        int item = q * NT_RNN + tid;
        bool v = item < NBD * 100;
        int k = v ? (item % 100) : 0;
        int b = v ? (item / 100) : 0;
        ck[q] = k; cb[q] = b; cv[q] = v;
        cw[q] = v && (b0 + b < BSZ);
        cc[q] = 0.f;
        outh[q] = hdh + ((size_t)(b0 + b) * TSZ) * KPL + k;
    }
    __syncthreads();

    #pragma unroll
    for (int q = 0; q < 4; ++q) {
        if (cv[q]) {
            sHa[ck[q] * HP + cb[q]] = h0[bidx[cb[q]] * HSZ + ck[q]];
            cc[q] = c0[bidx[cb[q]] * HSZ + ck[q]];
        }
    }
    __syncthreads();

    for (int t = 0; t < TSZ; ++t) {
        const float* hin = (t & 1) ? sHb : sHa;
        float* hout = (t & 1) ? sHa : sHb;
        if (tid < 400) {
            const int j = tid;
            float* gp = sG + j * GP;
            if (t == 0) {
                #pragma unroll
                for (int b = 0; b < NBD; ++b)
                    gp[b] = G0[(size_t)bidx[b] * G4 + j];
            } else {
                float acc[NBD];
                #pragma unroll
                for (int b = 0; b < NBD; ++b) acc[b] = 0.f;
                const float4* wj = (const float4*)(sW + j * 100);
                const float* hp = hin;
                #pragma unroll 5
                for (int k4 = 0; k4 < 25; ++k4) {
                    float4 w = wj[k4];
                    #pragma unroll
                    for (int dd = 0; dd < 4; ++dd) {
                        float wv = (dd == 0) ? w.x : (dd == 1) ? w.y : (dd == 2) ? w.z : w.w;
                        const float* hr = hp + (k4 * 4 + dd) * HP;
                        float4 h0v = *(const float4*)(hr);
                        float4 h1v = *(const float4*)(hr + 4);
                        float4 h2v = *(const float4*)(hr + 8);
                        float2 h3v = *(const float2*)(hr + 12);
                        acc[0]  = fmaf(wv, h0v.x, acc[0]);
                        acc[1]  = fmaf(wv, h0v.y, acc[1]);
                        acc[2]  = fmaf(wv, h0v.z, acc[2]);
                        acc[3]  = fmaf(wv, h0v.w, acc[3]);
                        acc[4]  = fmaf(wv, h1v.x, acc[4]);
                        acc[5]  = fmaf(wv, h1v.y, acc[5]);
                        acc[6]  = fmaf(wv, h1v.z, acc[6]);
                        acc[7]  = fmaf(wv, h1v.w, acc[7]);
                        acc[8]  = fmaf(wv, h2v.x, acc[8]);
                        acc[9]  = fmaf(wv, h2v.y, acc[9]);
                        acc[10] = fmaf(wv, h2v.z, acc[10]);
                        acc[11] = fmaf(wv, h2v.w, acc[11]);
                        acc[12] = fmaf(wv, h3v.x, acc[12]);
                        acc[13] = fmaf(wv, h3v.y, acc[13]);
                    }
                }
                #pragma unroll
                for (int b = 0; b < NBD; ++b) gp[b] = acc[b] + bq;
            }
        }
        __syncthreads();
        #pragma unroll
        for (int q = 0; q < 4; ++q) {
            if (cv[q]) {
                int k = ck[q], b = cb[q];
                float gi = sigf(sG[(k) * GP + b]);
                float gf = sigf(sG[(100 + k) * GP + b]);
                float gg = tanhf_fast(sG[(200 + k) * GP + b]);
                float go = sigf(sG[(300 + k) * GP + b]);
                float c = fmaf(gf, cc[q], gi * gg);
                cc[q] = c;
                float h = go * tanhf_fast(c);
                hout[k * HP + b] = h;
                if (cw[q])
                    outh[q][(size_t)t * KPL] = __float2bfloat16(h);
            }
        }
        __syncthreads();
    }
}

// ---------------- launch ----------------------------------------------------
extern "C" void kernel_launch(void* const* d_in, const int* in_sizes, int n_in,
                              void* d_out, int out_size)
{
    const float* src     = (const float*)d_in[0];
    const float* trg     = (const float*)d_in[1];
    const float* enc_Wih = (const float*)d_in[2];
    const float* enc_Whh = (const float*)d_in[3];
    const float* enc_bih = (const float*)d_in[4];
    const float* enc_bhh = (const float*)d_in[5];
    const float* pd_Wih  = (const float*)d_in[6];
    const float* pd_Whh  = (const float*)d_in[7];
    const float* pd_bih  = (const float*)d_in[8];
    const float* pd_bhh  = (const float*)d_in[9];
    const float* pd_fcW  = (const float*)d_in[10];
    const float* pd_fcb  = (const float*)d_in[11];
    const float* rd_Wih  = (const float*)d_in[12];
    const float* rd_Whh  = (const float*)d_in[13];
    const float* rd_bih  = (const float*)d_in[14];
    const float* rd_bhh  = (const float*)d_in[15];
    const float* rd_fcW  = (const float*)d_in[16];
    const float* rd_fcb  = (const float*)d_in[17];
    float* out = (float*)d_out;

    float *pX, *pHenc, *pCenc, *pG0, *pWeff, *pBeff, *pLoss;
    __nv_bfloat16 *pSrch, *pSrcl, *pWihh, *pWihl, *pFcwh, *pFcwl, *pHdh;
    cudaGetSymbolAddress((void**)&pX,    g_X);
    cudaGetSymbolAddress((void**)&pHenc, g_henc);
    cudaGetSymbolAddress((void**)&pCenc, g_cenc);
    cudaGetSymbolAddress((void**)&pG0,   g_G0);
    cudaGetSymbolAddress((void**)&pWeff, g_Weff);
    cudaGetSymbolAddress((void**)&pBeff, g_beff);
    cudaGetSymbolAddress((void**)&pLoss, g_loss);
    cudaGetSymbolAddress((void**)&pSrch, g_srch);
    cudaGetSymbolAddress((void**)&pSrcl, g_srcl);
    cudaGetSymbolAddress((void**)&pWihh, g_wihh);
    cudaGetSymbolAddress((void**)&pWihl, g_wihl);
    cudaGetSymbolAddress((void**)&pFcwh, g_fcwh);
    cudaGetSymbolAddress((void**)&pFcwl, g_fcwl);
    cudaGetSymbolAddress((void**)&pHdh,  g_hdh);

    const int SMEM_RNN = RNN_SMEM_F * 4;
    const int SMEM_DEC = DEC_SMEM_F * 4;
    const int SMEM_GEMM = (int)sizeof(Bf16GemmSmem);
    cudaFuncSetAttribute(rnn_enc,  cudaFuncAttributeMaxDynamicSharedMemorySize, SMEM_RNN);
    cudaFuncSetAttribute(rnn_dec2, cudaFuncAttributeMaxDynamicSharedMemorySize, SMEM_DEC);
    cudaFuncSetAttribute(gemm_bf16_store, cudaFuncAttributeMaxDynamicSharedMemorySize, SMEM_GEMM);
    cudaFuncSetAttribute(gemm_bf16_loss2, cudaFuncAttributeMaxDynamicSharedMemorySize, SMEM_GEMM);

    const int RNN_BLOCKS = (BSZ + NB - 1) / NB;     // 143
    const int DEC_BLOCKS = (BSZ + NBD - 1) / NBD;   // 72
    const int MROWS = BSZ * TSZ;                    // 100000

    // launches 1-3: prep (launch #4 = phase-A tensor GEMM, the profiled slot)
    cvt_split_t<ISZ, KPA><<<(MROWS * (KPA / 4) + 255) / 256, 256>>>(src, pSrch, pSrcl, MROWS);
    cvt_split_t<ISZ, KPA><<<(G4 * (KPA / 4) + 255) / 256, 256>>>(enc_Wih, pWihh, pWihl, G4);
    {
        dim3 grid(G4, 2);
        fold2_kernel<<<grid, 128>>>(pd_Wih, pd_Whh, pd_fcW, pd_fcb, pd_bih, pd_bhh,
                                    rd_Wih, rd_Whh, rd_fcW, rd_fcb, rd_bih, rd_bhh,
                                    pWeff, pBeff, pLoss);
    }

    // launch 4: phase A (tensor cores, R10 128x64 tile)
    {
        dim3 grid((G4 + 63) / 64, (MROWS + 127) / 128);
        gemm_bf16_store<<<grid, 256, SMEM_GEMM>>>(pSrch, pSrcl, KPA, pWihh, pWihl, KPA,
                                                  enc_bih, enc_bhh, pX, MROWS, G4, KPA);
    }

    // encoder recurrence
    rnn_enc<<<RNN_BLOCKS, NT_RNN, SMEM_RNN>>>(pX, enc_Whh, pHenc, pCenc);

    // fcW splits (only needed by loss GEMMs)
    cvt_split_t<HSZ, KPL><<<(ISZ * (KPL / 4) + 255) / 256, 256>>>(pd_fcW, pFcwh, pFcwl, ISZ);
    cvt_split_t<HSZ, KPL><<<(ISZ * (KPL / 4) + 255) / 256, 256>>>(rd_fcW, pFcwh + ISZ * KPL,
                                                                  pFcwl + ISZ * KPL, ISZ);

    // decoder step-0 gates (both decoders, one launch)
    {
        dim3 grid((G4 + 63) / 64, (BSZ + 255) / 256, 2);
        gemm_g0<<<grid, 256>>>(pHenc, pd_Whh, rd_Whh, pd_bih, rd_bih,
                               pd_bhh, rd_bhh, pG0, BSZ, G4, HSZ);
    }

    // merged decoders: 144 CTAs = one full wave
    {
        dim3 grid(DEC_BLOCKS, 2);
        rnn_dec2<<<grid, NT_RNN, SMEM_DEC>>>(pG0, pWeff, pBeff, pHenc, pCenc, pHdh);
    }

    // merged losses (tensor cores, A = hi-only decoder h, fused MSE epilogue)
    {
        dim3 grid((ISZ + 63) / 64, (MROWS + 127) / 128, 2);
        gemm_bf16_loss2<<<grid, 256, SMEM_GEMM>>>(pHdh, pFcwh, pFcwl,
                                                  pd_fcb, rd_fcb, trg, src,
                                                  pLoss, MROWS, ISZ);
    }

    finalize_kernel<<<1, 1>>>(pLoss, out, 1.0f / (float)(BSZ * TSZ * ISZ));
}

// round 13
// speedup vs baseline: 1.1505x; 1.0559x over previous
#include <cuda_runtime.h>
#include <cuda_bf16.h>
#include <math.h>

#define BSZ 1000
#define TSZ 100
#define ISZ 264
#define HSZ 100
#define G4  400   // 4*H
#define KPA 272   // padded K for phase A (264 -> 17*16)
#define KPL 112   // padded K for loss GEMMs (100 -> 7*16)

// ---------------- device scratch (static: no allocation allowed) ----------
__device__ float g_X[(size_t)BSZ * TSZ * G4];       // encoder gate inputs fp32
__device__ float g_henc[BSZ * HSZ];
__device__ float g_cenc[BSZ * HSZ];
__device__ float g_G0[2][BSZ * G4];                 // decoder step-0 gates
__device__ float g_Weff[2][G4 * HSZ];
__device__ float g_beff[2][G4];
__device__ float g_loss[2];

// bf16 operands (A-side hi-only; B-side split hi/lo)
__device__ __nv_bfloat16 g_srch[(size_t)BSZ * TSZ * KPA];
__device__ __nv_bfloat16 g_wihh[G4 * KPA];
__device__ __nv_bfloat16 g_wihl[G4 * KPA];
__device__ __nv_bfloat16 g_fcwh[2][ISZ * KPL];
__device__ __nv_bfloat16 g_fcwl[2][ISZ * KPL];
__device__ __nv_bfloat16 g_hdh[2][(size_t)BSZ * TSZ * KPL];  // decoder h (bf16)

// ---------------- fast activations (ex2/rcp approx: ~2^-22 rel err) --------
__device__ __forceinline__ float ex2f(float x) {
    float r; asm("ex2.approx.f32 %0, %1;" : "=f"(r) : "f"(x)); return r;
}
__device__ __forceinline__ float rcpf(float x) {
    float r; asm("rcp.approx.f32 %0, %1;" : "=f"(r) : "f"(x)); return r;
}
__device__ __forceinline__ float sigf(float x) {
    return rcpf(1.f + ex2f(-1.4426950408889634f * x));
}
__device__ __forceinline__ float tanhf_fast(float x) {
    return fmaf(2.f, rcpf(1.f + ex2f(-2.8853900817779268f * x)), -1.f);
}

// ---------------- small kernels -------------------------------------------
__global__ void finalize_kernel(const float* loss, float* out, float inv) {
    out[0] = loss[0] * inv;
    out[1] = loss[1] * inv;
}

// fp32 -> bf16 hi only, K padded to Kp.
template <int K, int Kp>
__global__ __launch_bounds__(256) void cvt_hi_t(
    const float* __restrict__ x, __nv_bfloat16* __restrict__ h, int rows)
{
    const int Kp4 = Kp / 4;
    int idx = blockIdx.x * 256 + threadIdx.x;
    if (idx >= rows * Kp4) return;
    int r = idx / Kp4;
    int k4 = (idx - r * Kp4) * 4;
    float4 v;
    if (k4 + 3 < K) {
        v = *(const float4*)(x + (size_t)r * K + k4);
    } else {
        float tmp[4] = {0.f, 0.f, 0.f, 0.f};
        #pragma unroll
        for (int e = 0; e < 4; ++e)
            if (k4 + e < K) tmp[e] = x[(size_t)r * K + k4 + e];
        v = make_float4(tmp[0], tmp[1], tmp[2], tmp[3]);
    }
    __nv_bfloat16 hh[4];
    hh[0] = __float2bfloat16(v.x);
    hh[1] = __float2bfloat16(v.y);
    hh[2] = __float2bfloat16(v.z);
    hh[3] = __float2bfloat16(v.w);
    *(uint2*)(h + (size_t)idx * 4) = *(const uint2*)hh;
}

// fp32 -> (bf16 hi, bf16 lo), K padded to Kp.
template <int K, int Kp>
__global__ __launch_bounds__(256) void cvt_split_t(
    const float* __restrict__ x, __nv_bfloat16* __restrict__ h,
    __nv_bfloat16* __restrict__ l, int rows)
{
    const int Kp4 = Kp / 4;
    int idx = blockIdx.x * 256 + threadIdx.x;
    if (idx >= rows * Kp4) return;
    int r = idx / Kp4;
    int k4 = (idx - r * Kp4) * 4;
    float4 v;
    if (k4 + 3 < K) {
        v = *(const float4*)(x + (size_t)r * K + k4);
    } else {
        float tmp[4] = {0.f, 0.f, 0.f, 0.f};
        #pragma unroll
        for (int e = 0; e < 4; ++e)
            if (k4 + e < K) tmp[e] = x[(size_t)r * K + k4 + e];
        v = make_float4(tmp[0], tmp[1], tmp[2], tmp[3]);
    }
    float vv[4] = {v.x, v.y, v.z, v.w};
    __nv_bfloat16 hh[4], ll[4];
    #pragma unroll
    for (int e = 0; e < 4; ++e) {
        hh[e] = __float2bfloat16(vv[e]);
        ll[e] = __float2bfloat16(vv[e] - __bfloat162float(hh[e]));
    }
    *(uint2*)(h + (size_t)idx * 4) = *(const uint2*)hh;
    *(uint2*)(l + (size_t)idx * 4) = *(const uint2*)ll;
}

// Both decoder folds in one launch: blockIdx.y selects decoder.
__global__ __launch_bounds__(128) void fold2_kernel(
    const float* __restrict__ pd_Wih, const float* __restrict__ pd_Whh,
    const float* __restrict__ pd_fcW, const float* __restrict__ pd_fcb,
    const float* __restrict__ pd_bih, const float* __restrict__ pd_bhh,
    const float* __restrict__ rd_Wih, const float* __restrict__ rd_Whh,
    const float* __restrict__ rd_fcW, const float* __restrict__ rd_fcb,
    const float* __restrict__ rd_bih, const float* __restrict__ rd_bhh,
    float* __restrict__ Weff, float* __restrict__ beff, float* __restrict__ loss)
{
    const int did = blockIdx.y;
    const float* Wih = did ? rd_Wih : pd_Wih;
    const float* Whh = did ? rd_Whh : pd_Whh;
    const float* fcW = did ? rd_fcW : pd_fcW;
    const float* fcb = did ? rd_fcb : pd_fcb;
    const float* bih = did ? rd_bih : pd_bih;
    const float* bhh = did ? rd_bhh : pd_bhh;
    float* We = Weff + (size_t)did * G4 * HSZ;
    float* be = beff + (size_t)did * G4;

    int j = blockIdx.x;
    int tid = threadIdx.x;
    if (blockIdx.x == 0 && did == 0 && tid < 2) loss[tid] = 0.f;

    __shared__ float swih[ISZ];
    __shared__ float red[128];
    for (int i = tid; i < ISZ; i += 128) swih[i] = Wih[j * ISZ + i];
    __syncthreads();
    if (tid < HSZ) {
        float acc = Whh[j * HSZ + tid];
        #pragma unroll 4
        for (int i = 0; i < ISZ; ++i)
            acc = fmaf(swih[i], fcW[i * HSZ + tid], acc);
        We[j * HSZ + tid] = acc;
    }
    float p = 0.f;
    for (int i = tid; i < ISZ; i += 128) p = fmaf(swih[i], fcb[i], p);
    red[tid] = p;
    __syncthreads();
    for (int s = 64; s > 0; s >>= 1) {
        if (tid < s) red[tid] += red[tid + s];
        __syncthreads();
    }
    if (tid == 0) be[j] = bih[j] + bhh[j] + red[0];
}

// ---------------- SIMT NT GEMM for the two small G0 GEMMs ------------------
#define AP 264
#define BP 68
__global__ __launch_bounds__(256) void gemm_g0(
    const float* __restrict__ A,
    const float* __restrict__ B0, const float* __restrict__ B1,
    const float* __restrict__ b10, const float* __restrict__ b11,
    const float* __restrict__ b20, const float* __restrict__ b21,
    float* __restrict__ Cbase, int M, int N, int K)
{
    const int did = blockIdx.z;
    const float* B = did ? B1 : B0;
    const float* bias1 = did ? b11 : b10;
    const float* bias2 = did ? b21 : b20;
    float* C = Cbase + (size_t)did * M * N;

    __shared__ float As[8 * AP];
    __shared__ float Bs[8 * BP];
    const int tid = threadIdx.x;
    const int tx = tid & 7;
    const int ty = tid >> 3;
    const int m0 = blockIdx.y * 256, n0 = blockIdx.x * 64;

    float acc[8][8];
    #pragma unroll
    for (int i = 0; i < 8; ++i)
        #pragma unroll
        for (int j = 0; j < 8; ++j) acc[i][j] = 0.f;

    const int am = m0 + tid;
    const int br = tid >> 2;
    const int bc = (tid & 3) * 2;

    for (int k0 = 0; k0 < K; k0 += 8) {
        #pragma unroll
        for (int j = 0; j < 8; ++j) {
            int k = k0 + j;
            As[j * AP + tid] = (am < M && k < K) ? A[(size_t)am * K + k] : 0.f;
        }
        {
            int n = n0 + br;
            #pragma unroll
            for (int j = 0; j < 2; ++j) {
                int k = k0 + bc + j;
                Bs[(bc + j) * BP + br] = (n < N && k < K) ? B[(size_t)n * K + k] : 0.f;
            }
        }
        __syncthreads();
        #pragma unroll
        for (int kk = 0; kk < 8; ++kk) {
            float4 a0 = *(const float4*)(As + kk * AP + ty * 8);
            float4 a1 = *(const float4*)(As + kk * AP + ty * 8 + 4);
            float4 b0 = *(const float4*)(Bs + kk * BP + tx * 8);
            float4 b1 = *(const float4*)(Bs + kk * BP + tx * 8 + 4);
            float av[8] = {a0.x, a0.y, a0.z, a0.w, a1.x, a1.y, a1.z, a1.w};
            float bv[8] = {b0.x, b0.y, b0.z, b0.w, b1.x, b1.y, b1.z, b1.w};
            #pragma unroll
            for (int i = 0; i < 8; ++i)
                #pragma unroll
                for (int j = 0; j < 8; ++j)
                    acc[i][j] = fmaf(av[i], bv[j], acc[i][j]);
        }
        __syncthreads();
    }

    #pragma unroll
    for (int i = 0; i < 8; ++i) {
        int m = m0 + ty * 8 + i;
        if (m < M) {
            #pragma unroll
            for (int j = 0; j < 8; ++j) {
                int n = n0 + tx * 8 + j;
                if (n < N) C[(size_t)m * N + n] = acc[i][j] + bias1[n] + bias2[n];
            }
        }
    }
}

// ---------------- tensor-core bf16 NT GEMM core -----------------------------
// CTA 128m x 64n, warps 4m x 2n, warp tile 32x32. LDSM fragment loads.
// A is plain bf16 (hi-only); B is split (hi+lo): 2 MMAs per fragment pair.
#define SAP 24

__device__ __forceinline__ void mma16816(float* d, const unsigned* a, const unsigned* b) {
    asm volatile(
        "mma.sync.aligned.m16n8k16.row.col.f32.bf16.bf16.f32 "
        "{%0,%1,%2,%3},{%4,%5,%6,%7},{%8,%9},{%0,%1,%2,%3};"
        : "+f"(d[0]), "+f"(d[1]), "+f"(d[2]), "+f"(d[3])
        : "r"(a[0]), "r"(a[1]), "r"(a[2]), "r"(a[3]), "r"(b[0]), "r"(b[1]));
}

__device__ __forceinline__ void ldsm_x4(unsigned* r, unsigned addr) {
    asm volatile(
        "ldmatrix.sync.aligned.m8n8.x4.shared.b16 {%0,%1,%2,%3}, [%4];"
        : "=r"(r[0]), "=r"(r[1]), "=r"(r[2]), "=r"(r[3]) : "r"(addr));
}

struct Bf16GemmSmem {
    __nv_bfloat16 Ash[2][128 * SAP];
    __nv_bfloat16 Bsh[2][64 * SAP];
    __nv_bfloat16 Bsl[2][64 * SAP];
    float red[256];
};

// A-hi-only mainloop (A plain bf16, B hi+lo): 2 MMAs per fragment pair.
__device__ __forceinline__ void bf16_mainloop_a1(
    Bf16GemmSmem* sm, float d[2][4][4],
    const __nv_bfloat16* Ah, int lda,
    const __nv_bfloat16* Bh, const __nv_bfloat16* Bl, int ldb,
    int m0, int n0, int M, int N, int Kp)
{
    const int tid = threadIdx.x;
    const int lane = tid & 31;
    const int wid = tid >> 5;
    const int wy = wid & 3;
    const int wx = wid >> 2;

    const int ar = tid >> 1;
    const int ah8 = (tid & 1) * 8;
    const int bs = tid & 127;
    const int brow = bs >> 1;
    const int bh8 = (bs & 1) * 8;
    const int gm = m0 + ar;
    const int gn = n0 + brow;
    const __nv_bfloat16* srcB = (tid < 128) ? Bh : Bl;

    const unsigned aoff =
        ((unsigned)((wy * 32 + ((lane >> 3) & 1) * 8 + (lane & 7)) * SAP
                    + (lane >> 4) * 8)) * 2u;
    const unsigned boff =
        ((unsigned)((wx * 32 + ((lane >> 4) & 1) * 8 + (lane & 7)) * SAP
                    + ((lane >> 3) & 1) * 8)) * 2u;

    const unsigned ashb = (unsigned)__cvta_generic_to_shared(sm->Ash[0]);
    const unsigned bshb = (unsigned)__cvta_generic_to_shared(sm->Bsh[0]);
    const unsigned bslb = (unsigned)__cvta_generic_to_shared(sm->Bsl[0]);
    const unsigned abuf = 128 * SAP * 2;
    const unsigned bbuf = 64 * SAP * 2;
    const unsigned ni2step = 16 * SAP * 2;
    const unsigned mistep = 16 * SAP * 2;

    const uint4 zv = make_uint4(0, 0, 0, 0);
    uint4 vh = zv, vb = zv;
    if (gm < M) vh = *(const uint4*)(Ah + (size_t)gm * lda + ah8);
    if (gn < N) vb = *(const uint4*)(srcB + (size_t)gn * ldb + bh8);

    const int niter = Kp / 16;
    for (int i = 0; i < niter; ++i) {
        const unsigned cur = (unsigned)(i & 1);
        *(uint4*)&sm->Ash[cur][ar * SAP + ah8] = vh;
        __nv_bfloat16* dstB = (tid < 128) ? sm->Bsh[cur] : sm->Bsl[cur];
        *(uint4*)&dstB[brow * SAP + bh8] = vb;
        __syncthreads();

        if (i + 1 < niter) {
            int kn = (i + 1) * 16;
            vh = zv; vb = zv;
            if (gm < M) vh = *(const uint4*)(Ah + (size_t)gm * lda + kn + ah8);
            if (gn < N) vb = *(const uint4*)(srcB + (size_t)gn * ldb + kn + bh8);
        }

        unsigned bhf[4][2], blf[4][2];
        {
            unsigned r[4];
            unsigned b0 = bshb + cur * bbuf + boff;
            ldsm_x4(r, b0);
            bhf[0][0] = r[0]; bhf[0][1] = r[1]; bhf[1][0] = r[2]; bhf[1][1] = r[3];
            ldsm_x4(r, b0 + ni2step);
            bhf[2][0] = r[0]; bhf[2][1] = r[1]; bhf[3][0] = r[2]; bhf[3][1] = r[3];
            unsigned b1 = bslb + cur * bbuf + boff;
            ldsm_x4(r, b1);
            blf[0][0] = r[0]; blf[0][1] = r[1]; blf[1][0] = r[2]; blf[1][1] = r[3];
            ldsm_x4(r, b1 + ni2step);
            blf[2][0] = r[0]; blf[2][1] = r[1]; blf[3][0] = r[2]; blf[3][1] = r[3];
        }
        #pragma unroll
        for (int mi = 0; mi < 2; ++mi) {
            unsigned ahf[4];
            ldsm_x4(ahf, ashb + cur * abuf + aoff + mi * mistep);
            #pragma unroll
            for (int ni = 0; ni < 4; ++ni) {
                mma16816(d[mi][ni], ahf, bhf[ni]);
                mma16816(d[mi][ni], ahf, blf[ni]);
            }
        }
    }
    __syncthreads();
}

// Phase-A variant: stores C with two biases.
__global__ __launch_bounds__(256, 3) void gemm_bf16_store(
    const __nv_bfloat16* __restrict__ Ah, int lda,
    const __nv_bfloat16* __restrict__ Bh, const __nv_bfloat16* __restrict__ Bl, int ldb,
    const float* __restrict__ bias1, const float* __restrict__ bias2,
    float* __restrict__ C, int M, int N, int Kp)
{
    extern __shared__ char smraw[];
    Bf16GemmSmem* sm = (Bf16GemmSmem*)smraw;
    const int tid = threadIdx.x;
    const int lane = tid & 31;
    const int wid = tid >> 5;
    const int wy = wid & 3, wx = wid >> 2;
    const int g = lane >> 2, t = lane & 3;
    const int m0 = blockIdx.y * 128, n0 = blockIdx.x * 64;

    float d[2][4][4];
    #pragma unroll
    for (int mi = 0; mi < 2; ++mi)
        #pragma unroll
        for (int ni = 0; ni < 4; ++ni)
            #pragma unroll
            for (int e = 0; e < 4; ++e) d[mi][ni][e] = 0.f;

    bf16_mainloop_a1(sm, d, Ah, lda, Bh, Bl, ldb, m0, n0, M, N, Kp);

    #pragma unroll
    for (int mi = 0; mi < 2; ++mi) {
        #pragma unroll
        for (int rr = 0; rr < 2; ++rr) {
            int m = m0 + wy * 32 + mi * 16 + rr * 8 + g;
            if (m >= M) continue;
            #pragma unroll
            for (int ni = 0; ni < 4; ++ni) {
                int n = n0 + wx * 32 + ni * 8 + 2 * t;
                if (n + 1 < N) {
                    float v0 = d[mi][ni][rr * 2 + 0] + bias1[n] + bias2[n];
                    float v1 = d[mi][ni][rr * 2 + 1] + bias1[n + 1] + bias2[n + 1];
                    *(float2*)(C + (size_t)m * N + n) = make_float2(v0, v1);
                } else if (n < N) {
                    C[(size_t)m * N + n] = d[mi][ni][rr * 2 + 0] + bias1[n] + bias2[n];
                }
            }
        }
    }
}

// Merged loss variant: A = decoder h (bf16 hi only); fused MSE epilogue.
__global__ __launch_bounds__(256, 3) void gemm_bf16_loss2(
    const __nv_bfloat16* __restrict__ Ahb,
    const __nv_bfloat16* __restrict__ Bhb, const __nv_bfloat16* __restrict__ Blb,
    const float* __restrict__ fcb0, const float* __restrict__ fcb1,
    const float* __restrict__ trg, const float* __restrict__ src,
    float* __restrict__ loss, int M, int N)
{
    extern __shared__ char smraw[];
    Bf16GemmSmem* sm = (Bf16GemmSmem*)smraw;
    const int did = blockIdx.z;
    const __nv_bfloat16* Ah = Ahb + (size_t)did * M * KPL;
    const __nv_bfloat16* Bh = Bhb + (size_t)did * N * KPL;
    const __nv_bfloat16* Bl = Blb + (size_t)did * N * KPL;
    const float* bias = did ? fcb1 : fcb0;
    const float* ref = did ? src : trg;
    float* lossOut = did ? (loss + 0) : (loss + 1);
    const int revT = did ? TSZ : 0;

    const int tid = threadIdx.x;
    const int lane = tid & 31;
    const int wid = tid >> 5;
    const int wy = wid & 3, wx = wid >> 2;
    const int g = lane >> 2, t = lane & 3;
    const int m0 = blockIdx.y * 128, n0 = blockIdx.x * 64;

    float d[2][4][4];
    #pragma unroll
    for (int mi = 0; mi < 2; ++mi)
        #pragma unroll
        for (int ni = 0; ni < 4; ++ni)
            #pragma unroll
            for (int e = 0; e < 4; ++e) d[mi][ni][e] = 0.f;

    bf16_mainloop_a1(sm, d, Ah, KPL, Bh, Bl, KPL, m0, n0, M, N, KPL);

    float ls = 0.f;
    #pragma unroll
    for (int mi = 0; mi < 2; ++mi) {
        #pragma unroll
        for (int rr = 0; rr < 2; ++rr) {
            int m = m0 + wy * 32 + mi * 16 + rr * 8 + g;
            if (m >= M) continue;
            const float* rrow;
            if (revT > 0) {
                int b = m / revT, tt = m - b * revT;
                rrow = ref + ((size_t)b * revT + (revT - 1 - tt)) * N;
            } else {
                rrow = ref + (size_t)m * N;
            }
            #pragma unroll
            for (int ni = 0; ni < 4; ++ni) {
                int n = n0 + wx * 32 + ni * 8 + 2 * t;
                #pragma unroll
                for (int e = 0; e < 2; ++e) {
                    if (n + e < N) {
                        float v = d[mi][ni][rr * 2 + e] + bias[n + e];
                        float diff = v - rrow[n + e];
                        ls = fmaf(diff, diff, ls);
                    }
                }
            }
        }
    }
    sm->red[tid] = ls;
    __syncthreads();
    for (int s = 128; s > 0; s >>= 1) {
        if (tid < s) sm->red[tid] += sm->red[tid + s];
        __syncthreads();
    }
    if (tid == 0) atomicAdd(lossOut, sm->red[0]);
}

// ---------------- LSTM recurrence kernels ----------------------------------
#define NB 7
#define NT_RNN 416
#define RNN_SMEM_F (40000 + 800 + 800 + 3600)

__global__ __launch_bounds__(NT_RNN, 1) void rnn_enc(
    const float* __restrict__ X, const float* __restrict__ Whh,
    float* __restrict__ hf, float* __restrict__ cf)
{
    extern __shared__ float s[];
    float* sW  = s;
    float* sHa = s + 40000;
    float* sHb = sHa + 800;
    float* sG  = sHb + 800;
    const int tid = threadIdx.x;
    const int b0 = blockIdx.x * NB;

    for (int i = tid; i < 10000; i += NT_RNN)
        ((float4*)sW)[i] = ((const float4*)Whh)[i];
    for (int i = tid; i < 800; i += NT_RNN) sHa[i] = 0.f;
    __syncthreads();

    const int i0 = tid, i1 = tid + NT_RNN;
    const int k0c = i0 % 100, b0c = i0 / 100;
    const int k1c = i1 % 100, b1c = i1 / 100;
    const bool v0 = (i0 < NB * 100), v1 = (i1 < NB * 100);
    float c0r = 0.f, c1r = 0.f, h0r = 0.f, h1r = 0.f;

    int bidx[NB];
    #pragma unroll
    for (int b = 0; b < NB; ++b) {
        int bb = b0 + b; if (bb > BSZ - 1) bb = BSZ - 1;
        bidx[b] = bb;
    }

    for (int t = 0; t < TSZ; ++t) {
        const float* hin = (t & 1) ? sHb : sHa;
        float* hout = (t & 1) ? sHa : sHb;
        if (tid < 400) {
            const int j = tid;
            float xr[NB];
            #pragma unroll
            for (int b = 0; b < NB; ++b)
                xr[b] = X[((size_t)bidx[b] * TSZ + t) * G4 + j];
            float acc[NB];
            #pragma unroll
            for (int b = 0; b < NB; ++b) acc[b] = 0.f;
            const float4* wj = (const float4*)(sW + j * 100);
            const float* hp = hin;
            #pragma unroll 5
            for (int k4 = 0; k4 < 25; ++k4) {
                float4 w = wj[k4];
                #pragma unroll
                for (int dd = 0; dd < 4; ++dd) {
                    float wv = (dd == 0) ? w.x : (dd == 1) ? w.y : (dd == 2) ? w.z : w.w;
                    float4 ha = *(const float4*)(hp + (k4 * 4 + dd) * 8);
                    float4 hb = *(const float4*)(hp + (k4 * 4 + dd) * 8 + 4);
                    acc[0] = fmaf(wv, ha.x, acc[0]);
                    acc[1] = fmaf(wv, ha.y, acc[1]);
                    acc[2] = fmaf(wv, ha.z, acc[2]);
                    acc[3] = fmaf(wv, ha.w, acc[3]);
                    acc[4] = fmaf(wv, hb.x, acc[4]);
                    acc[5] = fmaf(wv, hb.y, acc[5]);
                    acc[6] = fmaf(wv, hb.z, acc[6]);
                }
            }
            float* gp = sG + j * 9;
            #pragma unroll
            for (int b = 0; b < NB; ++b) gp[b] = acc[b] + xr[b];
        }
        __syncthreads();
        if (v0) {
            float gi = sigf(sG[(k0c) * 9 + b0c]);
            float gf = sigf(sG[(100 + k0c) * 9 + b0c]);
            float gg = tanhf_fast(sG[(200 + k0c) * 9 + b0c]);
            float go = sigf(sG[(300 + k0c) * 9 + b0c]);
            c0r = fmaf(gf, c0r, gi * gg);
            h0r = go * tanhf_fast(c0r);
            hout[k0c * 8 + b0c] = h0r;
        }
        if (v1) {
            float gi = sigf(sG[(k1c) * 9 + b1c]);
            float gf = sigf(sG[(100 + k1c) * 9 + b1c]);
            float gg = tanhf_fast(sG[(200 + k1c) * 9 + b1c]);
            float go = sigf(sG[(300 + k1c) * 9 + b1c]);
            c1r = fmaf(gf, c1r, gi * gg);
            h1r = go * tanhf_fast(c1r);
            hout[k1c * 8 + b1c] = h1r;
        }
        __syncthreads();
    }

    if (v0 && b0 + b0c < BSZ) {
        hf[(b0 + b0c) * HSZ + k0c] = h0r;
        cf[(b0 + b0c) * HSZ + k0c] = c0r;
    }
    if (v1 && b0 + b1c < BSZ) {
        hf[(b0 + b1c) * HSZ + k1c] = h1r;
        cf[(b0 + b1c) * HSZ + k1c] = c1r;
    }
}

// ---- merged decoders, NB=14 per CTA: grid (72, 2) = 144 CTAs = ONE wave ----
#define NBD 14
#define HP 16
#define GP 15
#define DEC_SMEM_F (40000 + 1600 + 1600 + 6000)

__global__ __launch_bounds__(NT_RNN, 1) void rnn_dec2(
    const float* __restrict__ G0base, const float* __restrict__ Weffbase,
    const float* __restrict__ beffbase,
    const float* __restrict__ h0, const float* __restrict__ c0,
    __nv_bfloat16* __restrict__ hdhb)
{
    extern __shared__ float s[];
    float* sW  = s;
    float* sHa = s + 40000;
    float* sHb = sHa + 1600;
    float* sG  = sHb + 1600;
    const int tid = threadIdx.x;
    const int b0 = blockIdx.x * NBD;
    const int did = blockIdx.y;

    const float* G0   = G0base + (size_t)did * BSZ * G4;
    const float* Weff = Weffbase + (size_t)did * G4 * HSZ;
    const float* beff = beffbase + (size_t)did * G4;
    __nv_bfloat16* hdh = hdhb + (size_t)did * BSZ * TSZ * KPL;

    for (int i = tid; i < 10000; i += NT_RNN)
        ((float4*)sW)[i] = ((const float4*)Weff)[i];
    for (int i = tid; i < 3200; i += NT_RNN) sHa[i] = 0.f;

    const float bq = (tid < 400) ? beff[tid] : 0.f;

    int bidx[NBD];
    #pragma unroll
    for (int b = 0; b < NBD; ++b) {
        int bb = b0 + b; if (bb > BSZ - 1) bb = BSZ - 1;
        bidx[b] = bb;
    }

    int ck[4], cb[4];
    bool cv[4], cw[4];
    float cc[4];
    __nv_bfloat16* outh[4];
    #pragma unroll
    for (int q = 0; q < 4; ++q) {
        int item = q * NT_RNN + tid;
        bool v = item < NBD * 100;
        int k = v ? (item % 100) : 0;
        int b = v ? (item / 100) : 0;
        ck[q] = k; cb[q] = b; cv[q] = v;
        cw[q] = v && (b0 + b < BSZ);
        cc[q] = 0.f;
        outh[q] = hdh + ((size_t)(b0 + b) * TSZ) * KPL + k;
    }
    __syncthreads();

    #pragma unroll
    for (int q = 0; q < 4; ++q) {
        if (cv[q]) {
            sHa[ck[q] * HP + cb[q]] = h0[bidx[cb[q]] * HSZ + ck[q]];
            cc[q] = c0[bidx[cb[q]] * HSZ + ck[q]];
        }
    }
    __syncthreads();

    for (int t = 0; t < TSZ; ++t) {
        const float* hin = (t & 1) ? sHb : sHa;
        float* hout = (t & 1) ? sHa : sHb;
        if (tid < 400) {
            const int j = tid;
            float* gp = sG + j * GP;
            if (t == 0) {
                #pragma unroll
                for (int b = 0; b < NBD; ++b)
                    gp[b] = G0[(size_t)bidx[b] * G4 + j];
            } else {
                float acc[NBD];
                #pragma unroll
                for (int b = 0; b < NBD; ++b) acc[b] = 0.f;
                const float4* wj = (const float4*)(sW + j * 100);
                const float* hp = hin;
                #pragma unroll 5
                for (int k4 = 0; k4 < 25; ++k4) {
                    float4 w = wj[k4];
                    #pragma unroll
                    for (int dd = 0; dd < 4; ++dd) {
                        float wv = (dd == 0) ? w.x : (dd == 1) ? w.y : (dd == 2) ? w.z : w.w;
                        const float* hr = hp + (k4 * 4 + dd) * HP;
                        float4 h0v = *(const float4*)(hr);
                        float4 h1v = *(const float4*)(hr + 4);
                        float4 h2v = *(const float4*)(hr + 8);
                        float2 h3v = *(const float2*)(hr + 12);
                        acc[0]  = fmaf(wv, h0v.x, acc[0]);
                        acc[1]  = fmaf(wv, h0v.y, acc[1]);
                        acc[2]  = fmaf(wv, h0v.z, acc[2]);
                        acc[3]  = fmaf(wv, h0v.w, acc[3]);
                        acc[4]  = fmaf(wv, h1v.x, acc[4]);
                        acc[5]  = fmaf(wv, h1v.y, acc[5]);
                        acc[6]  = fmaf(wv, h1v.z, acc[6]);
                        acc[7]  = fmaf(wv, h1v.w, acc[7]);
                        acc[8]  = fmaf(wv, h2v.x, acc[8]);
                        acc[9]  = fmaf(wv, h2v.y, acc[9]);
                        acc[10] = fmaf(wv, h2v.z, acc[10]);
                        acc[11] = fmaf(wv, h2v.w, acc[11]);
                        acc[12] = fmaf(wv, h3v.x, acc[12]);
                        acc[13] = fmaf(wv, h3v.y, acc[13]);
                    }
                }
                #pragma unroll
                for (int b = 0; b < NBD; ++b) gp[b] = acc[b] + bq;
            }
        }
        __syncthreads();
        #pragma unroll
        for (int q = 0; q < 4; ++q) {
            if (cv[q]) {
                int k = ck[q], b = cb[q];
                float gi = sigf(sG[(k) * GP + b]);
                float gf = sigf(sG[(100 + k) * GP + b]);
                float gg = tanhf_fast(sG[(200 + k) * GP + b]);
                float go = sigf(sG[(300 + k) * GP + b]);
                float c = fmaf(gf, cc[q], gi * gg);
                cc[q] = c;
                float h = go * tanhf_fast(c);
                hout[k * HP + b] = h;
                if (cw[q])
                    outh[q][(size_t)t * KPL] = __float2bfloat16(h);
            }
        }
        __syncthreads();
    }
}

// ---------------- launch ----------------------------------------------------
extern "C" void kernel_launch(void* const* d_in, const int* in_sizes, int n_in,
                              void* d_out, int out_size)
{
    const float* src     = (const float*)d_in[0];
    const float* trg     = (const float*)d_in[1];
    const float* enc_Wih = (const float*)d_in[2];
    const float* enc_Whh = (const float*)d_in[3];
    const float* enc_bih = (const float*)d_in[4];
    const float* enc_bhh = (const float*)d_in[5];
    const float* pd_Wih  = (const float*)d_in[6];
    const float* pd_Whh  = (const float*)d_in[7];
    const float* pd_bih  = (const float*)d_in[8];
    const float* pd_bhh  = (const float*)d_in[9];
    const float* pd_fcW  = (const float*)d_in[10];
    const float* pd_fcb  = (const float*)d_in[11];
    const float* rd_Wih  = (const float*)d_in[12];
    const float* rd_Whh  = (const float*)d_in[13];
    const float* rd_bih  = (const float*)d_in[14];
    const float* rd_bhh  = (const float*)d_in[15];
    const float* rd_fcW  = (const float*)d_in[16];
    const float* rd_fcb  = (const float*)d_in[17];
    float* out = (float*)d_out;

    float *pX, *pHenc, *pCenc, *pG0, *pWeff, *pBeff, *pLoss;
    __nv_bfloat16 *pSrch, *pWihh, *pWihl, *pFcwh, *pFcwl, *pHdh;
    cudaGetSymbolAddress((void**)&pX,    g_X);
    cudaGetSymbolAddress((void**)&pHenc, g_henc);
    cudaGetSymbolAddress((void**)&pCenc, g_cenc);
    cudaGetSymbolAddress((void**)&pG0,   g_G0);
    cudaGetSymbolAddress((void**)&pWeff, g_Weff);
    cudaGetSymbolAddress((void**)&pBeff, g_beff);
    cudaGetSymbolAddress((void**)&pLoss, g_loss);
    cudaGetSymbolAddress((void**)&pSrch, g_srch);
    cudaGetSymbolAddress((void**)&pWihh, g_wihh);
    cudaGetSymbolAddress((void**)&pWihl, g_wihl);
    cudaGetSymbolAddress((void**)&pFcwh, g_fcwh);
    cudaGetSymbolAddress((void**)&pFcwl, g_fcwl);
    cudaGetSymbolAddress((void**)&pHdh,  g_hdh);

    const int SMEM_RNN = RNN_SMEM_F * 4;
    const int SMEM_DEC = DEC_SMEM_F * 4;
    const int SMEM_GEMM = (int)sizeof(Bf16GemmSmem);
    cudaFuncSetAttribute(rnn_enc,  cudaFuncAttributeMaxDynamicSharedMemorySize, SMEM_RNN);
    cudaFuncSetAttribute(rnn_dec2, cudaFuncAttributeMaxDynamicSharedMemorySize, SMEM_DEC);
    cudaFuncSetAttribute(gemm_bf16_store, cudaFuncAttributeMaxDynamicSharedMemorySize, SMEM_GEMM);
    cudaFuncSetAttribute(gemm_bf16_loss2, cudaFuncAttributeMaxDynamicSharedMemorySize, SMEM_GEMM);

    const int RNN_BLOCKS = (BSZ + NB - 1) / NB;     // 143
    const int DEC_BLOCKS = (BSZ + NBD - 1) / NBD;   // 72
    const int MROWS = BSZ * TSZ;                    // 100000

    // launches 1-3: prep (launch #4 = phase-A tensor GEMM, the profiled slot)
    cvt_hi_t<ISZ, KPA><<<(MROWS * (KPA / 4) + 255) / 256, 256>>>(src, pSrch, MROWS);
    cvt_split_t<ISZ, KPA><<<(G4 * (KPA / 4) + 255) / 256, 256>>>(enc_Wih, pWihh, pWihl, G4);
    {
        dim3 grid(G4, 2);
        fold2_kernel<<<grid, 128>>>(pd_Wih, pd_Whh, pd_fcW, pd_fcb, pd_bih, pd_bhh,
                                    rd_Wih, rd_Whh, rd_fcW, rd_fcb, rd_bih, rd_bhh,
                                    pWeff, pBeff, pLoss);
    }

    // launch 4: phase A (tensor cores, A hi-only + B split)
    {
        dim3 grid((G4 + 63) / 64, (MROWS + 127) / 128);
        gemm_bf16_store<<<grid, 256, SMEM_GEMM>>>(pSrch, KPA, pWihh, pWihl, KPA,
                                                  enc_bih, enc_bhh, pX, MROWS, G4, KPA);
    }

    // encoder recurrence
    rnn_enc<<<RNN_BLOCKS, NT_RNN, SMEM_RNN>>>(pX, enc_Whh, pHenc, pCenc);

    // fcW splits (only needed by loss GEMMs)
    cvt_split_t<HSZ, KPL><<<(ISZ * (KPL / 4) + 255) / 256, 256>>>(pd_fcW, pFcwh, pFcwl, ISZ);
    cvt_split_t<HSZ, KPL><<<(ISZ * (KPL / 4) + 255) / 256, 256>>>(rd_fcW, pFcwh + ISZ * KPL,
                                                                  pFcwl + ISZ * KPL, ISZ);

    // decoder step-0 gates (both decoders, one launch)
    {
        dim3 grid((G4 + 63) / 64, (BSZ + 255) / 256, 2);
        gemm_g0<<<grid, 256>>>(pHenc, pd_Whh, rd_Whh, pd_bih, rd_bih,
                               pd_bhh, rd_bhh, pG0, BSZ, G4, HSZ);
    }

    // merged decoders: 144 CTAs = one full wave
    {
        dim3 grid(DEC_BLOCKS, 2);
        rnn_dec2<<<grid, NT_RNN, SMEM_DEC>>>(pG0, pWeff, pBeff, pHenc, pCenc, pHdh);
    }

    // merged losses (tensor cores, A = hi-only decoder h, fused MSE epilogue)
    {
        dim3 grid((ISZ + 63) / 64, (MROWS + 127) / 128, 2);
        gemm_bf16_loss2<<<grid, 256, SMEM_GEMM>>>(pHdh, pFcwh, pFcwl,
                                                  pd_fcb, rd_fcb, trg, src,
                                                  pLoss, MROWS, ISZ);
    }

    finalize_kernel<<<1, 1>>>(pLoss, out, 1.0f / (float)(BSZ * TSZ * ISZ));
}

// round 14
// speedup vs baseline: 1.1685x; 1.0157x over previous
#include <cuda_runtime.h>
#include <cuda_bf16.h>
#include <math.h>

#define BSZ 1000
#define TSZ 100
#define ISZ 264
#define HSZ 100
#define G4  400   // 4*H
#define KPA 272   // padded K for phase A (264 -> 17*16)
#define KPL 112   // padded K for loss GEMMs (100 -> 7*16)

// ---------------- device scratch (static: no allocation allowed) ----------
__device__ float g_X[(size_t)BSZ * TSZ * G4];       // encoder gate inputs fp32
__device__ float g_henc[BSZ * HSZ];
__device__ float g_cenc[BSZ * HSZ];
__device__ float g_Weff[2][G4 * HSZ];
__device__ float g_beff[2][G4];
__device__ float g_loss[2];

// bf16 operands
__device__ __nv_bfloat16 g_srch[(size_t)BSZ * TSZ * KPA];
__device__ __nv_bfloat16 g_wihh[G4 * KPA];
__device__ __nv_bfloat16 g_wihl[G4 * KPA];
__device__ __nv_bfloat16 g_fcwh[2][ISZ * KPL];
__device__ __nv_bfloat16 g_hdh[2][(size_t)BSZ * TSZ * KPL];  // decoder h (bf16)

// ---------------- fast activations (ex2/rcp approx: ~2^-22 rel err) --------
__device__ __forceinline__ float ex2f(float x) {
    float r; asm("ex2.approx.f32 %0, %1;" : "=f"(r) : "f"(x)); return r;
}
__device__ __forceinline__ float rcpf(float x) {
    float r; asm("rcp.approx.f32 %0, %1;" : "=f"(r) : "f"(x)); return r;
}
__device__ __forceinline__ float sigf(float x) {
    return rcpf(1.f + ex2f(-1.4426950408889634f * x));
}
__device__ __forceinline__ float tanhf_fast(float x) {
    return fmaf(2.f, rcpf(1.f + ex2f(-2.8853900817779268f * x)), -1.f);
}

// ---------------- small kernels -------------------------------------------
__global__ void finalize_kernel(const float* loss, float* out, float inv) {
    out[0] = loss[0] * inv;
    out[1] = loss[1] * inv;
}

// fp32 -> bf16 hi only, K padded to Kp.
template <int K, int Kp>
__global__ __launch_bounds__(256) void cvt_hi_t(
    const float* __restrict__ x, __nv_bfloat16* __restrict__ h, int rows)
{
    const int Kp4 = Kp / 4;
    int idx = blockIdx.x * 256 + threadIdx.x;
    if (idx >= rows * Kp4) return;
    int r = idx / Kp4;
    int k4 = (idx - r * Kp4) * 4;
    float4 v;
    if (k4 + 3 < K) {
        v = *(const float4*)(x + (size_t)r * K + k4);
    } else {
        float tmp[4] = {0.f, 0.f, 0.f, 0.f};
        #pragma unroll
        for (int e = 0; e < 4; ++e)
            if (k4 + e < K) tmp[e] = x[(size_t)r * K + k4 + e];
        v = make_float4(tmp[0], tmp[1], tmp[2], tmp[3]);
    }
    __nv_bfloat16 hh[4];
    hh[0] = __float2bfloat16(v.x);
    hh[1] = __float2bfloat16(v.y);
    hh[2] = __float2bfloat16(v.z);
    hh[3] = __float2bfloat16(v.w);
    *(uint2*)(h + (size_t)idx * 4) = *(const uint2*)hh;
}

// fp32 -> (bf16 hi, bf16 lo), K padded to Kp.
template <int K, int Kp>
__global__ __launch_bounds__(256) void cvt_split_t(
    const float* __restrict__ x, __nv_bfloat16* __restrict__ h,
    __nv_bfloat16* __restrict__ l, int rows)
{
    const int Kp4 = Kp / 4;
    int idx = blockIdx.x * 256 + threadIdx.x;
    if (idx >= rows * Kp4) return;
    int r = idx / Kp4;
    int k4 = (idx - r * Kp4) * 4;
    float4 v;
    if (k4 + 3 < K) {
        v = *(const float4*)(x + (size_t)r * K + k4);
    } else {
        float tmp[4] = {0.f, 0.f, 0.f, 0.f};
        #pragma unroll
        for (int e = 0; e < 4; ++e)
            if (k4 + e < K) tmp[e] = x[(size_t)r * K + k4 + e];
        v = make_float4(tmp[0], tmp[1], tmp[2], tmp[3]);
    }
    float vv[4] = {v.x, v.y, v.z, v.w};
    __nv_bfloat16 hh[4], ll[4];
    #pragma unroll
    for (int e = 0; e < 4; ++e) {
        hh[e] = __float2bfloat16(vv[e]);
        ll[e] = __float2bfloat16(vv[e] - __bfloat162float(hh[e]));
    }
    *(uint2*)(h + (size_t)idx * 4) = *(const uint2*)hh;
    *(uint2*)(l + (size_t)idx * 4) = *(const uint2*)ll;
}

// Both decoder folds in one launch: blockIdx.y selects decoder.
__global__ __launch_bounds__(128) void fold2_kernel(
    const float* __restrict__ pd_Wih, const float* __restrict__ pd_Whh,
    const float* __restrict__ pd_fcW, const float* __restrict__ pd_fcb,
    const float* __restrict__ pd_bih, const float* __restrict__ pd_bhh,
    const float* __restrict__ rd_Wih, const float* __restrict__ rd_Whh,
    const float* __restrict__ rd_fcW, const float* __restrict__ rd_fcb,
    const float* __restrict__ rd_bih, const float* __restrict__ rd_bhh,
    float* __restrict__ Weff, float* __restrict__ beff, float* __restrict__ loss)
{
    const int did = blockIdx.y;
    const float* Wih = did ? rd_Wih : pd_Wih;
    const float* Whh = did ? rd_Whh : pd_Whh;
    const float* fcW = did ? rd_fcW : pd_fcW;
    const float* fcb = did ? rd_fcb : pd_fcb;
    const float* bih = did ? rd_bih : pd_bih;
    const float* bhh = did ? rd_bhh : pd_bhh;
    float* We = Weff + (size_t)did * G4 * HSZ;
    float* be = beff + (size_t)did * G4;

    int j = blockIdx.x;
    int tid = threadIdx.x;
    if (blockIdx.x == 0 && did == 0 && tid < 2) loss[tid] = 0.f;

    __shared__ float swih[ISZ];
    __shared__ float red[128];
    for (int i = tid; i < ISZ; i += 128) swih[i] = Wih[j * ISZ + i];
    __syncthreads();
    if (tid < HSZ) {
        float acc = Whh[j * HSZ + tid];
        #pragma unroll 4
        for (int i = 0; i < ISZ; ++i)
            acc = fmaf(swih[i], fcW[i * HSZ + tid], acc);
        We[j * HSZ + tid] = acc;
    }
    float p = 0.f;
    for (int i = tid; i < ISZ; i += 128) p = fmaf(swih[i], fcb[i], p);
    red[tid] = p;
    __syncthreads();
    for (int s = 64; s > 0; s >>= 1) {
        if (tid < s) red[tid] += red[tid + s];
        __syncthreads();
    }
    if (tid == 0) be[j] = bih[j] + bhh[j] + red[0];
}

// ---------------- tensor-core bf16 NT GEMM core -----------------------------
// CTA 128m x 64n, warps 4m x 2n, warp tile 32x32. LDSM fragment loads.
#define SAP 24

__device__ __forceinline__ void mma16816(float* d, const unsigned* a, const unsigned* b) {
    asm volatile(
        "mma.sync.aligned.m16n8k16.row.col.f32.bf16.bf16.f32 "
        "{%0,%1,%2,%3},{%4,%5,%6,%7},{%8,%9},{%0,%1,%2,%3};"
        : "+f"(d[0]), "+f"(d[1]), "+f"(d[2]), "+f"(d[3])
        : "r"(a[0]), "r"(a[1]), "r"(a[2]), "r"(a[3]), "r"(b[0]), "r"(b[1]));
}

__device__ __forceinline__ void ldsm_x4(unsigned* r, unsigned addr) {
    asm volatile(
        "ldmatrix.sync.aligned.m8n8.x4.shared.b16 {%0,%1,%2,%3}, [%4];"
        : "=r"(r[0]), "=r"(r[1]), "=r"(r[2]), "=r"(r[3]) : "r"(addr));
}

struct Bf16GemmSmem {
    __nv_bfloat16 Ash[2][128 * SAP];
    __nv_bfloat16 Bsh[2][64 * SAP];
    __nv_bfloat16 Bsl[2][64 * SAP];
    float red[256];
};

// A hi-only, B split (hi+lo): 2 MMAs per fragment pair. (phase A)
__device__ __forceinline__ void bf16_mainloop_a1(
    Bf16GemmSmem* sm, float d[2][4][4],
    const __nv_bfloat16* Ah, int lda,
    const __nv_bfloat16* Bh, const __nv_bfloat16* Bl, int ldb,
    int m0, int n0, int M, int N, int Kp)
{
    const int tid = threadIdx.x;
    const int lane = tid & 31;
    const int wid = tid >> 5;
    const int wy = wid & 3;
    const int wx = wid >> 2;

    const int ar = tid >> 1;
    const int ah8 = (tid & 1) * 8;
    const int bs = tid & 127;
    const int brow = bs >> 1;
    const int bh8 = (bs & 1) * 8;
    const int gm = m0 + ar;
    const int gn = n0 + brow;
    const __nv_bfloat16* srcB = (tid < 128) ? Bh : Bl;

    const unsigned aoff =
        ((unsigned)((wy * 32 + ((lane >> 3) & 1) * 8 + (lane & 7)) * SAP
                    + (lane >> 4) * 8)) * 2u;
    const unsigned boff =
        ((unsigned)((wx * 32 + ((lane >> 4) & 1) * 8 + (lane & 7)) * SAP
                    + ((lane >> 3) & 1) * 8)) * 2u;

    const unsigned ashb = (unsigned)__cvta_generic_to_shared(sm->Ash[0]);
    const unsigned bshb = (unsigned)__cvta_generic_to_shared(sm->Bsh[0]);
    const unsigned bslb = (unsigned)__cvta_generic_to_shared(sm->Bsl[0]);
    const unsigned abuf = 128 * SAP * 2;
    const unsigned bbuf = 64 * SAP * 2;
    const unsigned ni2step = 16 * SAP * 2;
    const unsigned mistep = 16 * SAP * 2;

    const uint4 zv = make_uint4(0, 0, 0, 0);
    uint4 vh = zv, vb = zv;
    if (gm < M) vh = *(const uint4*)(Ah + (size_t)gm * lda + ah8);
    if (gn < N) vb = *(const uint4*)(srcB + (size_t)gn * ldb + bh8);

    const int niter = Kp / 16;
    for (int i = 0; i < niter; ++i) {
        const unsigned cur = (unsigned)(i & 1);
        *(uint4*)&sm->Ash[cur][ar * SAP + ah8] = vh;
        __nv_bfloat16* dstB = (tid < 128) ? sm->Bsh[cur] : sm->Bsl[cur];
        *(uint4*)&dstB[brow * SAP + bh8] = vb;
        __syncthreads();

        if (i + 1 < niter) {
            int kn = (i + 1) * 16;
            vh = zv; vb = zv;
            if (gm < M) vh = *(const uint4*)(Ah + (size_t)gm * lda + kn + ah8);
            if (gn < N) vb = *(const uint4*)(srcB + (size_t)gn * ldb + kn + bh8);
        }

        unsigned bhf[4][2], blf[4][2];
        {
            unsigned r[4];
            unsigned b0 = bshb + cur * bbuf + boff;
            ldsm_x4(r, b0);
            bhf[0][0] = r[0]; bhf[0][1] = r[1]; bhf[1][0] = r[2]; bhf[1][1] = r[3];
            ldsm_x4(r, b0 + ni2step);
            bhf[2][0] = r[0]; bhf[2][1] = r[1]; bhf[3][0] = r[2]; bhf[3][1] = r[3];
            unsigned b1 = bslb + cur * bbuf + boff;
            ldsm_x4(r, b1);
            blf[0][0] = r[0]; blf[0][1] = r[1]; blf[1][0] = r[2]; blf[1][1] = r[3];
            ldsm_x4(r, b1 + ni2step);
            blf[2][0] = r[0]; blf[2][1] = r[1]; blf[3][0] = r[2]; blf[3][1] = r[3];
        }
        #pragma unroll
        for (int mi = 0; mi < 2; ++mi) {
            unsigned ahf[4];
            ldsm_x4(ahf, ashb + cur * abuf + aoff + mi * mistep);
            #pragma unroll
            for (int ni = 0; ni < 4; ++ni) {
                mma16816(d[mi][ni], ahf, bhf[ni]);
                mma16816(d[mi][ni], ahf, blf[ni]);
            }
        }
    }
    __syncthreads();
}

// A hi-only, B hi-only: 1 MMA per fragment pair. (loss GEMMs)
__device__ __forceinline__ void bf16_mainloop_11(
    Bf16GemmSmem* sm, float d[2][4][4],
    const __nv_bfloat16* Ah, int lda,
    const __nv_bfloat16* Bh, int ldb,
    int m0, int n0, int M, int N, int Kp)
{
    const int tid = threadIdx.x;
    const int lane = tid & 31;
    const int wid = tid >> 5;
    const int wy = wid & 3;
    const int wx = wid >> 2;

    const int ar = tid >> 1;
    const int ah8 = (tid & 1) * 8;
    const int brow = (tid & 127) >> 1;
    const int bh8 = (tid & 1) * 8;
    const int gm = m0 + ar;
    const int gn = n0 + brow;
    const bool bldr = (tid < 128);

    const unsigned aoff =
        ((unsigned)((wy * 32 + ((lane >> 3) & 1) * 8 + (lane & 7)) * SAP
                    + (lane >> 4) * 8)) * 2u;
    const unsigned boff =
        ((unsigned)((wx * 32 + ((lane >> 4) & 1) * 8 + (lane & 7)) * SAP
                    + ((lane >> 3) & 1) * 8)) * 2u;

    const unsigned ashb = (unsigned)__cvta_generic_to_shared(sm->Ash[0]);
    const unsigned bshb = (unsigned)__cvta_generic_to_shared(sm->Bsh[0]);
    const unsigned abuf = 128 * SAP * 2;
    const unsigned bbuf = 64 * SAP * 2;
    const unsigned ni2step = 16 * SAP * 2;
    const unsigned mistep = 16 * SAP * 2;

    const uint4 zv = make_uint4(0, 0, 0, 0);
    uint4 vh = zv, vb = zv;
    if (gm < M) vh = *(const uint4*)(Ah + (size_t)gm * lda + ah8);
    if (bldr && gn < N) vb = *(const uint4*)(Bh + (size_t)gn * ldb + bh8);

    const int niter = Kp / 16;
    for (int i = 0; i < niter; ++i) {
        const unsigned cur = (unsigned)(i & 1);
        *(uint4*)&sm->Ash[cur][ar * SAP + ah8] = vh;
        if (bldr) *(uint4*)&sm->Bsh[cur][brow * SAP + bh8] = vb;
        __syncthreads();

        if (i + 1 < niter) {
            int kn = (i + 1) * 16;
            vh = zv; vb = zv;
            if (gm < M) vh = *(const uint4*)(Ah + (size_t)gm * lda + kn + ah8);
            if (bldr && gn < N) vb = *(const uint4*)(Bh + (size_t)gn * ldb + kn + bh8);
        }

        unsigned bhf[4][2];
        {
            unsigned r[4];
            unsigned b0 = bshb + cur * bbuf + boff;
            ldsm_x4(r, b0);
            bhf[0][0] = r[0]; bhf[0][1] = r[1]; bhf[1][0] = r[2]; bhf[1][1] = r[3];
            ldsm_x4(r, b0 + ni2step);
            bhf[2][0] = r[0]; bhf[2][1] = r[1]; bhf[3][0] = r[2]; bhf[3][1] = r[3];
        }
        #pragma unroll
        for (int mi = 0; mi < 2; ++mi) {
            unsigned ahf[4];
            ldsm_x4(ahf, ashb + cur * abuf + aoff + mi * mistep);
            #pragma unroll
            for (int ni = 0; ni < 4; ++ni)
                mma16816(d[mi][ni], ahf, bhf[ni]);
        }
    }
    __syncthreads();
}

// Phase-A variant: stores C with two biases.
__global__ __launch_bounds__(256, 3) void gemm_bf16_store(
    const __nv_bfloat16* __restrict__ Ah, int lda,
    const __nv_bfloat16* __restrict__ Bh, const __nv_bfloat16* __restrict__ Bl, int ldb,
    const float* __restrict__ bias1, const float* __restrict__ bias2,
    float* __restrict__ C, int M, int N, int Kp)
{
    extern __shared__ char smraw[];
    Bf16GemmSmem* sm = (Bf16GemmSmem*)smraw;
    const int tid = threadIdx.x;
    const int lane = tid & 31;
    const int wid = tid >> 5;
    const int wy = wid & 3, wx = wid >> 2;
    const int g = lane >> 2, t = lane & 3;
    const int m0 = blockIdx.y * 128, n0 = blockIdx.x * 64;

    float d[2][4][4];
    #pragma unroll
    for (int mi = 0; mi < 2; ++mi)
        #pragma unroll
        for (int ni = 0; ni < 4; ++ni)
            #pragma unroll
            for (int e = 0; e < 4; ++e) d[mi][ni][e] = 0.f;

    bf16_mainloop_a1(sm, d, Ah, lda, Bh, Bl, ldb, m0, n0, M, N, Kp);

    #pragma unroll
    for (int mi = 0; mi < 2; ++mi) {
        #pragma unroll
        for (int rr = 0; rr < 2; ++rr) {
            int m = m0 + wy * 32 + mi * 16 + rr * 8 + g;
            if (m >= M) continue;
            #pragma unroll
            for (int ni = 0; ni < 4; ++ni) {
                int n = n0 + wx * 32 + ni * 8 + 2 * t;
                if (n + 1 < N) {
                    float v0 = d[mi][ni][rr * 2 + 0] + bias1[n] + bias2[n];
                    float v1 = d[mi][ni][rr * 2 + 1] + bias1[n + 1] + bias2[n + 1];
                    *(float2*)(C + (size_t)m * N + n) = make_float2(v0, v1);
                } else if (n < N) {
                    C[(size_t)m * N + n] = d[mi][ni][rr * 2 + 0] + bias1[n] + bias2[n];
                }
            }
        }
    }
}

// Merged loss variant: A = decoder h, B = fcW (both bf16 hi only); fused MSE.
__global__ __launch_bounds__(256, 3) void gemm_bf16_loss2(
    const __nv_bfloat16* __restrict__ Ahb,
    const __nv_bfloat16* __restrict__ Bhb,
    const float* __restrict__ fcb0, const float* __restrict__ fcb1,
    const float* __restrict__ trg, const float* __restrict__ src,
    float* __restrict__ loss, int M, int N)
{
    extern __shared__ char smraw[];
    Bf16GemmSmem* sm = (Bf16GemmSmem*)smraw;
    const int did = blockIdx.z;
    const __nv_bfloat16* Ah = Ahb + (size_t)did * M * KPL;
    const __nv_bfloat16* Bh = Bhb + (size_t)did * N * KPL;
    const float* bias = did ? fcb1 : fcb0;
    const float* ref = did ? src : trg;
    float* lossOut = did ? (loss + 0) : (loss + 1);
    const int revT = did ? TSZ : 0;

    const int tid = threadIdx.x;
    const int lane = tid & 31;
    const int wid = tid >> 5;
    const int wy = wid & 3, wx = wid >> 2;
    const int g = lane >> 2, t = lane & 3;
    const int m0 = blockIdx.y * 128, n0 = blockIdx.x * 64;

    float d[2][4][4];
    #pragma unroll
    for (int mi = 0; mi < 2; ++mi)
        #pragma unroll
        for (int ni = 0; ni < 4; ++ni)
            #pragma unroll
            for (int e = 0; e < 4; ++e) d[mi][ni][e] = 0.f;

    bf16_mainloop_11(sm, d, Ah, KPL, Bh, KPL, m0, n0, M, N, KPL);

    float ls = 0.f;
    #pragma unroll
    for (int mi = 0; mi < 2; ++mi) {
        #pragma unroll
        for (int rr = 0; rr < 2; ++rr) {
            int m = m0 + wy * 32 + mi * 16 + rr * 8 + g;
            if (m >= M) continue;
            const float* rrow;
            if (revT > 0) {
                int b = m / revT, tt = m - b * revT;
                rrow = ref + ((size_t)b * revT + (revT - 1 - tt)) * N;
            } else {
                rrow = ref + (size_t)m * N;
            }
            #pragma unroll
            for (int ni = 0; ni < 4; ++ni) {
                int n = n0 + wx * 32 + ni * 8 + 2 * t;
                #pragma unroll
                for (int e = 0; e < 2; ++e) {
                    if (n + e < N) {
                        float v = d[mi][ni][rr * 2 + e] + bias[n + e];
                        float diff = v - rrow[n + e];
                        ls = fmaf(diff, diff, ls);
                    }
                }
            }
        }
    }
    sm->red[tid] = ls;
    __syncthreads();
    for (int s = 128; s > 0; s >>= 1) {
        if (tid < s) sm->red[tid] += sm->red[tid + s];
        __syncthreads();
    }
    if (tid == 0) atomicAdd(lossOut, sm->red[0]);
}

// ---------------- LSTM recurrence kernels ----------------------------------
#define NB 7
#define NT_RNN 416
#define RNN_SMEM_F (40000 + 800 + 800 + 3600)

__global__ __launch_bounds__(NT_RNN, 1) void rnn_enc(
    const float* __restrict__ X, const float* __restrict__ Whh,
    float* __restrict__ hf, float* __restrict__ cf)
{
    extern __shared__ float s[];
    float* sW  = s;
    float* sHa = s + 40000;
    float* sHb = sHa + 800;
    float* sG  = sHb + 800;
    const int tid = threadIdx.x;
    const int b0 = blockIdx.x * NB;

    for (int i = tid; i < 10000; i += NT_RNN)
        ((float4*)sW)[i] = ((const float4*)Whh)[i];
    for (int i = tid; i < 800; i += NT_RNN) sHa[i] = 0.f;
    __syncthreads();

    const int i0 = tid, i1 = tid + NT_RNN;
    const int k0c = i0 % 100, b0c = i0 / 100;
    const int k1c = i1 % 100, b1c = i1 / 100;
    const bool v0 = (i0 < NB * 100), v1 = (i1 < NB * 100);
    float c0r = 0.f, c1r = 0.f, h0r = 0.f, h1r = 0.f;

    int bidx[NB];
    #pragma unroll
    for (int b = 0; b < NB; ++b) {
        int bb = b0 + b; if (bb > BSZ - 1) bb = BSZ - 1;
        bidx[b] = bb;
    }

    for (int t = 0; t < TSZ; ++t) {
        const float* hin = (t & 1) ? sHb : sHa;
        float* hout = (t & 1) ? sHa : sHb;
        if (tid < 400) {
            const int j = tid;
            float xr[NB];
            #pragma unroll
            for (int b = 0; b < NB; ++b)
                xr[b] = X[((size_t)bidx[b] * TSZ + t) * G4 + j];
            float acc[NB];
            #pragma unroll
            for (int b = 0; b < NB; ++b) acc[b] = 0.f;
            const float4* wj = (const float4*)(sW + j * 100);
            const float* hp = hin;
            #pragma unroll 5
            for (int k4 = 0; k4 < 25; ++k4) {
                float4 w = wj[k4];
                #pragma unroll
                for (int dd = 0; dd < 4; ++dd) {
                    float wv = (dd == 0) ? w.x : (dd == 1) ? w.y : (dd == 2) ? w.z : w.w;
                    float4 ha = *(const float4*)(hp + (k4 * 4 + dd) * 8);
                    float4 hb = *(const float4*)(hp + (k4 * 4 + dd) * 8 + 4);
                    acc[0] = fmaf(wv, ha.x, acc[0]);
                    acc[1] = fmaf(wv, ha.y, acc[1]);
                    acc[2] = fmaf(wv, ha.z, acc[2]);
                    acc[3] = fmaf(wv, ha.w, acc[3]);
                    acc[4] = fmaf(wv, hb.x, acc[4]);
                    acc[5] = fmaf(wv, hb.y, acc[5]);
                    acc[6] = fmaf(wv, hb.z, acc[6]);
                }
            }
            float* gp = sG + j * 9;
            #pragma unroll
            for (int b = 0; b < NB; ++b) gp[b] = acc[b] + xr[b];
        }
        __syncthreads();
        if (v0) {
            float gi = sigf(sG[(k0c) * 9 + b0c]);
            float gf = sigf(sG[(100 + k0c) * 9 + b0c]);
            float gg = tanhf_fast(sG[(200 + k0c) * 9 + b0c]);
            float go = sigf(sG[(300 + k0c) * 9 + b0c]);
            c0r = fmaf(gf, c0r, gi * gg);
            h0r = go * tanhf_fast(c0r);
            hout[k0c * 8 + b0c] = h0r;
        }
        if (v1) {
            float gi = sigf(sG[(k1c) * 9 + b1c]);
            float gf = sigf(sG[(100 + k1c) * 9 + b1c]);
            float gg = tanhf_fast(sG[(200 + k1c) * 9 + b1c]);
            float go = sigf(sG[(300 + k1c) * 9 + b1c]);
            c1r = fmaf(gf, c1r, gi * gg);
            h1r = go * tanhf_fast(c1r);
            hout[k1c * 8 + b1c] = h1r;
        }
        __syncthreads();
    }

    if (v0 && b0 + b0c < BSZ) {
        hf[(b0 + b0c) * HSZ + k0c] = h0r;
        cf[(b0 + b0c) * HSZ + k0c] = c0r;
    }
    if (v1 && b0 + b1c < BSZ) {
        hf[(b0 + b1c) * HSZ + k1c] = h1r;
        cf[(b0 + b1c) * HSZ + k1c] = c1r;
    }
}

// ---- merged decoders, NB=14 per CTA: grid (72, 2) = 144 CTAs = ONE wave ----
// Step-0 gates computed in-kernel from Whh (global, L2-hot) — no G0 GEMM.
#define NBD 14
#define HP 16
#define GP 15
#define DEC_SMEM_F (40000 + 1600 + 1600 + 6000)

__global__ __launch_bounds__(NT_RNN, 1) void rnn_dec2(
    const float* __restrict__ Whh0, const float* __restrict__ Whh1,
    const float* __restrict__ bih0, const float* __restrict__ bhh0,
    const float* __restrict__ bih1, const float* __restrict__ bhh1,
    const float* __restrict__ Weffbase, const float* __restrict__ beffbase,
    const float* __restrict__ h0, const float* __restrict__ c0,
    __nv_bfloat16* __restrict__ hdhb)
{
    extern __shared__ float s[];
    float* sW  = s;
    float* sHa = s + 40000;
    float* sHb = sHa + 1600;
    float* sG  = sHb + 1600;
    const int tid = threadIdx.x;
    const int b0 = blockIdx.x * NBD;
    const int did = blockIdx.y;

    const float* Whh  = did ? Whh1 : Whh0;
    const float* Weff = Weffbase + (size_t)did * G4 * HSZ;
    const float* beff = beffbase + (size_t)did * G4;
    __nv_bfloat16* hdh = hdhb + (size_t)did * BSZ * TSZ * KPL;

    for (int i = tid; i < 10000; i += NT_RNN)
        ((float4*)sW)[i] = ((const float4*)Weff)[i];
    for (int i = tid; i < 3200; i += NT_RNN) sHa[i] = 0.f;

    const float bq = (tid < 400) ? beff[tid] : 0.f;
    const float b0q = (tid < 400)
        ? ((did ? bih1[tid] : bih0[tid]) + (did ? bhh1[tid] : bhh0[tid])) : 0.f;

    int ck[4], cb[4];
    bool cv[4], cw[4];
    float cc[4];
    __nv_bfloat16* outh[4];
    #pragma unroll
    for (int q = 0; q < 4; ++q) {
        int item = q * NT_RNN + tid;
        bool v = item < NBD * 100;
        int k = v ? (item % 100) : 0;
        int b = v ? (item / 100) : 0;
        ck[q] = k; cb[q] = b; cv[q] = v;
        cw[q] = v && (b0 + b < BSZ);
        cc[q] = 0.f;
        outh[q] = hdh + ((size_t)(b0 + b) * TSZ) * KPL + k;
    }
    __syncthreads();

    #pragma unroll
    for (int q = 0; q < 4; ++q) {
        if (cv[q]) {
            int bb = b0 + cb[q]; if (bb > BSZ - 1) bb = BSZ - 1;
            sHa[ck[q] * HP + cb[q]] = h0[bb * HSZ + ck[q]];
            cc[q] = c0[bb * HSZ + ck[q]];
        }
    }
    __syncthreads();

    for (int t = 0; t < TSZ; ++t) {
        const float* hin = (t & 1) ? sHb : sHa;
        float* hout = (t & 1) ? sHa : sHb;
        if (tid < 400) {
            const int j = tid;
            float* gp = sG + j * GP;
            // t==0 uses Whh (global, L2-hot: rows shared by all 144 CTAs)
            // t>=1 uses Weff (smem)
            const float4* wj = (t == 0)
                ? (const float4*)(Whh + j * 100)
                : (const float4*)(sW + j * 100);
            const float bias = (t == 0) ? b0q : bq;
            float acc[NBD];
            #pragma unroll
            for (int b = 0; b < NBD; ++b) acc[b] = 0.f;
            const float* hp = hin;
            #pragma unroll 5
            for (int k4 = 0; k4 < 25; ++k4) {
                float4 w = wj[k4];
                #pragma unroll
                for (int dd = 0; dd < 4; ++dd) {
                    float wv = (dd == 0) ? w.x : (dd == 1) ? w.y : (dd == 2) ? w.z : w.w;
                    const float* hr = hp + (k4 * 4 + dd) * HP;
                    float4 h0v = *(const float4*)(hr);
                    float4 h1v = *(const float4*)(hr + 4);
                    float4 h2v = *(const float4*)(hr + 8);
                    float2 h3v = *(const float2*)(hr + 12);
                    acc[0]  = fmaf(wv, h0v.x, acc[0]);
                    acc[1]  = fmaf(wv, h0v.y, acc[1]);
                    acc[2]  = fmaf(wv, h0v.z, acc[2]);
                    acc[3]  = fmaf(wv, h0v.w, acc[3]);
                    acc[4]  = fmaf(wv, h1v.x, acc[4]);
                    acc[5]  = fmaf(wv, h1v.y, acc[5]);
                    acc[6]  = fmaf(wv, h1v.z, acc[6]);
                    acc[7]  = fmaf(wv, h1v.w, acc[7]);
                    acc[8]  = fmaf(wv, h2v.x, acc[8]);
                    acc[9]  = fmaf(wv, h2v.y, acc[9]);
                    acc[10] = fmaf(wv, h2v.z, acc[10]);
                    acc[11] = fmaf(wv, h2v.w, acc[11]);
                    acc[12] = fmaf(wv, h3v.x, acc[12]);
                    acc[13] = fmaf(wv, h3v.y, acc[13]);
                }
            }
            #pragma unroll
            for (int b = 0; b < NBD; ++b) gp[b] = acc[b] + bias;
        }
        __syncthreads();
        #pragma unroll
        for (int q = 0; q < 4; ++q) {
            if (cv[q]) {
                int k = ck[q], b = cb[q];
                float gi = sigf(sG[(k) * GP + b]);
                float gf = sigf(sG[(100 + k) * GP + b]);
                float gg = tanhf_fast(sG[(200 + k) * GP + b]);
                float go = sigf(sG[(300 + k) * GP + b]);
                float c = fmaf(gf, cc[q], gi * gg);
                cc[q] = c;
                float h = go * tanhf_fast(c);
                hout[k * HP + b] = h;
                if (cw[q])
                    outh[q][(size_t)t * KPL] = __float2bfloat16(h);
            }
        }
        __syncthreads();
    }
}

// ---------------- launch ----------------------------------------------------
extern "C" void kernel_launch(void* const* d_in, const int* in_sizes, int n_in,
                              void* d_out, int out_size)
{
    const float* src     = (const float*)d_in[0];
    const float* trg     = (const float*)d_in[1];
    const float* enc_Wih = (const float*)d_in[2];
    const float* enc_Whh = (const float*)d_in[3];
    const float* enc_bih = (const float*)d_in[4];
    const float* enc_bhh = (const float*)d_in[5];
    const float* pd_Wih  = (const float*)d_in[6];
    const float* pd_Whh  = (const float*)d_in[7];
    const float* pd_bih  = (const float*)d_in[8];
    const float* pd_bhh  = (const float*)d_in[9];
    const float* pd_fcW  = (const float*)d_in[10];
    const float* pd_fcb  = (const float*)d_in[11];
    const float* rd_Wih  = (const float*)d_in[12];
    const float* rd_Whh  = (const float*)d_in[13];
    const float* rd_bih  = (const float*)d_in[14];
    const float* rd_bhh  = (const float*)d_in[15];
    const float* rd_fcW  = (const float*)d_in[16];
    const float* rd_fcb  = (const float*)d_in[17];
    float* out = (float*)d_out;

    float *pX, *pHenc, *pCenc, *pWeff, *pBeff, *pLoss;
    __nv_bfloat16 *pSrch, *pWihh, *pWihl, *pFcwh, *pHdh;
    cudaGetSymbolAddress((void**)&pX,    g_X);
    cudaGetSymbolAddress((void**)&pHenc, g_henc);
    cudaGetSymbolAddress((void**)&pCenc, g_cenc);
    cudaGetSymbolAddress((void**)&pWeff, g_Weff);
    cudaGetSymbolAddress((void**)&pBeff, g_beff);
    cudaGetSymbolAddress((void**)&pLoss, g_loss);
    cudaGetSymbolAddress((void**)&pSrch, g_srch);
    cudaGetSymbolAddress((void**)&pWihh, g_wihh);
    cudaGetSymbolAddress((void**)&pWihl, g_wihl);
    cudaGetSymbolAddress((void**)&pFcwh, g_fcwh);
    cudaGetSymbolAddress((void**)&pHdh,  g_hdh);

    const int SMEM_RNN = RNN_SMEM_F * 4;
    const int SMEM_DEC = DEC_SMEM_F * 4;
    const int SMEM_GEMM = (int)sizeof(Bf16GemmSmem);
    cudaFuncSetAttribute(rnn_enc,  cudaFuncAttributeMaxDynamicSharedMemorySize, SMEM_RNN);
    cudaFuncSetAttribute(rnn_dec2, cudaFuncAttributeMaxDynamicSharedMemorySize, SMEM_DEC);
    cudaFuncSetAttribute(gemm_bf16_store, cudaFuncAttributeMaxDynamicSharedMemorySize, SMEM_GEMM);
    cudaFuncSetAttribute(gemm_bf16_loss2, cudaFuncAttributeMaxDynamicSharedMemorySize, SMEM_GEMM);

    const int RNN_BLOCKS = (BSZ + NB - 1) / NB;     // 143
    const int DEC_BLOCKS = (BSZ + NBD - 1) / NBD;   // 72
    const int MROWS = BSZ * TSZ;                    // 100000

    // launches 1-3: prep (launch #4 = phase-A tensor GEMM, the profiled slot)
    cvt_hi_t<ISZ, KPA><<<(MROWS * (KPA / 4) + 255) / 256, 256>>>(src, pSrch, MROWS);
    cvt_split_t<ISZ, KPA><<<(G4 * (KPA / 4) + 255) / 256, 256>>>(enc_Wih, pWihh, pWihl, G4);
    {
        dim3 grid(G4, 2);
        fold2_kernel<<<grid, 128>>>(pd_Wih, pd_Whh, pd_fcW, pd_fcb, pd_bih, pd_bhh,
                                    rd_Wih, rd_Whh, rd_fcW, rd_fcb, rd_bih, rd_bhh,
                                    pWeff, pBeff, pLoss);
    }

    // launch 4: phase A (tensor cores, A hi-only + B split)
    {
        dim3 grid((G4 + 63) / 64, (MROWS + 127) / 128);
        gemm_bf16_store<<<grid, 256, SMEM_GEMM>>>(pSrch, KPA, pWihh, pWihl, KPA,
                                                  enc_bih, enc_bhh, pX, MROWS, G4, KPA);
    }

    // encoder recurrence
    rnn_enc<<<RNN_BLOCKS, NT_RNN, SMEM_RNN>>>(pX, enc_Whh, pHenc, pCenc);

    // fcW hi-only conversions (loss GEMM B operands)
    cvt_hi_t<HSZ, KPL><<<(ISZ * (KPL / 4) + 255) / 256, 256>>>(pd_fcW, pFcwh, ISZ);
    cvt_hi_t<HSZ, KPL><<<(ISZ * (KPL / 4) + 255) / 256, 256>>>(rd_fcW, pFcwh + ISZ * KPL, ISZ);

    // merged decoders (step-0 gates computed in-kernel): 144 CTAs = one wave
    {
        dim3 grid(DEC_BLOCKS, 2);
        rnn_dec2<<<grid, NT_RNN, SMEM_DEC>>>(pd_Whh, rd_Whh,
                                             pd_bih, pd_bhh, rd_bih, rd_bhh,
                                             pWeff, pBeff, pHenc, pCenc, pHdh);
    }

    // merged losses (pure bf16 tensor GEMM, fused MSE epilogue)
    {
        dim3 grid((ISZ + 63) / 64, (MROWS + 127) / 128, 2);
        gemm_bf16_loss2<<<grid, 256, SMEM_GEMM>>>(pHdh, pFcwh,
                                                  pd_fcb, rd_fcb, trg, src,
                                                  pLoss, MROWS, ISZ);
    }

    finalize_kernel<<<1, 1>>>(pLoss, out, 1.0f / (float)(BSZ * TSZ * ISZ));
}

// round 15
// speedup vs baseline: 1.1935x; 1.0214x over previous
#include <cuda_runtime.h>
#include <cuda_bf16.h>
#include <math.h>

#define BSZ 1000
#define TSZ 100
#define ISZ 264
#define HSZ 100
#define G4  400   // 4*H
#define KPA 272   // padded K for phase A (264 -> 17*16)
#define KPL 112   // padded K for loss GEMMs (100 -> 7*16)

// ---------------- device scratch (static: no allocation allowed) ----------
__device__ float g_X[(size_t)BSZ * TSZ * G4];       // encoder gate inputs fp32
__device__ float g_henc[BSZ * HSZ];
__device__ float g_cenc[BSZ * HSZ];
__device__ float g_Weff[2][G4 * HSZ];
__device__ float g_beff[2][G4];
__device__ float g_loss[2];

// bf16 operands
__device__ __nv_bfloat16 g_srch[(size_t)BSZ * TSZ * KPA];
__device__ __nv_bfloat16 g_wihh[G4 * KPA];
__device__ __nv_bfloat16 g_wihl[G4 * KPA];
__device__ __nv_bfloat16 g_fcwh[2][ISZ * KPL];
__device__ __nv_bfloat16 g_hdh[2][(size_t)BSZ * TSZ * KPL];  // decoder h (bf16)

// ---------------- f32x2 packed helpers --------------------------------------
__device__ __forceinline__ unsigned long long pk2(float v) {
    unsigned long long r;
    asm("mov.b64 %0, {%1,%1};" : "=l"(r) : "f"(v));
    return r;
}
__device__ __forceinline__ void fma2(unsigned long long& d,
                                     unsigned long long a, unsigned long long b) {
    asm("fma.rn.f32x2 %0, %1, %2, %0;" : "+l"(d) : "l"(a), "l"(b));
}
__device__ __forceinline__ float2 up2(unsigned long long v) {
    float2 r;
    asm("mov.b64 {%0,%1}, %2;" : "=f"(r.x), "=f"(r.y) : "l"(v));
    return r;
}
union F4U { float4 f4; unsigned long long u[2]; };

// ---------------- fast activations (ex2/rcp approx: ~2^-22 rel err) --------
__device__ __forceinline__ float ex2f(float x) {
    float r; asm("ex2.approx.f32 %0, %1;" : "=f"(r) : "f"(x)); return r;
}
__device__ __forceinline__ float rcpf(float x) {
    float r; asm("rcp.approx.f32 %0, %1;" : "=f"(r) : "f"(x)); return r;
}
__device__ __forceinline__ float sigf(float x) {
    return rcpf(1.f + ex2f(-1.4426950408889634f * x));
}
__device__ __forceinline__ float tanhf_fast(float x) {
    return fmaf(2.f, rcpf(1.f + ex2f(-2.8853900817779268f * x)), -1.f);
}

// ---------------- small kernels -------------------------------------------
__global__ void finalize_kernel(const float* loss, float* out, float inv) {
    out[0] = loss[0] * inv;
    out[1] = loss[1] * inv;
}

// fp32 -> bf16 hi only, K padded to Kp.
template <int K, int Kp>
__global__ __launch_bounds__(256) void cvt_hi_t(
    const float* __restrict__ x, __nv_bfloat16* __restrict__ h, int rows)
{
    const int Kp4 = Kp / 4;
    int idx = blockIdx.x * 256 + threadIdx.x;
    if (idx >= rows * Kp4) return;
    int r = idx / Kp4;
    int k4 = (idx - r * Kp4) * 4;
    float4 v;
    if (k4 + 3 < K) {
        v = *(const float4*)(x + (size_t)r * K + k4);
    } else {
        float tmp[4] = {0.f, 0.f, 0.f, 0.f};
        #pragma unroll
        for (int e = 0; e < 4; ++e)
            if (k4 + e < K) tmp[e] = x[(size_t)r * K + k4 + e];
        v = make_float4(tmp[0], tmp[1], tmp[2], tmp[3]);
    }
    __nv_bfloat16 hh[4];
    hh[0] = __float2bfloat16(v.x);
    hh[1] = __float2bfloat16(v.y);
    hh[2] = __float2bfloat16(v.z);
    hh[3] = __float2bfloat16(v.w);
    *(uint2*)(h + (size_t)idx * 4) = *(const uint2*)hh;
}

// fp32 -> (bf16 hi, bf16 lo), K padded to Kp.
template <int K, int Kp>
__global__ __launch_bounds__(256) void cvt_split_t(
    const float* __restrict__ x, __nv_bfloat16* __restrict__ h,
    __nv_bfloat16* __restrict__ l, int rows)
{
    const int Kp4 = Kp / 4;
    int idx = blockIdx.x * 256 + threadIdx.x;
    if (idx >= rows * Kp4) return;
    int r = idx / Kp4;
    int k4 = (idx - r * Kp4) * 4;
    float4 v;
    if (k4 + 3 < K) {
        v = *(const float4*)(x + (size_t)r * K + k4);
    } else {
        float tmp[4] = {0.f, 0.f, 0.f, 0.f};
        #pragma unroll
        for (int e = 0; e < 4; ++e)
            if (k4 + e < K) tmp[e] = x[(size_t)r * K + k4 + e];
        v = make_float4(tmp[0], tmp[1], tmp[2], tmp[3]);
    }
    float vv[4] = {v.x, v.y, v.z, v.w};
    __nv_bfloat16 hh[4], ll[4];
    #pragma unroll
    for (int e = 0; e < 4; ++e) {
        hh[e] = __float2bfloat16(vv[e]);
        ll[e] = __float2bfloat16(vv[e] - __bfloat162float(hh[e]));
    }
    *(uint2*)(h + (size_t)idx * 4) = *(const uint2*)hh;
    *(uint2*)(l + (size_t)idx * 4) = *(const uint2*)ll;
}

// Both decoder folds in one launch: blockIdx.y selects decoder.
__global__ __launch_bounds__(128) void fold2_kernel(
    const float* __restrict__ pd_Wih, const float* __restrict__ pd_Whh,
    const float* __restrict__ pd_fcW, const float* __restrict__ pd_fcb,
    const float* __restrict__ pd_bih, const float* __restrict__ pd_bhh,
    const float* __restrict__ rd_Wih, const float* __restrict__ rd_Whh,
    const float* __restrict__ rd_fcW, const float* __restrict__ rd_fcb,
    const float* __restrict__ rd_bih, const float* __restrict__ rd_bhh,
    float* __restrict__ Weff, float* __restrict__ beff, float* __restrict__ loss)
{
    const int did = blockIdx.y;
    const float* Wih = did ? rd_Wih : pd_Wih;
    const float* Whh = did ? rd_Whh : pd_Whh;
    const float* fcW = did ? rd_fcW : pd_fcW;
    const float* fcb = did ? rd_fcb : pd_fcb;
    const float* bih = did ? rd_bih : pd_bih;
    const float* bhh = did ? rd_bhh : pd_bhh;
    float* We = Weff + (size_t)did * G4 * HSZ;
    float* be = beff + (size_t)did * G4;

    int j = blockIdx.x;
    int tid = threadIdx.x;
    if (blockIdx.x == 0 && did == 0 && tid < 2) loss[tid] = 0.f;

    __shared__ float swih[ISZ];
    __shared__ float red[128];
    for (int i = tid; i < ISZ; i += 128) swih[i] = Wih[j * ISZ + i];
    __syncthreads();
    if (tid < HSZ) {
        float acc = Whh[j * HSZ + tid];
        #pragma unroll 4
        for (int i = 0; i < ISZ; ++i)
            acc = fmaf(swih[i], fcW[i * HSZ + tid], acc);
        We[j * HSZ + tid] = acc;
    }
    float p = 0.f;
    for (int i = tid; i < ISZ; i += 128) p = fmaf(swih[i], fcb[i], p);
    red[tid] = p;
    __syncthreads();
    for (int s = 64; s > 0; s >>= 1) {
        if (tid < s) red[tid] += red[tid + s];
        __syncthreads();
    }
    if (tid == 0) be[j] = bih[j] + bhh[j] + red[0];
}

// ---------------- tensor-core bf16 NT GEMM core -----------------------------
#define SAP 24

__device__ __forceinline__ void mma16816(float* d, const unsigned* a, const unsigned* b) {
    asm volatile(
        "mma.sync.aligned.m16n8k16.row.col.f32.bf16.bf16.f32 "
        "{%0,%1,%2,%3},{%4,%5,%6,%7},{%8,%9},{%0,%1,%2,%3};"
        : "+f"(d[0]), "+f"(d[1]), "+f"(d[2]), "+f"(d[3])
        : "r"(a[0]), "r"(a[1]), "r"(a[2]), "r"(a[3]), "r"(b[0]), "r"(b[1]));
}

__device__ __forceinline__ void ldsm_x4(unsigned* r, unsigned addr) {
    asm volatile(
        "ldmatrix.sync.aligned.m8n8.x4.shared.b16 {%0,%1,%2,%3}, [%4];"
        : "=r"(r[0]), "=r"(r[1]), "=r"(r[2]), "=r"(r[3]) : "r"(addr));
}

struct Bf16GemmSmem {
    __nv_bfloat16 Ash[2][128 * SAP];
    __nv_bfloat16 Bsh[2][64 * SAP];
    __nv_bfloat16 Bsl[2][64 * SAP];
    float red[256];
};

// A hi-only, B split (hi+lo): 2 MMAs per fragment pair. (phase A)
__device__ __forceinline__ void bf16_mainloop_a1(
    Bf16GemmSmem* sm, float d[2][4][4],
    const __nv_bfloat16* Ah, int lda,
    const __nv_bfloat16* Bh, const __nv_bfloat16* Bl, int ldb,
    int m0, int n0, int M, int N, int Kp)
{
    const int tid = threadIdx.x;
    const int lane = tid & 31;
    const int wid = tid >> 5;
    const int wy = wid & 3;
    const int wx = wid >> 2;

    const int ar = tid >> 1;
    const int ah8 = (tid & 1) * 8;
    const int bs = tid & 127;
    const int brow = bs >> 1;
    const int bh8 = (bs & 1) * 8;
    const int gm = m0 + ar;
    const int gn = n0 + brow;
    const __nv_bfloat16* srcB = (tid < 128) ? Bh : Bl;

    const unsigned aoff =
        ((unsigned)((wy * 32 + ((lane >> 3) & 1) * 8 + (lane & 7)) * SAP
                    + (lane >> 4) * 8)) * 2u;
    const unsigned boff =
        ((unsigned)((wx * 32 + ((lane >> 4) & 1) * 8 + (lane & 7)) * SAP
                    + ((lane >> 3) & 1) * 8)) * 2u;

    const unsigned ashb = (unsigned)__cvta_generic_to_shared(sm->Ash[0]);
    const unsigned bshb = (unsigned)__cvta_generic_to_shared(sm->Bsh[0]);
    const unsigned bslb = (unsigned)__cvta_generic_to_shared(sm->Bsl[0]);
    const unsigned abuf = 128 * SAP * 2;
    const unsigned bbuf = 64 * SAP * 2;
    const unsigned ni2step = 16 * SAP * 2;
    const unsigned mistep = 16 * SAP * 2;

    const uint4 zv = make_uint4(0, 0, 0, 0);
    uint4 vh = zv, vb = zv;
    if (gm < M) vh = *(const uint4*)(Ah + (size_t)gm * lda + ah8);
    if (gn < N) vb = *(const uint4*)(srcB + (size_t)gn * ldb + bh8);

    const int niter = Kp / 16;
    for (int i = 0; i < niter; ++i) {
        const unsigned cur = (unsigned)(i & 1);
        *(uint4*)&sm->Ash[cur][ar * SAP + ah8] = vh;
        __nv_bfloat16* dstB = (tid < 128) ? sm->Bsh[cur] : sm->Bsl[cur];
        *(uint4*)&dstB[brow * SAP + bh8] = vb;
        __syncthreads();

        if (i + 1 < niter) {
            int kn = (i + 1) * 16;
            vh = zv; vb = zv;
            if (gm < M) vh = *(const uint4*)(Ah + (size_t)gm * lda + kn + ah8);
            if (gn < N) vb = *(const uint4*)(srcB + (size_t)gn * ldb + kn + bh8);
        }

        unsigned bhf[4][2], blf[4][2];
        {
            unsigned r[4];
            unsigned b0 = bshb + cur * bbuf + boff;
            ldsm_x4(r, b0);
            bhf[0][0] = r[0]; bhf[0][1] = r[1]; bhf[1][0] = r[2]; bhf[1][1] = r[3];
            ldsm_x4(r, b0 + ni2step);
            bhf[2][0] = r[0]; bhf[2][1] = r[1]; bhf[3][0] = r[2]; bhf[3][1] = r[3];
            unsigned b1 = bslb + cur * bbuf + boff;
            ldsm_x4(r, b1);
            blf[0][0] = r[0]; blf[0][1] = r[1]; blf[1][0] = r[2]; blf[1][1] = r[3];
            ldsm_x4(r, b1 + ni2step);
            blf[2][0] = r[0]; blf[2][1] = r[1]; blf[3][0] = r[2]; blf[3][1] = r[3];
        }
        #pragma unroll
        for (int mi = 0; mi < 2; ++mi) {
            unsigned ahf[4];
            ldsm_x4(ahf, ashb + cur * abuf + aoff + mi * mistep);
            #pragma unroll
            for (int ni = 0; ni < 4; ++ni) {
                mma16816(d[mi][ni], ahf, bhf[ni]);
                mma16816(d[mi][ni], ahf, blf[ni]);
            }
        }
    }
    __syncthreads();
}

// A hi-only, B hi-only: 1 MMA per fragment pair. (loss GEMMs)
__device__ __forceinline__ void bf16_mainloop_11(
    Bf16GemmSmem* sm, float d[2][4][4],
    const __nv_bfloat16* Ah, int lda,
    const __nv_bfloat16* Bh, int ldb,
    int m0, int n0, int M, int N, int Kp)
{
    const int tid = threadIdx.x;
    const int lane = tid & 31;
    const int wid = tid >> 5;
    const int wy = wid & 3;
    const int wx = wid >> 2;

    const int ar = tid >> 1;
    const int ah8 = (tid & 1) * 8;
    const int brow = (tid & 127) >> 1;
    const int bh8 = (tid & 1) * 8;
    const int gm = m0 + ar;
    const int gn = n0 + brow;
    const bool bldr = (tid < 128);

    const unsigned aoff =
        ((unsigned)((wy * 32 + ((lane >> 3) & 1) * 8 + (lane & 7)) * SAP
                    + (lane >> 4) * 8)) * 2u;
    const unsigned boff =
        ((unsigned)((wx * 32 + ((lane >> 4) & 1) * 8 + (lane & 7)) * SAP
                    + ((lane >> 3) & 1) * 8)) * 2u;

    const unsigned ashb = (unsigned)__cvta_generic_to_shared(sm->Ash[0]);
    const unsigned bshb = (unsigned)__cvta_generic_to_shared(sm->Bsh[0]);
    const unsigned abuf = 128 * SAP * 2;
    const unsigned bbuf = 64 * SAP * 2;
    const unsigned ni2step = 16 * SAP * 2;
    const unsigned mistep = 16 * SAP * 2;

    const uint4 zv = make_uint4(0, 0, 0, 0);
    uint4 vh = zv, vb = zv;
    if (gm < M) vh = *(const uint4*)(Ah + (size_t)gm * lda + ah8);
    if (bldr && gn < N) vb = *(const uint4*)(Bh + (size_t)gn * ldb + bh8);

    const int niter = Kp / 16;
    for (int i = 0; i < niter; ++i) {
        const unsigned cur = (unsigned)(i & 1);
        *(uint4*)&sm->Ash[cur][ar * SAP + ah8] = vh;
        if (bldr) *(uint4*)&sm->Bsh[cur][brow * SAP + bh8] = vb;
        __syncthreads();

        if (i + 1 < niter) {
            int kn = (i + 1) * 16;
            vh = zv; vb = zv;
            if (gm < M) vh = *(const uint4*)(Ah + (size_t)gm * lda + kn + ah8);
            if (bldr && gn < N) vb = *(const uint4*)(Bh + (size_t)gn * ldb + kn + bh8);
        }

        unsigned bhf[4][2];
        {
            unsigned r[4];
            unsigned b0 = bshb + cur * bbuf + boff;
            ldsm_x4(r, b0);
            bhf[0][0] = r[0]; bhf[0][1] = r[1]; bhf[1][0] = r[2]; bhf[1][1] = r[3];
            ldsm_x4(r, b0 + ni2step);
            bhf[2][0] = r[0]; bhf[2][1] = r[1]; bhf[3][0] = r[2]; bhf[3][1] = r[3];
        }
        #pragma unroll
        for (int mi = 0; mi < 2; ++mi) {
            unsigned ahf[4];
            ldsm_x4(ahf, ashb + cur * abuf + aoff + mi * mistep);
            #pragma unroll
            for (int ni = 0; ni < 4; ++ni)
                mma16816(d[mi][ni], ahf, bhf[ni]);
        }
    }
    __syncthreads();
}

// Phase-A variant: stores C with two biases.
__global__ __launch_bounds__(256, 3) void gemm_bf16_store(
    const __nv_bfloat16* __restrict__ Ah, int lda,
    const __nv_bfloat16* __restrict__ Bh, const __nv_bfloat16* __restrict__ Bl, int ldb,
    const float* __restrict__ bias1, const float* __restrict__ bias2,
    float* __restrict__ C, int M, int N, int Kp)
{
    extern __shared__ char smraw[];
    Bf16GemmSmem* sm = (Bf16GemmSmem*)smraw;
    const int tid = threadIdx.x;
    const int lane = tid & 31;
    const int wid = tid >> 5;
    const int wy = wid & 3, wx = wid >> 2;
    const int g = lane >> 2, t = lane & 3;
    const int m0 = blockIdx.y * 128, n0 = blockIdx.x * 64;

    float d[2][4][4];
    #pragma unroll
    for (int mi = 0; mi < 2; ++mi)
        #pragma unroll
        for (int ni = 0; ni < 4; ++ni)
            #pragma unroll
            for (int e = 0; e < 4; ++e) d[mi][ni][e] = 0.f;

    bf16_mainloop_a1(sm, d, Ah, lda, Bh, Bl, ldb, m0, n0, M, N, Kp);

    #pragma unroll
    for (int mi = 0; mi < 2; ++mi) {
        #pragma unroll
        for (int rr = 0; rr < 2; ++rr) {
            int m = m0 + wy * 32 + mi * 16 + rr * 8 + g;
            if (m >= M) continue;
            #pragma unroll
            for (int ni = 0; ni < 4; ++ni) {
                int n = n0 + wx * 32 + ni * 8 + 2 * t;
                if (n + 1 < N) {
                    float v0 = d[mi][ni][rr * 2 + 0] + bias1[n] + bias2[n];
                    float v1 = d[mi][ni][rr * 2 + 1] + bias1[n + 1] + bias2[n + 1];
                    *(float2*)(C + (size_t)m * N + n) = make_float2(v0, v1);
                } else if (n < N) {
                    C[(size_t)m * N + n] = d[mi][ni][rr * 2 + 0] + bias1[n] + bias2[n];
                }
            }
        }
    }
}

// Merged loss variant: A = decoder h, B = fcW (both bf16 hi only); fused MSE.
__global__ __launch_bounds__(256, 3) void gemm_bf16_loss2(
    const __nv_bfloat16* __restrict__ Ahb,
    const __nv_bfloat16* __restrict__ Bhb,
    const float* __restrict__ fcb0, const float* __restrict__ fcb1,
    const float* __restrict__ trg, const float* __restrict__ src,
    float* __restrict__ loss, int M, int N)
{
    extern __shared__ char smraw[];
    Bf16GemmSmem* sm = (Bf16GemmSmem*)smraw;
    const int did = blockIdx.z;
    const __nv_bfloat16* Ah = Ahb + (size_t)did * M * KPL;
    const __nv_bfloat16* Bh = Bhb + (size_t)did * N * KPL;
    const float* bias = did ? fcb1 : fcb0;
    const float* ref = did ? src : trg;
    float* lossOut = did ? (loss + 0) : (loss + 1);
    const int revT = did ? TSZ : 0;

    const int tid = threadIdx.x;
    const int lane = tid & 31;
    const int wid = tid >> 5;
    const int wy = wid & 3, wx = wid >> 2;
    const int g = lane >> 2, t = lane & 3;
    const int m0 = blockIdx.y * 128, n0 = blockIdx.x * 64;

    float d[2][4][4];
    #pragma unroll
    for (int mi = 0; mi < 2; ++mi)
        #pragma unroll
        for (int ni = 0; ni < 4; ++ni)
            #pragma unroll
            for (int e = 0; e < 4; ++e) d[mi][ni][e] = 0.f;

    bf16_mainloop_11(sm, d, Ah, KPL, Bh, KPL, m0, n0, M, N, KPL);

    float ls = 0.f;
    #pragma unroll
    for (int mi = 0; mi < 2; ++mi) {
        #pragma unroll
        for (int rr = 0; rr < 2; ++rr) {
            int m = m0 + wy * 32 + mi * 16 + rr * 8 + g;
            if (m >= M) continue;
            const float* rrow;
            if (revT > 0) {
                int b = m / revT, tt = m - b * revT;
                rrow = ref + ((size_t)b * revT + (revT - 1 - tt)) * N;
            } else {
                rrow = ref + (size_t)m * N;
            }
            #pragma unroll
            for (int ni = 0; ni < 4; ++ni) {
                int n = n0 + wx * 32 + ni * 8 + 2 * t;
                #pragma unroll
                for (int e = 0; e < 2; ++e) {
                    if (n + e < N) {
                        float v = d[mi][ni][rr * 2 + e] + bias[n + e];
                        float diff = v - rrow[n + e];
                        ls = fmaf(diff, diff, ls);
                    }
                }
            }
        }
    }
    sm->red[tid] = ls;
    __syncthreads();
    for (int s = 128; s > 0; s >>= 1) {
        if (tid < s) sm->red[tid] += sm->red[tid + s];
        __syncthreads();
    }
    if (tid == 0) atomicAdd(lossOut, sm->red[0]);
}

// ---------------- LSTM recurrence kernels ----------------------------------
#define NB 7
#define NT_RNN 416
#define RNN_SMEM_F (40000 + 800 + 800 + 3600)

__global__ __launch_bounds__(NT_RNN, 1) void rnn_enc(
    const float* __restrict__ X, const float* __restrict__ Whh,
    float* __restrict__ hf, float* __restrict__ cf)
{
    extern __shared__ float s[];
    float* sW  = s;
    float* sHa = s + 40000;
    float* sHb = sHa + 800;
    float* sG  = sHb + 800;
    const int tid = threadIdx.x;
    const int b0 = blockIdx.x * NB;

    for (int i = tid; i < 10000; i += NT_RNN)
        ((float4*)sW)[i] = ((const float4*)Whh)[i];
    for (int i = tid; i < 800; i += NT_RNN) sHa[i] = 0.f;
    __syncthreads();

    const int i0 = tid, i1 = tid + NT_RNN;
    const int k0c = i0 % 100, b0c = i0 / 100;
    const int k1c = i1 % 100, b1c = i1 / 100;
    const bool v0 = (i0 < NB * 100), v1 = (i1 < NB * 100);
    float c0r = 0.f, c1r = 0.f, h0r = 0.f, h1r = 0.f;

    int bidx[NB];
    #pragma unroll
    for (int b = 0; b < NB; ++b) {
        int bb = b0 + b; if (bb > BSZ - 1) bb = BSZ - 1;
        bidx[b] = bb;
    }

    for (int t = 0; t < TSZ; ++t) {
        const float* hin = (t & 1) ? sHb : sHa;
        float* hout = (t & 1) ? sHa : sHb;
        if (tid < 400) {
            const int j = tid;
            float xr[NB];
            #pragma unroll
            for (int b = 0; b < NB; ++b)
                xr[b] = X[((size_t)bidx[b] * TSZ + t) * G4 + j];
            // packed f32x2 accumulators: lanes = batches 0..7 (lane 7 unused)
            unsigned long long a2[4] = {0ull, 0ull, 0ull, 0ull};
            const float4* wj = (const float4*)(sW + j * 100);
            const float* hp = hin;
            #pragma unroll 5
            for (int k4 = 0; k4 < 25; ++k4) {
                float4 w = wj[k4];
                #pragma unroll
                for (int dd = 0; dd < 4; ++dd) {
                    float wv = (dd == 0) ? w.x : (dd == 1) ? w.y : (dd == 2) ? w.z : w.w;
                    unsigned long long w2 = pk2(wv);
                    F4U u0, u1;
                    u0.f4 = *(const float4*)(hp + (k4 * 4 + dd) * 8);
                    u1.f4 = *(const float4*)(hp + (k4 * 4 + dd) * 8 + 4);
                    fma2(a2[0], u0.u[0], w2);
                    fma2(a2[1], u0.u[1], w2);
                    fma2(a2[2], u1.u[0], w2);
                    fma2(a2[3], u1.u[1], w2);
                }
            }
            float2 p0 = up2(a2[0]), p1 = up2(a2[1]);
            float2 p2 = up2(a2[2]), p3 = up2(a2[3]);
            float accv[7] = {p0.x, p0.y, p1.x, p1.y, p2.x, p2.y, p3.x};
            float* gp = sG + j * 9;
            #pragma unroll
            for (int b = 0; b < NB; ++b) gp[b] = accv[b] + xr[b];
        }
        __syncthreads();
        if (v0) {
            float gi = sigf(sG[(k0c) * 9 + b0c]);
            float gf = sigf(sG[(100 + k0c) * 9 + b0c]);
            float gg = tanhf_fast(sG[(200 + k0c) * 9 + b0c]);
            float go = sigf(sG[(300 + k0c) * 9 + b0c]);
            c0r = fmaf(gf, c0r, gi * gg);
            h0r = go * tanhf_fast(c0r);
            hout[k0c * 8 + b0c] = h0r;
        }
        if (v1) {
            float gi = sigf(sG[(k1c) * 9 + b1c]);
            float gf = sigf(sG[(100 + k1c) * 9 + b1c]);
            float gg = tanhf_fast(sG[(200 + k1c) * 9 + b1c]);
            float go = sigf(sG[(300 + k1c) * 9 + b1c]);
            c1r = fmaf(gf, c1r, gi * gg);
            h1r = go * tanhf_fast(c1r);
            hout[k1c * 8 + b1c] = h1r;
        }
        __syncthreads();
    }

    if (v0 && b0 + b0c < BSZ) {
        hf[(b0 + b0c) * HSZ + k0c] = h0r;
        cf[(b0 + b0c) * HSZ + k0c] = c0r;
    }
    if (v1 && b0 + b1c < BSZ) {
        hf[(b0 + b1c) * HSZ + k1c] = h1r;
        cf[(b0 + b1c) * HSZ + k1c] = c1r;
    }
}

// ---- merged decoders, NB=14 per CTA: grid (72, 2) = 144 CTAs = ONE wave ----
// Step-0 gates computed in-kernel from Whh (global, L2-hot) — no G0 GEMM.
#define NBD 14
#define HP 16
#define GP 15
#define DEC_SMEM_F (40000 + 1600 + 1600 + 6000)

__global__ __launch_bounds__(NT_RNN, 1) void rnn_dec2(
    const float* __restrict__ Whh0, const float* __restrict__ Whh1,
    const float* __restrict__ bih0, const float* __restrict__ bhh0,
    const float* __restrict__ bih1, const float* __restrict__ bhh1,
    const float* __restrict__ Weffbase, const float* __restrict__ beffbase,
    const float* __restrict__ h0, const float* __restrict__ c0,
    __nv_bfloat16* __restrict__ hdhb)
{
    extern __shared__ float s[];
    float* sW  = s;
    float* sHa = s + 40000;
    float* sHb = sHa + 1600;
    float* sG  = sHb + 1600;
    const int tid = threadIdx.x;
    const int b0 = blockIdx.x * NBD;
    const int did = blockIdx.y;

    const float* Whh  = did ? Whh1 : Whh0;
    const float* Weff = Weffbase + (size_t)did * G4 * HSZ;
    const float* beff = beffbase + (size_t)did * G4;
    __nv_bfloat16* hdh = hdhb + (size_t)did * BSZ * TSZ * KPL;

    for (int i = tid; i < 10000; i += NT_RNN)
        ((float4*)sW)[i] = ((const float4*)Weff)[i];
    for (int i = tid; i < 3200; i += NT_RNN) sHa[i] = 0.f;

    const float bq = (tid < 400) ? beff[tid] : 0.f;
    const float b0q = (tid < 400)
        ? ((did ? bih1[tid] : bih0[tid]) + (did ? bhh1[tid] : bhh0[tid])) : 0.f;

    int ck[4], cb[4];
    bool cv[4], cw[4];
    float cc[4];
    __nv_bfloat16* outh[4];
    #pragma unroll
    for (int q = 0; q < 4; ++q) {
        int item = q * NT_RNN + tid;
        bool v = item < NBD * 100;
        int k = v ? (item % 100) : 0;
        int b = v ? (item / 100) : 0;
        ck[q] = k; cb[q] = b; cv[q] = v;
        cw[q] = v && (b0 + b < BSZ);
        cc[q] = 0.f;
        outh[q] = hdh + ((size_t)(b0 + b) * TSZ) * KPL + k;
    }
    __syncthreads();

    #pragma unroll
    for (int q = 0; q < 4; ++q) {
        if (cv[q]) {
            int bb = b0 + cb[q]; if (bb > BSZ - 1) bb = BSZ - 1;
            sHa[ck[q] * HP + cb[q]] = h0[bb * HSZ + ck[q]];
            cc[q] = c0[bb * HSZ + ck[q]];
        }
    }
    __syncthreads();

    for (int t = 0; t < TSZ; ++t) {
        const float* hin = (t & 1) ? sHb : sHa;
        float* hout = (t & 1) ? sHa : sHb;
        if (tid < 400) {
            const int j = tid;
            float* gp = sG + j * GP;
            const float4* wj = (t == 0)
                ? (const float4*)(Whh + j * 100)
                : (const float4*)(sW + j * 100);
            const float bias = (t == 0) ? b0q : bq;
            // packed f32x2 accumulators: 7 pairs = 14 batches (+2 pad lanes)
            unsigned long long a2[7] = {0ull,0ull,0ull,0ull,0ull,0ull,0ull};
            const float* hp = hin;
            #pragma unroll 5
            for (int k4 = 0; k4 < 25; ++k4) {
                float4 w = wj[k4];
                #pragma unroll
                for (int dd = 0; dd < 4; ++dd) {
                    float wv = (dd == 0) ? w.x : (dd == 1) ? w.y : (dd == 2) ? w.z : w.w;
                    unsigned long long w2 = pk2(wv);
                    const float* hr = hp + (k4 * 4 + dd) * HP;
                    F4U u0, u1, u2;
                    u0.f4 = *(const float4*)(hr);
                    u1.f4 = *(const float4*)(hr + 4);
                    u2.f4 = *(const float4*)(hr + 8);
                    unsigned long long h6 = *(const unsigned long long*)(hr + 12);
                    fma2(a2[0], u0.u[0], w2);
                    fma2(a2[1], u0.u[1], w2);
                    fma2(a2[2], u1.u[0], w2);
                    fma2(a2[3], u1.u[1], w2);
                    fma2(a2[4], u2.u[0], w2);
                    fma2(a2[5], u2.u[1], w2);
                    fma2(a2[6], h6, w2);
                }
            }
            #pragma unroll
            for (int p = 0; p < 7; ++p) {
                float2 v = up2(a2[p]);
                gp[2 * p]     = v.x + bias;
                gp[2 * p + 1] = v.y + bias;
            }
        }
        __syncthreads();
        #pragma unroll
        for (int q = 0; q < 4; ++q) {
            if (cv[q]) {
                int k = ck[q], b = cb[q];
                float gi = sigf(sG[(k) * GP + b]);
                float gf = sigf(sG[(100 + k) * GP + b]);
                float gg = tanhf_fast(sG[(200 + k) * GP + b]);
                float go = sigf(sG[(300 + k) * GP + b]);
                float c = fmaf(gf, cc[q], gi * gg);
                cc[q] = c;
                float h = go * tanhf_fast(c);
                hout[k * HP + b] = h;
                if (cw[q])
                    outh[q][(size_t)t * KPL] = __float2bfloat16(h);
            }
        }
        __syncthreads();
    }
}

// ---------------- launch ----------------------------------------------------
extern "C" void kernel_launch(void* const* d_in, const int* in_sizes, int n_in,
                              void* d_out, int out_size)
{
    const float* src     = (const float*)d_in[0];
    const float* trg     = (const float*)d_in[1];
    const float* enc_Wih = (const float*)d_in[2];
    const float* enc_Whh = (const float*)d_in[3];
    const float* enc_bih = (const float*)d_in[4];
    const float* enc_bhh = (const float*)d_in[5];
    const float* pd_Wih  = (const float*)d_in[6];
    const float* pd_Whh  = (const float*)d_in[7];
    const float* pd_bih  = (const float*)d_in[8];
    const float* pd_bhh  = (const float*)d_in[9];
    const float* pd_fcW  = (const float*)d_in[10];
    const float* pd_fcb  = (const float*)d_in[11];
    const float* rd_Wih  = (const float*)d_in[12];
    const float* rd_Whh  = (const float*)d_in[13];
    const float* rd_bih  = (const float*)d_in[14];
    const float* rd_bhh  = (const float*)d_in[15];
    const float* rd_fcW  = (const float*)d_in[16];
    const float* rd_fcb  = (const float*)d_in[17];
    float* out = (float*)d_out;

    float *pX, *pHenc, *pCenc, *pWeff, *pBeff, *pLoss;
    __nv_bfloat16 *pSrch, *pWihh, *pWihl, *pFcwh, *pHdh;
    cudaGetSymbolAddress((void**)&pX,    g_X);
    cudaGetSymbolAddress((void**)&pHenc, g_henc);
    cudaGetSymbolAddress((void**)&pCenc, g_cenc);
    cudaGetSymbolAddress((void**)&pWeff, g_Weff);
    cudaGetSymbolAddress((void**)&pBeff, g_beff);
    cudaGetSymbolAddress((void**)&pLoss, g_loss);
    cudaGetSymbolAddress((void**)&pSrch, g_srch);
    cudaGetSymbolAddress((void**)&pWihh, g_wihh);
    cudaGetSymbolAddress((void**)&pWihl, g_wihl);
    cudaGetSymbolAddress((void**)&pFcwh, g_fcwh);
    cudaGetSymbolAddress((void**)&pHdh,  g_hdh);

    const int SMEM_RNN = RNN_SMEM_F * 4;
    const int SMEM_DEC = DEC_SMEM_F * 4;
    const int SMEM_GEMM = (int)sizeof(Bf16GemmSmem);
    cudaFuncSetAttribute(rnn_enc,  cudaFuncAttributeMaxDynamicSharedMemorySize, SMEM_RNN);
    cudaFuncSetAttribute(rnn_dec2, cudaFuncAttributeMaxDynamicSharedMemorySize, SMEM_DEC);
    cudaFuncSetAttribute(gemm_bf16_store, cudaFuncAttributeMaxDynamicSharedMemorySize, SMEM_GEMM);
    cudaFuncSetAttribute(gemm_bf16_loss2, cudaFuncAttributeMaxDynamicSharedMemorySize, SMEM_GEMM);

    const int RNN_BLOCKS = (BSZ + NB - 1) / NB;     // 143
    const int DEC_BLOCKS = (BSZ + NBD - 1) / NBD;   // 72
    const int MROWS = BSZ * TSZ;                    // 100000

    // launches 1-3: prep (launch #4 = phase-A tensor GEMM, the profiled slot)
    cvt_hi_t<ISZ, KPA><<<(MROWS * (KPA / 4) + 255) / 256, 256>>>(src, pSrch, MROWS);
    cvt_split_t<ISZ, KPA><<<(G4 * (KPA / 4) + 255) / 256, 256>>>(enc_Wih, pWihh, pWihl, G4);
    {
        dim3 grid(G4, 2);
        fold2_kernel<<<grid, 128>>>(pd_Wih, pd_Whh, pd_fcW, pd_fcb, pd_bih, pd_bhh,
                                    rd_Wih, rd_Whh, rd_fcW, rd_fcb, rd_bih, rd_bhh,
                                    pWeff, pBeff, pLoss);
    }

    // launch 4: phase A (tensor cores, A hi-only + B split)
    {
        dim3 grid((G4 + 63) / 64, (MROWS + 127) / 128);
        gemm_bf16_store<<<grid, 256, SMEM_GEMM>>>(pSrch, KPA, pWihh, pWihl, KPA,
                                                  enc_bih, enc_bhh, pX, MROWS, G4, KPA);
    }

    // encoder recurrence (f32x2 packed gate GEMM)
    rnn_enc<<<RNN_BLOCKS, NT_RNN, SMEM_RNN>>>(pX, enc_Whh, pHenc, pCenc);

    // fcW hi-only conversions (loss GEMM B operands)
    cvt_hi_t<HSZ, KPL><<<(ISZ * (KPL / 4) + 255) / 256, 256>>>(pd_fcW, pFcwh, ISZ);
    cvt_hi_t<HSZ, KPL><<<(ISZ * (KPL / 4) + 255) / 256, 256>>>(rd_fcW, pFcwh + ISZ * KPL, ISZ);

    // merged decoders (f32x2 packed gate GEMM): 144 CTAs = one wave
    {
        dim3 grid(DEC_BLOCKS, 2);
        rnn_dec2<<<grid, NT_RNN, SMEM_DEC>>>(pd_Whh, rd_Whh,
                                             pd_bih, pd_bhh, rd_bih, rd_bhh,
                                             pWeff, pBeff, pHenc, pCenc, pHdh);
    }

    // merged losses (pure bf16 tensor GEMM, fused MSE epilogue)
    {
        dim3 grid((ISZ + 63) / 64, (MROWS + 127) / 128, 2);
        gemm_bf16_loss2<<<grid, 256, SMEM_GEMM>>>(pHdh, pFcwh,
                                                  pd_fcb, rd_fcb, trg, src,
                                                  pLoss, MROWS, ISZ);
    }

    finalize_kernel<<<1, 1>>>(pLoss, out, 1.0f / (float)(BSZ * TSZ * ISZ));
}

// round 16
// speedup vs baseline: 1.6020x; 1.3423x over previous
#include <cuda_runtime.h>
#include <cuda_bf16.h>
#include <math.h>

#define BSZ 1000
#define TSZ 100
#define ISZ 264
#define HSZ 100
#define G4  400   // 4*H
#define KPA 272   // padded K for phase A (264 -> 17*16)
#define KPL 112   // padded K for loss GEMMs / decoder MMA (100 -> 7*16)

// ---------------- device scratch (static: no allocation allowed) ----------
__device__ float g_X[(size_t)BSZ * TSZ * G4];       // encoder gate inputs fp32
__device__ float g_henc[BSZ * HSZ];
__device__ float g_cenc[BSZ * HSZ];
__device__ float g_beff[2][G4];
__device__ float g_loss[2];

// bf16 operands
__device__ __nv_bfloat16 g_srch[(size_t)BSZ * TSZ * KPA];
__device__ __nv_bfloat16 g_wihh[G4 * KPA];
__device__ __nv_bfloat16 g_wihl[G4 * KPA];
__device__ __nv_bfloat16 g_fcwh[2][ISZ * KPL];
__device__ __nv_bfloat16 g_hdh[2][(size_t)BSZ * TSZ * KPL];  // decoder h (bf16)
// decoder weights, bf16 hi/lo, [j][k] pitch KPL (zero-padded k>=100)
__device__ __nv_bfloat16 g_weffh[2][G4 * KPL];
__device__ __nv_bfloat16 g_weffl[2][G4 * KPL];
__device__ __nv_bfloat16 g_whhh[2][G4 * KPL];
__device__ __nv_bfloat16 g_whhl[2][G4 * KPL];

// ---------------- f32x2 packed helpers --------------------------------------
__device__ __forceinline__ unsigned long long pk2(float v) {
    unsigned long long r;
    asm("mov.b64 %0, {%1,%1};" : "=l"(r) : "f"(v));
    return r;
}
__device__ __forceinline__ void fma2(unsigned long long& d,
                                     unsigned long long a, unsigned long long b) {
    asm("fma.rn.f32x2 %0, %1, %2, %0;" : "+l"(d) : "l"(a), "l"(b));
}
__device__ __forceinline__ float2 up2(unsigned long long v) {
    float2 r;
    asm("mov.b64 {%0,%1}, %2;" : "=f"(r.x), "=f"(r.y) : "l"(v));
    return r;
}
union F4U { float4 f4; unsigned long long u[2]; };

// ---------------- fast activations -----------------------------------------
__device__ __forceinline__ float ex2f(float x) {
    float r; asm("ex2.approx.f32 %0, %1;" : "=f"(r) : "f"(x)); return r;
}
__device__ __forceinline__ float rcpf(float x) {
    float r; asm("rcp.approx.f32 %0, %1;" : "=f"(r) : "f"(x)); return r;
}
__device__ __forceinline__ float sigf(float x) {
    return rcpf(1.f + ex2f(-1.4426950408889634f * x));
}
__device__ __forceinline__ float tanhf_fast(float x) {
    return fmaf(2.f, rcpf(1.f + ex2f(-2.8853900817779268f * x)), -1.f);
}

// ---------------- small kernels -------------------------------------------
__global__ void finalize_kernel(const float* loss, float* out, float inv) {
    out[0] = loss[0] * inv;
    out[1] = loss[1] * inv;
}

template <int K, int Kp>
__global__ __launch_bounds__(256) void cvt_hi_t(
    const float* __restrict__ x, __nv_bfloat16* __restrict__ h, int rows)
{
    const int Kp4 = Kp / 4;
    int idx = blockIdx.x * 256 + threadIdx.x;
    if (idx >= rows * Kp4) return;
    int r = idx / Kp4;
    int k4 = (idx - r * Kp4) * 4;
    float4 v;
    if (k4 + 3 < K) {
        v = *(const float4*)(x + (size_t)r * K + k4);
    } else {
        float tmp[4] = {0.f, 0.f, 0.f, 0.f};
        #pragma unroll
        for (int e = 0; e < 4; ++e)
            if (k4 + e < K) tmp[e] = x[(size_t)r * K + k4 + e];
        v = make_float4(tmp[0], tmp[1], tmp[2], tmp[3]);
    }
    __nv_bfloat16 hh[4];
    hh[0] = __float2bfloat16(v.x);
    hh[1] = __float2bfloat16(v.y);
    hh[2] = __float2bfloat16(v.z);
    hh[3] = __float2bfloat16(v.w);
    *(uint2*)(h + (size_t)idx * 4) = *(const uint2*)hh;
}

template <int K, int Kp>
__global__ __launch_bounds__(256) void cvt_split_t(
    const float* __restrict__ x, __nv_bfloat16* __restrict__ h,
    __nv_bfloat16* __restrict__ l, int rows)
{
    const int Kp4 = Kp / 4;
    int idx = blockIdx.x * 256 + threadIdx.x;
    if (idx >= rows * Kp4) return;
    int r = idx / Kp4;
    int k4 = (idx - r * Kp4) * 4;
    float4 v;
    if (k4 + 3 < K) {
        v = *(const float4*)(x + (size_t)r * K + k4);
    } else {
        float tmp[4] = {0.f, 0.f, 0.f, 0.f};
        #pragma unroll
        for (int e = 0; e < 4; ++e)
            if (k4 + e < K) tmp[e] = x[(size_t)r * K + k4 + e];
        v = make_float4(tmp[0], tmp[1], tmp[2], tmp[3]);
    }
    float vv[4] = {v.x, v.y, v.z, v.w};
    __nv_bfloat16 hh[4], ll[4];
    #pragma unroll
    for (int e = 0; e < 4; ++e) {
        hh[e] = __float2bfloat16(vv[e]);
        ll[e] = __float2bfloat16(vv[e] - __bfloat162float(hh[e]));
    }
    *(uint2*)(h + (size_t)idx * 4) = *(const uint2*)hh;
    *(uint2*)(l + (size_t)idx * 4) = *(const uint2*)ll;
}

// Both decoder folds: writes Weff as bf16 hi/lo (pitch KPL, zero-padded) + beff.
__global__ __launch_bounds__(128) void fold2_kernel(
    const float* __restrict__ pd_Wih, const float* __restrict__ pd_Whh,
    const float* __restrict__ pd_fcW, const float* __restrict__ pd_fcb,
    const float* __restrict__ pd_bih, const float* __restrict__ pd_bhh,
    const float* __restrict__ rd_Wih, const float* __restrict__ rd_Whh,
    const float* __restrict__ rd_fcW, const float* __restrict__ rd_fcb,
    const float* __restrict__ rd_bih, const float* __restrict__ rd_bhh,
    __nv_bfloat16* __restrict__ weffh, __nv_bfloat16* __restrict__ weffl,
    float* __restrict__ beff, float* __restrict__ loss)
{
    const int did = blockIdx.y;
    const float* Wih = did ? rd_Wih : pd_Wih;
    const float* Whh = did ? rd_Whh : pd_Whh;
    const float* fcW = did ? rd_fcW : pd_fcW;
    const float* fcb = did ? rd_fcb : pd_fcb;
    const float* bih = did ? rd_bih : pd_bih;
    const float* bhh = did ? rd_bhh : pd_bhh;
    __nv_bfloat16* Wh = weffh + (size_t)did * G4 * KPL;
    __nv_bfloat16* Wl = weffl + (size_t)did * G4 * KPL;
    float* be = beff + (size_t)did * G4;

    int j = blockIdx.x;
    int tid = threadIdx.x;
    if (blockIdx.x == 0 && did == 0 && tid < 2) loss[tid] = 0.f;

    __shared__ float swih[ISZ];
    __shared__ float red[128];
    for (int i = tid; i < ISZ; i += 128) swih[i] = Wih[j * ISZ + i];
    __syncthreads();
    if (tid < KPL) {
        float accv = 0.f;
        if (tid < HSZ) {
            float acc = Whh[j * HSZ + tid];
            #pragma unroll 4
            for (int i = 0; i < ISZ; ++i)
                acc = fmaf(swih[i], fcW[i * HSZ + tid], acc);
            accv = acc;
        }
        __nv_bfloat16 hi = __float2bfloat16(accv);
        Wh[j * KPL + tid] = hi;
        Wl[j * KPL + tid] = __float2bfloat16(accv - __bfloat162float(hi));
    }
    float p = 0.f;
    for (int i = tid; i < ISZ; i += 128) p = fmaf(swih[i], fcb[i], p);
    red[tid] = p;
    __syncthreads();
    for (int s = 64; s > 0; s >>= 1) {
        if (tid < s) red[tid] += red[tid + s];
        __syncthreads();
    }
    if (tid == 0) be[j] = bih[j] + bhh[j] + red[0];
}

// ---------------- tensor-core bf16 NT GEMM core -----------------------------
#define SAP 24

__device__ __forceinline__ void mma16816(float* d, const unsigned* a, const unsigned* b) {
    asm volatile(
        "mma.sync.aligned.m16n8k16.row.col.f32.bf16.bf16.f32 "
        "{%0,%1,%2,%3},{%4,%5,%6,%7},{%8,%9},{%0,%1,%2,%3};"
        : "+f"(d[0]), "+f"(d[1]), "+f"(d[2]), "+f"(d[3])
        : "r"(a[0]), "r"(a[1]), "r"(a[2]), "r"(a[3]), "r"(b[0]), "r"(b[1]));
}

__device__ __forceinline__ void ldsm_x4(unsigned* r, unsigned addr) {
    asm volatile(
        "ldmatrix.sync.aligned.m8n8.x4.shared.b16 {%0,%1,%2,%3}, [%4];"
        : "=r"(r[0]), "=r"(r[1]), "=r"(r[2]), "=r"(r[3]) : "r"(addr));
}

struct Bf16GemmSmem {
    __nv_bfloat16 Ash[2][128 * SAP];
    __nv_bfloat16 Bsh[2][64 * SAP];
    __nv_bfloat16 Bsl[2][64 * SAP];
    float red[256];
};

// A hi-only, B split (hi+lo): 2 MMAs per fragment pair. (phase A)
__device__ __forceinline__ void bf16_mainloop_a1(
    Bf16GemmSmem* sm, float d[2][4][4],
    const __nv_bfloat16* Ah, int lda,
    const __nv_bfloat16* Bh, const __nv_bfloat16* Bl, int ldb,
    int m0, int n0, int M, int N, int Kp)
{
    const int tid = threadIdx.x;
    const int lane = tid & 31;
    const int wid = tid >> 5;
    const int wy = wid & 3;
    const int wx = wid >> 2;

    const int ar = tid >> 1;
    const int ah8 = (tid & 1) * 8;
    const int bs = tid & 127;
    const int brow = bs >> 1;
    const int bh8 = (bs & 1) * 8;
    const int gm = m0 + ar;
    const int gn = n0 + brow;
    const __nv_bfloat16* srcB = (tid < 128) ? Bh : Bl;

    const unsigned aoff =
        ((unsigned)((wy * 32 + ((lane >> 3) & 1) * 8 + (lane & 7)) * SAP
                    + (lane >> 4) * 8)) * 2u;
    const unsigned boff =
        ((unsigned)((wx * 32 + ((lane >> 4) & 1) * 8 + (lane & 7)) * SAP
                    + ((lane >> 3) & 1) * 8)) * 2u;

    const unsigned ashb = (unsigned)__cvta_generic_to_shared(sm->Ash[0]);
    const unsigned bshb = (unsigned)__cvta_generic_to_shared(sm->Bsh[0]);
    const unsigned bslb = (unsigned)__cvta_generic_to_shared(sm->Bsl[0]);
    const unsigned abuf = 128 * SAP * 2;
    const unsigned bbuf = 64 * SAP * 2;
    const unsigned ni2step = 16 * SAP * 2;
    const unsigned mistep = 16 * SAP * 2;

    const uint4 zv = make_uint4(0, 0, 0, 0);
    uint4 vh = zv, vb = zv;
    if (gm < M) vh = *(const uint4*)(Ah + (size_t)gm * lda + ah8);
    if (gn < N) vb = *(const uint4*)(srcB + (size_t)gn * ldb + bh8);

    const int niter = Kp / 16;
    for (int i = 0; i < niter; ++i) {
        const unsigned cur = (unsigned)(i & 1);
        *(uint4*)&sm->Ash[cur][ar * SAP + ah8] = vh;
        __nv_bfloat16* dstB = (tid < 128) ? sm->Bsh[cur] : sm->Bsl[cur];
        *(uint4*)&dstB[brow * SAP + bh8] = vb;
        __syncthreads();

        if (i + 1 < niter) {
            int kn = (i + 1) * 16;
            vh = zv; vb = zv;
            if (gm < M) vh = *(const uint4*)(Ah + (size_t)gm * lda + kn + ah8);
            if (gn < N) vb = *(const uint4*)(srcB + (size_t)gn * ldb + kn + bh8);
        }

        unsigned bhf[4][2], blf[4][2];
        {
            unsigned r[4];
            unsigned b0 = bshb + cur * bbuf + boff;
            ldsm_x4(r, b0);
            bhf[0][0] = r[0]; bhf[0][1] = r[1]; bhf[1][0] = r[2]; bhf[1][1] = r[3];
            ldsm_x4(r, b0 + ni2step);
            bhf[2][0] = r[0]; bhf[2][1] = r[1]; bhf[3][0] = r[2]; bhf[3][1] = r[3];
            unsigned b1 = bslb + cur * bbuf + boff;
            ldsm_x4(r, b1);
            blf[0][0] = r[0]; blf[0][1] = r[1]; blf[1][0] = r[2]; blf[1][1] = r[3];
            ldsm_x4(r, b1 + ni2step);
            blf[2][0] = r[0]; blf[2][1] = r[1]; blf[3][0] = r[2]; blf[3][1] = r[3];
        }
        #pragma unroll
        for (int mi = 0; mi < 2; ++mi) {
            unsigned ahf[4];
            ldsm_x4(ahf, ashb + cur * abuf + aoff + mi * mistep);
            #pragma unroll
            for (int ni = 0; ni < 4; ++ni) {
                mma16816(d[mi][ni], ahf, bhf[ni]);
                mma16816(d[mi][ni], ahf, blf[ni]);
            }
        }
    }
    __syncthreads();
}

// A hi-only, B hi-only: 1 MMA per fragment pair. (loss GEMMs)
__device__ __forceinline__ void bf16_mainloop_11(
    Bf16GemmSmem* sm, float d[2][4][4],
    const __nv_bfloat16* Ah, int lda,
    const __nv_bfloat16* Bh, int ldb,
    int m0, int n0, int M, int N, int Kp)
{
    const int tid = threadIdx.x;
    const int lane = tid & 31;
    const int wid = tid >> 5;
    const int wy = wid & 3;
    const int wx = wid >> 2;

    const int ar = tid >> 1;
    const int ah8 = (tid & 1) * 8;
    const int brow = (tid & 127) >> 1;
    const int bh8 = (tid & 1) * 8;
    const int gm = m0 + ar;
    const int gn = n0 + brow;
    const bool bldr = (tid < 128);

    const unsigned aoff =
        ((unsigned)((wy * 32 + ((lane >> 3) & 1) * 8 + (lane & 7)) * SAP
                    + (lane >> 4) * 8)) * 2u;
    const unsigned boff =
        ((unsigned)((wx * 32 + ((lane >> 4) & 1) * 8 + (lane & 7)) * SAP
                    + ((lane >> 3) & 1) * 8)) * 2u;

    const unsigned ashb = (unsigned)__cvta_generic_to_shared(sm->Ash[0]);
    const unsigned bshb = (unsigned)__cvta_generic_to_shared(sm->Bsh[0]);
    const unsigned abuf = 128 * SAP * 2;
    const unsigned bbuf = 64 * SAP * 2;
    const unsigned ni2step = 16 * SAP * 2;
    const unsigned mistep = 16 * SAP * 2;

    const uint4 zv = make_uint4(0, 0, 0, 0);
    uint4 vh = zv, vb = zv;
    if (gm < M) vh = *(const uint4*)(Ah + (size_t)gm * lda + ah8);
    if (bldr && gn < N) vb = *(const uint4*)(Bh + (size_t)gn * ldb + bh8);

    const int niter = Kp / 16;
    for (int i = 0; i < niter; ++i) {
        const unsigned cur = (unsigned)(i & 1);
        *(uint4*)&sm->Ash[cur][ar * SAP + ah8] = vh;
        if (bldr) *(uint4*)&sm->Bsh[cur][brow * SAP + bh8] = vb;
        __syncthreads();

        if (i + 1 < niter) {
            int kn = (i + 1) * 16;
            vh = zv; vb = zv;
            if (gm < M) vh = *(const uint4*)(Ah + (size_t)gm * lda + kn + ah8);
            if (bldr && gn < N) vb = *(const uint4*)(Bh + (size_t)gn * ldb + kn + bh8);
        }

        unsigned bhf[4][2];
        {
            unsigned r[4];
            unsigned b0 = bshb + cur * bbuf + boff;
            ldsm_x4(r, b0);
            bhf[0][0] = r[0]; bhf[0][1] = r[1]; bhf[1][0] = r[2]; bhf[1][1] = r[3];
            ldsm_x4(r, b0 + ni2step);
            bhf[2][0] = r[0]; bhf[2][1] = r[1]; bhf[3][0] = r[2]; bhf[3][1] = r[3];
        }
        #pragma unroll
        for (int mi = 0; mi < 2; ++mi) {
            unsigned ahf[4];
            ldsm_x4(ahf, ashb + cur * abuf + aoff + mi * mistep);
            #pragma unroll
            for (int ni = 0; ni < 4; ++ni)
                mma16816(d[mi][ni], ahf, bhf[ni]);
        }
    }
    __syncthreads();
}

__global__ __launch_bounds__(256, 3) void gemm_bf16_store(
    const __nv_bfloat16* __restrict__ Ah, int lda,
    const __nv_bfloat16* __restrict__ Bh, const __nv_bfloat16* __restrict__ Bl, int ldb,
    const float* __restrict__ bias1, const float* __restrict__ bias2,
    float* __restrict__ C, int M, int N, int Kp)
{
    extern __shared__ char smraw[];
    Bf16GemmSmem* sm = (Bf16GemmSmem*)smraw;
    const int tid = threadIdx.x;
    const int lane = tid & 31;
    const int wid = tid >> 5;
    const int wy = wid & 3, wx = wid >> 2;
    const int g = lane >> 2, t = lane & 3;
    const int m0 = blockIdx.y * 128, n0 = blockIdx.x * 64;

    float d[2][4][4];
    #pragma unroll
    for (int mi = 0; mi < 2; ++mi)
        #pragma unroll
        for (int ni = 0; ni < 4; ++ni)
            #pragma unroll
            for (int e = 0; e < 4; ++e) d[mi][ni][e] = 0.f;

    bf16_mainloop_a1(sm, d, Ah, lda, Bh, Bl, ldb, m0, n0, M, N, Kp);

    #pragma unroll
    for (int mi = 0; mi < 2; ++mi) {
        #pragma unroll
        for (int rr = 0; rr < 2; ++rr) {
            int m = m0 + wy * 32 + mi * 16 + rr * 8 + g;
            if (m >= M) continue;
            #pragma unroll
            for (int ni = 0; ni < 4; ++ni) {
                int n = n0 + wx * 32 + ni * 8 + 2 * t;
                if (n + 1 < N) {
                    float v0 = d[mi][ni][rr * 2 + 0] + bias1[n] + bias2[n];
                    float v1 = d[mi][ni][rr * 2 + 1] + bias1[n + 1] + bias2[n + 1];
                    *(float2*)(C + (size_t)m * N + n) = make_float2(v0, v1);
                } else if (n < N) {
                    C[(size_t)m * N + n] = d[mi][ni][rr * 2 + 0] + bias1[n] + bias2[n];
                }
            }
        }
    }
}

__global__ __launch_bounds__(256, 3) void gemm_bf16_loss2(
    const __nv_bfloat16* __restrict__ Ahb,
    const __nv_bfloat16* __restrict__ Bhb,
    const float* __restrict__ fcb0, const float* __restrict__ fcb1,
    const float* __restrict__ trg, const float* __restrict__ src,
    float* __restrict__ loss, int M, int N)
{
    extern __shared__ char smraw[];
    Bf16GemmSmem* sm = (Bf16GemmSmem*)smraw;
    const int did = blockIdx.z;
    const __nv_bfloat16* Ah = Ahb + (size_t)did * M * KPL;
    const __nv_bfloat16* Bh = Bhb + (size_t)did * N * KPL;
    const float* bias = did ? fcb1 : fcb0;
    const float* ref = did ? src : trg;
    float* lossOut = did ? (loss + 0) : (loss + 1);
    const int revT = did ? TSZ : 0;

    const int tid = threadIdx.x;
    const int lane = tid & 31;
    const int wid = tid >> 5;
    const int wy = wid & 3, wx = wid >> 2;
    const int g = lane >> 2, t = lane & 3;
    const int m0 = blockIdx.y * 128, n0 = blockIdx.x * 64;

    float d[2][4][4];
    #pragma unroll
    for (int mi = 0; mi < 2; ++mi)
        #pragma unroll
        for (int ni = 0; ni < 4; ++ni)
            #pragma unroll
            for (int e = 0; e < 4; ++e) d[mi][ni][e] = 0.f;

    bf16_mainloop_11(sm, d, Ah, KPL, Bh, KPL, m0, n0, M, N, KPL);

    float ls = 0.f;
    #pragma unroll
    for (int mi = 0; mi < 2; ++mi) {
        #pragma unroll
        for (int rr = 0; rr < 2; ++rr) {
            int m = m0 + wy * 32 + mi * 16 + rr * 8 + g;
            if (m >= M) continue;
            const float* rrow;
            if (revT > 0) {
                int b = m / revT, tt = m - b * revT;
                rrow = ref + ((size_t)b * revT + (revT - 1 - tt)) * N;
            } else {
                rrow = ref + (size_t)m * N;
            }
            #pragma unroll
            for (int ni = 0; ni < 4; ++ni) {
                int n = n0 + wx * 32 + ni * 8 + 2 * t;
                #pragma unroll
                for (int e = 0; e < 2; ++e) {
                    if (n + e < N) {
                        float v = d[mi][ni][rr * 2 + e] + bias[n + e];
                        float diff = v - rrow[n + e];
                        ls = fmaf(diff, diff, ls);
                    }
                }
            }
        }
    }
    sm->red[tid] = ls;
    __syncthreads();
    for (int s = 128; s > 0; s >>= 1) {
        if (tid < s) sm->red[tid] += sm->red[tid + s];
        __syncthreads();
    }
    if (tid == 0) atomicAdd(lossOut, sm->red[0]);
}

// ---------------- encoder recurrence (unchanged, FFMA2) ---------------------
#define NB 7
#define NT_RNN 416
#define RNN_SMEM_F (40000 + 800 + 800 + 3600)

__global__ __launch_bounds__(NT_RNN, 1) void rnn_enc(
    const float* __restrict__ X, const float* __restrict__ Whh,
    float* __restrict__ hf, float* __restrict__ cf)
{
    extern __shared__ float s[];
    float* sW  = s;
    float* sHa = s + 40000;
    float* sHb = sHa + 800;
    float* sG  = sHb + 800;
    const int tid = threadIdx.x;
    const int b0 = blockIdx.x * NB;

    for (int i = tid; i < 10000; i += NT_RNN)
        ((float4*)sW)[i] = ((const float4*)Whh)[i];
    for (int i = tid; i < 800; i += NT_RNN) sHa[i] = 0.f;
    __syncthreads();

    const int i0 = tid, i1 = tid + NT_RNN;
    const int k0c = i0 % 100, b0c = i0 / 100;
    const int k1c = i1 % 100, b1c = i1 / 100;
    const bool v0 = (i0 < NB * 100), v1 = (i1 < NB * 100);
    float c0r = 0.f, c1r = 0.f, h0r = 0.f, h1r = 0.f;

    int bidx[NB];
    #pragma unroll
    for (int b = 0; b < NB; ++b) {
        int bb = b0 + b; if (bb > BSZ - 1) bb = BSZ - 1;
        bidx[b] = bb;
    }

    for (int t = 0; t < TSZ; ++t) {
        const float* hin = (t & 1) ? sHb : sHa;
        float* hout = (t & 1) ? sHa : sHb;
        if (tid < 400) {
            const int j = tid;
            float xr[NB];
            #pragma unroll
            for (int b = 0; b < NB; ++b)
                xr[b] = X[((size_t)bidx[b] * TSZ + t) * G4 + j];
            unsigned long long a2[4] = {0ull, 0ull, 0ull, 0ull};
            const float4* wj = (const float4*)(sW + j * 100);
            const float* hp = hin;
            #pragma unroll 5
            for (int k4 = 0; k4 < 25; ++k4) {
                float4 w = wj[k4];
                #pragma unroll
                for (int dd = 0; dd < 4; ++dd) {
                    float wv = (dd == 0) ? w.x : (dd == 1) ? w.y : (dd == 2) ? w.z : w.w;
                    unsigned long long w2 = pk2(wv);
                    F4U u0, u1;
                    u0.f4 = *(const float4*)(hp + (k4 * 4 + dd) * 8);
                    u1.f4 = *(const float4*)(hp + (k4 * 4 + dd) * 8 + 4);
                    fma2(a2[0], u0.u[0], w2);
                    fma2(a2[1], u0.u[1], w2);
                    fma2(a2[2], u1.u[0], w2);
                    fma2(a2[3], u1.u[1], w2);
                }
            }
            float2 p0 = up2(a2[0]), p1 = up2(a2[1]);
            float2 p2 = up2(a2[2]), p3 = up2(a2[3]);
            float accv[7] = {p0.x, p0.y, p1.x, p1.y, p2.x, p2.y, p3.x};
            float* gp = sG + j * 9;
            #pragma unroll
            for (int b = 0; b < NB; ++b) gp[b] = accv[b] + xr[b];
        }
        __syncthreads();
        if (v0) {
            float gi = sigf(sG[(k0c) * 9 + b0c]);
            float gf = sigf(sG[(100 + k0c) * 9 + b0c]);
            float gg = tanhf_fast(sG[(200 + k0c) * 9 + b0c]);
            float go = sigf(sG[(300 + k0c) * 9 + b0c]);
            c0r = fmaf(gf, c0r, gi * gg);
            h0r = go * tanhf_fast(c0r);
            hout[k0c * 8 + b0c] = h0r;
        }
        if (v1) {
            float gi = sigf(sG[(k1c) * 9 + b1c]);
            float gf = sigf(sG[(100 + k1c) * 9 + b1c]);
            float gg = tanhf_fast(sG[(200 + k1c) * 9 + b1c]);
            float go = sigf(sG[(300 + k1c) * 9 + b1c]);
            c1r = fmaf(gf, c1r, gi * gg);
            h1r = go * tanhf_fast(c1r);
            hout[k1c * 8 + b1c] = h1r;
        }
        __syncthreads();
    }

    if (v0 && b0 + b0c < BSZ) {
        hf[(b0 + b0c) * HSZ + k0c] = h0r;
        cf[(b0 + b0c) * HSZ + k0c] = c0r;
    }
    if (v1 && b0 + b1c < BSZ) {
        hf[(b0 + b1c) * HSZ + k1c] = h1r;
        cf[(b0 + b1c) * HSZ + k1c] = c1r;
    }
}

// ---- MMA decoders: 16 batches/CTA, grid (63,2) = 126 CTAs, 320 threads -----
// Gates via mma.m16n8k16: A = h bf16 (hi-only), B = Weff bf16 hi+lo in smem.
// Step 0 uses Whh bf16 (preloaded); Weff copied in during t=0 cell phase.
#define DNT 320
#define DNB 16
#define APW 120                   // A pitch (bf16): 240 B rows, conflict-free
#define GPW 404                   // sG pitch (fp32)
// smem: Wh 89600 | Wl 89600 | Ab 2*16*120*2=7680 | sG 16*404*4=25856
#define DEC_SMEM_B (89600 + 89600 + 7680 + 25856)

__device__ __forceinline__ void dec_copyW(
    char* smem, const __nv_bfloat16* gh, const __nv_bfloat16* gl, int tid)
{
    uint4* dh = (uint4*)smem;
    uint4* dl = (uint4*)(smem + 89600);
    const uint4* sh = (const uint4*)gh;
    const uint4* sl = (const uint4*)gl;
    for (int i = tid; i < 5600; i += DNT) { dh[i] = sh[i]; dl[i] = sl[i]; }
}

__global__ __launch_bounds__(DNT, 1) void rnn_dec2(
    const __nv_bfloat16* __restrict__ whhh, const __nv_bfloat16* __restrict__ whhl,
    const __nv_bfloat16* __restrict__ weffh, const __nv_bfloat16* __restrict__ weffl,
    const float* __restrict__ bih0, const float* __restrict__ bhh0,
    const float* __restrict__ bih1, const float* __restrict__ bhh1,
    const float* __restrict__ beffbase,
    const float* __restrict__ h0, const float* __restrict__ c0,
    __nv_bfloat16* __restrict__ hdhb)
{
    extern __shared__ char smem[];
    __nv_bfloat16* Ab = (__nv_bfloat16*)(smem + 179200);
    float* sG = (float*)(smem + 186880);
    const int tid = threadIdx.x;
    const int lane = tid & 31;
    const int wid = tid >> 5;
    const int b0 = blockIdx.x * DNB;
    const int did = blockIdx.y;

    const size_t woff = (size_t)did * G4 * KPL;
    const float* beff = beffbase + (size_t)did * G4;
    const float* bih = did ? bih1 : bih0;
    const float* bhh = did ? bhh1 : bhh0;
    __nv_bfloat16* hdh = hdhb + (size_t)did * BSZ * TSZ * KPL;

    // load Whh (for step 0) and zero A buffers
    dec_copyW(smem, whhh + woff, whhl + woff, tid);
    {
        const uint4 zv = make_uint4(0, 0, 0, 0);
        for (int i = tid; i < 480; i += DNT) ((uint4*)Ab)[i] = zv;
    }

    // gate-warp constants
    const int ngrp = (wid < 5) ? 3 : 2;
    int grp[3];
    #pragma unroll
    for (int gi = 0; gi < 3; ++gi) grp[gi] = wid + gi * 10;
    const int c2 = (lane & 3) * 2;
    const int r0w = lane >> 2;
    float bE[3][2][2], bZ[3][2][2];
    #pragma unroll
    for (int gi = 0; gi < 3; ++gi) {
        #pragma unroll
        for (int st = 0; st < 2; ++st) {
            bE[gi][st][0] = bE[gi][st][1] = 0.f;
            bZ[gi][st][0] = bZ[gi][st][1] = 0.f;
            if (gi < ngrp) {
                int n = grp[gi] * 16 + st * 8 + c2;
                bE[gi][st][0] = beff[n];
                bE[gi][st][1] = beff[n + 1];
                bZ[gi][st][0] = bih[n] + bhh[n];
                bZ[gi][st][1] = bih[n + 1] + bhh[n + 1];
            }
        }
    }
    const unsigned aoff =
        ((unsigned)(((lane & 7) + ((lane >> 3) & 1) * 8) * APW)) * 2u
        + (unsigned)((lane >> 4) * 16);
    const unsigned boff =
        ((unsigned)((((lane >> 4) & 1) * 8 + (lane & 7)) * KPL)) * 2u
        + (unsigned)(((lane >> 3) & 1) * 16);
    const unsigned wbh = (unsigned)__cvta_generic_to_shared(smem);
    const unsigned abA = (unsigned)__cvta_generic_to_shared(Ab);
    const unsigned abufB = 16 * APW * 2;   // 3840 B per A buffer
    const unsigned grpstep = 16 * KPL * 2; // 3584 B per 16-row W group
    const unsigned wlo = 89600;

    // cell-phase constants: items (k,b), 5 per thread
    int ck[5], cb[5];
    bool cv[5], cw[5];
    float cc[5];
    __nv_bfloat16* outh[5];
    #pragma unroll
    for (int q = 0; q < 5; ++q) {
        int item = q * DNT + tid;
        bool v = item < DNB * 100;
        int k = v ? (item % 100) : 0;
        int b = v ? (item / 100) : 0;
        ck[q] = k; cb[q] = b; cv[q] = v;
        cw[q] = v && (b0 + b < BSZ);
        cc[q] = 0.f;
        outh[q] = hdh + ((size_t)(b0 + b) * TSZ) * KPL + k;
    }
    // init h0/c0 (h0 -> bf16 into Ab[0])
    #pragma unroll
    for (int q = 0; q < 5; ++q) {
        if (cv[q]) {
            int bb = b0 + cb[q]; if (bb > BSZ - 1) bb = BSZ - 1;
            Ab[cb[q] * APW + ck[q]] = __float2bfloat16(h0[bb * HSZ + ck[q]]);
            cc[q] = c0[bb * HSZ + ck[q]];
        }
    }
    __syncthreads();

    for (int t = 0; t < TSZ; ++t) {
        // ---- gate MMA phase ----
        {
            float d[3][2][4];
            #pragma unroll
            for (int gi = 0; gi < 3; ++gi)
                #pragma unroll
                for (int st = 0; st < 2; ++st)
                    #pragma unroll
                    for (int e = 0; e < 4; ++e) d[gi][st][e] = 0.f;

            const unsigned ab = abA + (unsigned)(t & 1) * abufB + aoff;
            #pragma unroll
            for (int k = 0; k < 7; ++k) {
                unsigned ah[4];
                ldsm_x4(ah, ab + k * 32);
                #pragma unroll
                for (int gi = 0; gi < 3; ++gi) {
                    if (gi < ngrp) {
                        unsigned bb = wbh + (unsigned)grp[gi] * grpstep + boff + k * 32;
                        unsigned bf[4];
                        ldsm_x4(bf, bb);
                        mma16816(d[gi][0], ah, bf + 0);
                        mma16816(d[gi][1], ah, bf + 2);
                        ldsm_x4(bf, bb + wlo);
                        mma16816(d[gi][0], ah, bf + 0);
                        mma16816(d[gi][1], ah, bf + 2);
                    }
                }
            }
            #pragma unroll
            for (int gi = 0; gi < 3; ++gi) {
                if (gi < ngrp) {
                    #pragma unroll
                    for (int st = 0; st < 2; ++st) {
                        int n = grp[gi] * 16 + st * 8 + c2;
                        float ba = (t == 0) ? bZ[gi][st][0] : bE[gi][st][0];
                        float bb2 = (t == 0) ? bZ[gi][st][1] : bE[gi][st][1];
                        *(float2*)&sG[r0w * GPW + n] =
                            make_float2(d[gi][st][0] + ba, d[gi][st][1] + bb2);
                        *(float2*)&sG[(r0w + 8) * GPW + n] =
                            make_float2(d[gi][st][2] + ba, d[gi][st][3] + bb2);
                    }
                }
            }
        }
        __syncthreads();
        // ---- cell phase ----
        {
            __nv_bfloat16* Adst = Ab + ((t + 1) & 1) * (16 * APW);
            #pragma unroll
            for (int q = 0; q < 5; ++q) {
                if (cv[q]) {
                    int k = ck[q], b = cb[q];
                    const float* gb = sG + b * GPW;
                    float gi = sigf(gb[k]);
                    float gf = sigf(gb[100 + k]);
                    float gg = tanhf_fast(gb[200 + k]);
                    float go = sigf(gb[300 + k]);
                    float c = fmaf(gf, cc[q], gi * gg);
                    cc[q] = c;
                    float h = go * tanhf_fast(c);
                    __nv_bfloat16 hb = __float2bfloat16(h);
                    Adst[b * APW + k] = hb;
                    if (cw[q]) outh[q][(size_t)t * KPL] = hb;
                }
            }
        }
        if (t == 0)   // swap in the folded recurrence weight for t >= 1
            dec_copyW(smem, weffh + woff, weffl + woff, tid);
        __syncthreads();
    }
}

// ---------------- launch ----------------------------------------------------
extern "C" void kernel_launch(void* const* d_in, const int* in_sizes, int n_in,
                              void* d_out, int out_size)
{
    const float* src     = (const float*)d_in[0];
    const float* trg     = (const float*)d_in[1];
    const float* enc_Wih = (const float*)d_in[2];
    const float* enc_Whh = (const float*)d_in[3];
    const float* enc_bih = (const float*)d_in[4];
    const float* enc_bhh = (const float*)d_in[5];
    const float* pd_Wih  = (const float*)d_in[6];
    const float* pd_Whh  = (const float*)d_in[7];
    const float* pd_bih  = (const float*)d_in[8];
    const float* pd_bhh  = (const float*)d_in[9];
    const float* pd_fcW  = (const float*)d_in[10];
    const float* pd_fcb  = (const float*)d_in[11];
    const float* rd_Wih  = (const float*)d_in[12];
    const float* rd_Whh  = (const float*)d_in[13];
    const float* rd_bih  = (const float*)d_in[14];
    const float* rd_bhh  = (const float*)d_in[15];
    const float* rd_fcW  = (const float*)d_in[16];
    const float* rd_fcb  = (const float*)d_in[17];
    float* out = (float*)d_out;

    float *pX, *pHenc, *pCenc, *pBeff, *pLoss;
    __nv_bfloat16 *pSrch, *pWihh, *pWihl, *pFcwh, *pHdh;
    __nv_bfloat16 *pWeffh, *pWeffl, *pWhhh, *pWhhl;
    cudaGetSymbolAddress((void**)&pX,    g_X);
    cudaGetSymbolAddress((void**)&pHenc, g_henc);
    cudaGetSymbolAddress((void**)&pCenc, g_cenc);
    cudaGetSymbolAddress((void**)&pBeff, g_beff);
    cudaGetSymbolAddress((void**)&pLoss, g_loss);
    cudaGetSymbolAddress((void**)&pSrch, g_srch);
    cudaGetSymbolAddress((void**)&pWihh, g_wihh);
    cudaGetSymbolAddress((void**)&pWihl, g_wihl);
    cudaGetSymbolAddress((void**)&pFcwh, g_fcwh);
    cudaGetSymbolAddress((void**)&pHdh,  g_hdh);
    cudaGetSymbolAddress((void**)&pWeffh, g_weffh);
    cudaGetSymbolAddress((void**)&pWeffl, g_weffl);
    cudaGetSymbolAddress((void**)&pWhhh,  g_whhh);
    cudaGetSymbolAddress((void**)&pWhhl,  g_whhl);

    const int SMEM_RNN = RNN_SMEM_F * 4;
    const int SMEM_GEMM = (int)sizeof(Bf16GemmSmem);
    cudaFuncSetAttribute(rnn_enc,  cudaFuncAttributeMaxDynamicSharedMemorySize, SMEM_RNN);
    cudaFuncSetAttribute(rnn_dec2, cudaFuncAttributeMaxDynamicSharedMemorySize, DEC_SMEM_B);
    cudaFuncSetAttribute(gemm_bf16_store, cudaFuncAttributeMaxDynamicSharedMemorySize, SMEM_GEMM);
    cudaFuncSetAttribute(gemm_bf16_loss2, cudaFuncAttributeMaxDynamicSharedMemorySize, SMEM_GEMM);

    const int RNN_BLOCKS = (BSZ + NB - 1) / NB;     // 143
    const int DEC_BLOCKS = (BSZ + DNB - 1) / DNB;   // 63
    const int MROWS = BSZ * TSZ;                    // 100000

    // prep (launch #4 = phase-A tensor GEMM, the profiled slot)
    cvt_hi_t<ISZ, KPA><<<(MROWS * (KPA / 4) + 255) / 256, 256>>>(src, pSrch, MROWS);
    cvt_split_t<ISZ, KPA><<<(G4 * (KPA / 4) + 255) / 256, 256>>>(enc_Wih, pWihh, pWihl, G4);
    {
        dim3 grid(G4, 2);
        fold2_kernel<<<grid, 128>>>(pd_Wih, pd_Whh, pd_fcW, pd_fcb, pd_bih, pd_bhh,
                                    rd_Wih, rd_Whh, rd_fcW, rd_fcb, rd_bih, rd_bhh,
                                    pWeffh, pWeffl, pBeff, pLoss);
    }

    // phase A (tensor cores)
    {
        dim3 grid((G4 + 63) / 64, (MROWS + 127) / 128);
        gemm_bf16_store<<<grid, 256, SMEM_GEMM>>>(pSrch, KPA, pWihh, pWihl, KPA,
                                                  enc_bih, enc_bhh, pX, MROWS, G4, KPA);
    }

    // encoder recurrence
    rnn_enc<<<RNN_BLOCKS, NT_RNN, SMEM_RNN>>>(pX, enc_Whh, pHenc, pCenc);

    // conversions for decoders + losses
    cvt_hi_t<HSZ, KPL><<<(ISZ * (KPL / 4) + 255) / 256, 256>>>(pd_fcW, pFcwh, ISZ);
    cvt_hi_t<HSZ, KPL><<<(ISZ * (KPL / 4) + 255) / 256, 256>>>(rd_fcW, pFcwh + ISZ * KPL, ISZ);
    cvt_split_t<HSZ, KPL><<<(G4 * (KPL / 4) + 255) / 256, 256>>>(pd_Whh, pWhhh, pWhhl, G4);
    cvt_split_t<HSZ, KPL><<<(G4 * (KPL / 4) + 255) / 256, 256>>>(rd_Whh, pWhhh + G4 * KPL,
                                                                 pWhhl + G4 * KPL, G4);

    // MMA decoders: 126 CTAs, one wave
    {
        dim3 grid(DEC_BLOCKS, 2);
        rnn_dec2<<<grid, DNT, DEC_SMEM_B>>>(pWhhh, pWhhl, pWeffh, pWeffl,
                                            pd_bih, pd_bhh, rd_bih, rd_bhh,
                                            pBeff, pHenc, pCenc, pHdh);
    }

    // merged losses
    {
        dim3 grid((ISZ + 63) / 64, (MROWS + 127) / 128, 2);
        gemm_bf16_loss2<<<grid, 256, SMEM_GEMM>>>(pHdh, pFcwh,
                                                  pd_fcb, rd_fcb, trg, src,
                                                  pLoss, MROWS, ISZ);
    }

    finalize_kernel<<<1, 1>>>(pLoss, out, 1.0f / (float)(BSZ * TSZ * ISZ));
}

// round 17
// speedup vs baseline: 1.7584x; 1.0976x over previous
#include <cuda_runtime.h>
#include <cuda_bf16.h>
#include <math.h>

#define BSZ 1000
#define TSZ 100
#define ISZ 264
#define HSZ 100
#define G4  400   // 4*H
#define KPA 272   // padded K for phase A (264 -> 17*16)
#define KPL 112   // padded K for loss GEMMs / recurrence MMA (100 -> 7*16)

// ---------------- device scratch (static: no allocation allowed) ----------
__device__ float g_X[(size_t)BSZ * TSZ * G4];       // encoder gate inputs fp32
__device__ float g_henc[BSZ * HSZ];
__device__ float g_cenc[BSZ * HSZ];
__device__ float g_beff[2][G4];
__device__ float g_loss[2];

// bf16 operands
__device__ __nv_bfloat16 g_srch[(size_t)BSZ * TSZ * KPA];
__device__ __nv_bfloat16 g_wihh[G4 * KPA];
__device__ __nv_bfloat16 g_wihl[G4 * KPA];
__device__ __nv_bfloat16 g_fcwh[2][ISZ * KPL];
__device__ __nv_bfloat16 g_hdh[2][(size_t)BSZ * TSZ * KPL];  // decoder h (bf16)
// recurrence weights, bf16 hi/lo, [j][k] pitch KPL (zero-padded k>=100)
__device__ __nv_bfloat16 g_weffh[2][G4 * KPL];
__device__ __nv_bfloat16 g_weffl[2][G4 * KPL];
__device__ __nv_bfloat16 g_whhh[2][G4 * KPL];
__device__ __nv_bfloat16 g_whhl[2][G4 * KPL];
__device__ __nv_bfloat16 g_ewhh[G4 * KPL];    // encoder Whh split
__device__ __nv_bfloat16 g_ewhl[G4 * KPL];

// ---------------- fast activations -----------------------------------------
__device__ __forceinline__ float ex2f(float x) {
    float r; asm("ex2.approx.f32 %0, %1;" : "=f"(r) : "f"(x)); return r;
}
__device__ __forceinline__ float rcpf(float x) {
    float r; asm("rcp.approx.f32 %0, %1;" : "=f"(r) : "f"(x)); return r;
}
__device__ __forceinline__ float sigf(float x) {
    return rcpf(1.f + ex2f(-1.4426950408889634f * x));
}
__device__ __forceinline__ float tanhf_fast(float x) {
    return fmaf(2.f, rcpf(1.f + ex2f(-2.8853900817779268f * x)), -1.f);
}

// ---------------- small kernels -------------------------------------------
__global__ void finalize_kernel(const float* loss, float* out, float inv) {
    out[0] = loss[0] * inv;
    out[1] = loss[1] * inv;
}

template <int K, int Kp>
__global__ __launch_bounds__(256) void cvt_hi_t(
    const float* __restrict__ x, __nv_bfloat16* __restrict__ h, int rows)
{
    const int Kp4 = Kp / 4;
    int idx = blockIdx.x * 256 + threadIdx.x;
    if (idx >= rows * Kp4) return;
    int r = idx / Kp4;
    int k4 = (idx - r * Kp4) * 4;
    float4 v;
    if (k4 + 3 < K) {
        v = *(const float4*)(x + (size_t)r * K + k4);
    } else {
        float tmp[4] = {0.f, 0.f, 0.f, 0.f};
        #pragma unroll
        for (int e = 0; e < 4; ++e)
            if (k4 + e < K) tmp[e] = x[(size_t)r * K + k4 + e];
        v = make_float4(tmp[0], tmp[1], tmp[2], tmp[3]);
    }
    __nv_bfloat16 hh[4];
    hh[0] = __float2bfloat16(v.x);
    hh[1] = __float2bfloat16(v.y);
    hh[2] = __float2bfloat16(v.z);
    hh[3] = __float2bfloat16(v.w);
    *(uint2*)(h + (size_t)idx * 4) = *(const uint2*)hh;
}

template <int K, int Kp>
__global__ __launch_bounds__(256) void cvt_split_t(
    const float* __restrict__ x, __nv_bfloat16* __restrict__ h,
    __nv_bfloat16* __restrict__ l, int rows)
{
    const int Kp4 = Kp / 4;
    int idx = blockIdx.x * 256 + threadIdx.x;
    if (idx >= rows * Kp4) return;
    int r = idx / Kp4;
    int k4 = (idx - r * Kp4) * 4;
    float4 v;
    if (k4 + 3 < K) {
        v = *(const float4*)(x + (size_t)r * K + k4);
    } else {
        float tmp[4] = {0.f, 0.f, 0.f, 0.f};
        #pragma unroll
        for (int e = 0; e < 4; ++e)
            if (k4 + e < K) tmp[e] = x[(size_t)r * K + k4 + e];
        v = make_float4(tmp[0], tmp[1], tmp[2], tmp[3]);
    }
    float vv[4] = {v.x, v.y, v.z, v.w};
    __nv_bfloat16 hh[4], ll[4];
    #pragma unroll
    for (int e = 0; e < 4; ++e) {
        hh[e] = __float2bfloat16(vv[e]);
        ll[e] = __float2bfloat16(vv[e] - __bfloat162float(hh[e]));
    }
    *(uint2*)(h + (size_t)idx * 4) = *(const uint2*)hh;
    *(uint2*)(l + (size_t)idx * 4) = *(const uint2*)ll;
}

// Both decoder folds: writes Weff as bf16 hi/lo (pitch KPL, zero-padded) + beff.
__global__ __launch_bounds__(128) void fold2_kernel(
    const float* __restrict__ pd_Wih, const float* __restrict__ pd_Whh,
    const float* __restrict__ pd_fcW, const float* __restrict__ pd_fcb,
    const float* __restrict__ pd_bih, const float* __restrict__ pd_bhh,
    const float* __restrict__ rd_Wih, const float* __restrict__ rd_Whh,
    const float* __restrict__ rd_fcW, const float* __restrict__ rd_fcb,
    const float* __restrict__ rd_bih, const float* __restrict__ rd_bhh,
    __nv_bfloat16* __restrict__ weffh, __nv_bfloat16* __restrict__ weffl,
    float* __restrict__ beff, float* __restrict__ loss)
{
    const int did = blockIdx.y;
    const float* Wih = did ? rd_Wih : pd_Wih;
    const float* Whh = did ? rd_Whh : pd_Whh;
    const float* fcW = did ? rd_fcW : pd_fcW;
    const float* fcb = did ? rd_fcb : pd_fcb;
    const float* bih = did ? rd_bih : pd_bih;
    const float* bhh = did ? rd_bhh : pd_bhh;
    __nv_bfloat16* Wh = weffh + (size_t)did * G4 * KPL;
    __nv_bfloat16* Wl = weffl + (size_t)did * G4 * KPL;
    float* be = beff + (size_t)did * G4;

    int j = blockIdx.x;
    int tid = threadIdx.x;
    if (blockIdx.x == 0 && did == 0 && tid < 2) loss[tid] = 0.f;

    __shared__ float swih[ISZ];
    __shared__ float red[128];
    for (int i = tid; i < ISZ; i += 128) swih[i] = Wih[j * ISZ + i];
    __syncthreads();
    if (tid < KPL) {
        float accv = 0.f;
        if (tid < HSZ) {
            float acc = Whh[j * HSZ + tid];
            #pragma unroll 4
            for (int i = 0; i < ISZ; ++i)
                acc = fmaf(swih[i], fcW[i * HSZ + tid], acc);
            accv = acc;
        }
        __nv_bfloat16 hi = __float2bfloat16(accv);
        Wh[j * KPL + tid] = hi;
        Wl[j * KPL + tid] = __float2bfloat16(accv - __bfloat162float(hi));
    }
    float p = 0.f;
    for (int i = tid; i < ISZ; i += 128) p = fmaf(swih[i], fcb[i], p);
    red[tid] = p;
    __syncthreads();
    for (int s = 64; s > 0; s >>= 1) {
        if (tid < s) red[tid] += red[tid + s];
        __syncthreads();
    }
    if (tid == 0) be[j] = bih[j] + bhh[j] + red[0];
}

// ---------------- tensor-core bf16 NT GEMM core -----------------------------
#define SAP 24

__device__ __forceinline__ void mma16816(float* d, const unsigned* a, const unsigned* b) {
    asm volatile(
        "mma.sync.aligned.m16n8k16.row.col.f32.bf16.bf16.f32 "
        "{%0,%1,%2,%3},{%4,%5,%6,%7},{%8,%9},{%0,%1,%2,%3};"
        : "+f"(d[0]), "+f"(d[1]), "+f"(d[2]), "+f"(d[3])
        : "r"(a[0]), "r"(a[1]), "r"(a[2]), "r"(a[3]), "r"(b[0]), "r"(b[1]));
}

__device__ __forceinline__ void ldsm_x4(unsigned* r, unsigned addr) {
    asm volatile(
        "ldmatrix.sync.aligned.m8n8.x4.shared.b16 {%0,%1,%2,%3}, [%4];"
        : "=r"(r[0]), "=r"(r[1]), "=r"(r[2]), "=r"(r[3]) : "r"(addr));
}

struct Bf16GemmSmem {
    __nv_bfloat16 Ash[2][128 * SAP];
    __nv_bfloat16 Bsh[2][64 * SAP];
    __nv_bfloat16 Bsl[2][64 * SAP];
    float red[256];
};

// A hi-only, B split (hi+lo): 2 MMAs per fragment pair. (phase A)
__device__ __forceinline__ void bf16_mainloop_a1(
    Bf16GemmSmem* sm, float d[2][4][4],
    const __nv_bfloat16* Ah, int lda,
    const __nv_bfloat16* Bh, const __nv_bfloat16* Bl, int ldb,
    int m0, int n0, int M, int N, int Kp)
{
    const int tid = threadIdx.x;
    const int lane = tid & 31;
    const int wid = tid >> 5;
    const int wy = wid & 3;
    const int wx = wid >> 2;

    const int ar = tid >> 1;
    const int ah8 = (tid & 1) * 8;
    const int bs = tid & 127;
    const int brow = bs >> 1;
    const int bh8 = (bs & 1) * 8;
    const int gm = m0 + ar;
    const int gn = n0 + brow;
    const __nv_bfloat16* srcB = (tid < 128) ? Bh : Bl;

    const unsigned aoff =
        ((unsigned)((wy * 32 + ((lane >> 3) & 1) * 8 + (lane & 7)) * SAP
                    + (lane >> 4) * 8)) * 2u;
    const unsigned boff =
        ((unsigned)((wx * 32 + ((lane >> 4) & 1) * 8 + (lane & 7)) * SAP
                    + ((lane >> 3) & 1) * 8)) * 2u;

    const unsigned ashb = (unsigned)__cvta_generic_to_shared(sm->Ash[0]);
    const unsigned bshb = (unsigned)__cvta_generic_to_shared(sm->Bsh[0]);
    const unsigned bslb = (unsigned)__cvta_generic_to_shared(sm->Bsl[0]);
    const unsigned abuf = 128 * SAP * 2;
    const unsigned bbuf = 64 * SAP * 2;
    const unsigned ni2step = 16 * SAP * 2;
    const unsigned mistep = 16 * SAP * 2;

    const uint4 zv = make_uint4(0, 0, 0, 0);
    uint4 vh = zv, vb = zv;
    if (gm < M) vh = *(const uint4*)(Ah + (size_t)gm * lda + ah8);
    if (gn < N) vb = *(const uint4*)(srcB + (size_t)gn * ldb + bh8);

    const int niter = Kp / 16;
    for (int i = 0; i < niter; ++i) {
        const unsigned cur = (unsigned)(i & 1);
        *(uint4*)&sm->Ash[cur][ar * SAP + ah8] = vh;
        __nv_bfloat16* dstB = (tid < 128) ? sm->Bsh[cur] : sm->Bsl[cur];
        *(uint4*)&dstB[brow * SAP + bh8] = vb;
        __syncthreads();

        if (i + 1 < niter) {
            int kn = (i + 1) * 16;
            vh = zv; vb = zv;
            if (gm < M) vh = *(const uint4*)(Ah + (size_t)gm * lda + kn + ah8);
            if (gn < N) vb = *(const uint4*)(srcB + (size_t)gn * ldb + kn + bh8);
        }

        unsigned bhf[4][2], blf[4][2];
        {
            unsigned r[4];
            unsigned b0 = bshb + cur * bbuf + boff;
            ldsm_x4(r, b0);
            bhf[0][0] = r[0]; bhf[0][1] = r[1]; bhf[1][0] = r[2]; bhf[1][1] = r[3];
            ldsm_x4(r, b0 + ni2step);
            bhf[2][0] = r[0]; bhf[2][1] = r[1]; bhf[3][0] = r[2]; bhf[3][1] = r[3];
            unsigned b1 = bslb + cur * bbuf + boff;
            ldsm_x4(r, b1);
            blf[0][0] = r[0]; blf[0][1] = r[1]; blf[1][0] = r[2]; blf[1][1] = r[3];
            ldsm_x4(r, b1 + ni2step);
            blf[2][0] = r[0]; blf[2][1] = r[1]; blf[3][0] = r[2]; blf[3][1] = r[3];
        }
        #pragma unroll
        for (int mi = 0; mi < 2; ++mi) {
            unsigned ahf[4];
            ldsm_x4(ahf, ashb + cur * abuf + aoff + mi * mistep);
            #pragma unroll
            for (int ni = 0; ni < 4; ++ni) {
                mma16816(d[mi][ni], ahf, bhf[ni]);
                mma16816(d[mi][ni], ahf, blf[ni]);
            }
        }
    }
    __syncthreads();
}

// A hi-only, B hi-only: 1 MMA per fragment pair. (loss GEMMs)
__device__ __forceinline__ void bf16_mainloop_11(
    Bf16GemmSmem* sm, float d[2][4][4],
    const __nv_bfloat16* Ah, int lda,
    const __nv_bfloat16* Bh, int ldb,
    int m0, int n0, int M, int N, int Kp)
{
    const int tid = threadIdx.x;
    const int lane = tid & 31;
    const int wid = tid >> 5;
    const int wy = wid & 3;
    const int wx = wid >> 2;

    const int ar = tid >> 1;
    const int ah8 = (tid & 1) * 8;
    const int brow = (tid & 127) >> 1;
    const int bh8 = (tid & 1) * 8;
    const int gm = m0 + ar;
    const int gn = n0 + brow;
    const bool bldr = (tid < 128);

    const unsigned aoff =
        ((unsigned)((wy * 32 + ((lane >> 3) & 1) * 8 + (lane & 7)) * SAP
                    + (lane >> 4) * 8)) * 2u;
    const unsigned boff =
        ((unsigned)((wx * 32 + ((lane >> 4) & 1) * 8 + (lane & 7)) * SAP
                    + ((lane >> 3) & 1) * 8)) * 2u;

    const unsigned ashb = (unsigned)__cvta_generic_to_shared(sm->Ash[0]);
    const unsigned bshb = (unsigned)__cvta_generic_to_shared(sm->Bsh[0]);
    const unsigned abuf = 128 * SAP * 2;
    const unsigned bbuf = 64 * SAP * 2;
    const unsigned ni2step = 16 * SAP * 2;
    const unsigned mistep = 16 * SAP * 2;

    const uint4 zv = make_uint4(0, 0, 0, 0);
    uint4 vh = zv, vb = zv;
    if (gm < M) vh = *(const uint4*)(Ah + (size_t)gm * lda + ah8);
    if (bldr && gn < N) vb = *(const uint4*)(Bh + (size_t)gn * ldb + bh8);

    const int niter = Kp / 16;
    for (int i = 0; i < niter; ++i) {
        const unsigned cur = (unsigned)(i & 1);
        *(uint4*)&sm->Ash[cur][ar * SAP + ah8] = vh;
        if (bldr) *(uint4*)&sm->Bsh[cur][brow * SAP + bh8] = vb;
        __syncthreads();

        if (i + 1 < niter) {
            int kn = (i + 1) * 16;
            vh = zv; vb = zv;
            if (gm < M) vh = *(const uint4*)(Ah + (size_t)gm * lda + kn + ah8);
            if (bldr && gn < N) vb = *(const uint4*)(Bh + (size_t)gn * ldb + kn + bh8);
        }

        unsigned bhf[4][2];
        {
            unsigned r[4];
            unsigned b0 = bshb + cur * bbuf + boff;
            ldsm_x4(r, b0);
            bhf[0][0] = r[0]; bhf[0][1] = r[1]; bhf[1][0] = r[2]; bhf[1][1] = r[3];
            ldsm_x4(r, b0 + ni2step);
            bhf[2][0] = r[0]; bhf[2][1] = r[1]; bhf[3][0] = r[2]; bhf[3][1] = r[3];
        }
        #pragma unroll
        for (int mi = 0; mi < 2; ++mi) {
            unsigned ahf[4];
            ldsm_x4(ahf, ashb + cur * abuf + aoff + mi * mistep);
            #pragma unroll
            for (int ni = 0; ni < 4; ++ni)
                mma16816(d[mi][ni], ahf, bhf[ni]);
        }
    }
    __syncthreads();
}

__global__ __launch_bounds__(256, 3) void gemm_bf16_store(
    const __nv_bfloat16* __restrict__ Ah, int lda,
    const __nv_bfloat16* __restrict__ Bh, const __nv_bfloat16* __restrict__ Bl, int ldb,
    const float* __restrict__ bias1, const float* __restrict__ bias2,
    float* __restrict__ C, int M, int N, int Kp)
{
    extern __shared__ char smraw[];
    Bf16GemmSmem* sm = (Bf16GemmSmem*)smraw;
    const int tid = threadIdx.x;
    const int lane = tid & 31;
    const int wid = tid >> 5;
    const int wy = wid & 3, wx = wid >> 2;
    const int g = lane >> 2, t = lane & 3;
    const int m0 = blockIdx.y * 128, n0 = blockIdx.x * 64;

    float d[2][4][4];
    #pragma unroll
    for (int mi = 0; mi < 2; ++mi)
        #pragma unroll
        for (int ni = 0; ni < 4; ++ni)
            #pragma unroll
            for (int e = 0; e < 4; ++e) d[mi][ni][e] = 0.f;

    bf16_mainloop_a1(sm, d, Ah, lda, Bh, Bl, ldb, m0, n0, M, N, Kp);

    #pragma unroll
    for (int mi = 0; mi < 2; ++mi) {
        #pragma unroll
        for (int rr = 0; rr < 2; ++rr) {
            int m = m0 + wy * 32 + mi * 16 + rr * 8 + g;
            if (m >= M) continue;
            #pragma unroll
            for (int ni = 0; ni < 4; ++ni) {
                int n = n0 + wx * 32 + ni * 8 + 2 * t;
                if (n + 1 < N) {
                    float v0 = d[mi][ni][rr * 2 + 0] + bias1[n] + bias2[n];
                    float v1 = d[mi][ni][rr * 2 + 1] + bias1[n + 1] + bias2[n + 1];
                    *(float2*)(C + (size_t)m * N + n) = make_float2(v0, v1);
                } else if (n < N) {
                    C[(size_t)m * N + n] = d[mi][ni][rr * 2 + 0] + bias1[n] + bias2[n];
                }
            }
        }
    }
}

__global__ __launch_bounds__(256, 3) void gemm_bf16_loss2(
    const __nv_bfloat16* __restrict__ Ahb,
    const __nv_bfloat16* __restrict__ Bhb,
    const float* __restrict__ fcb0, const float* __restrict__ fcb1,
    const float* __restrict__ trg, const float* __restrict__ src,
    float* __restrict__ loss, int M, int N)
{
    extern __shared__ char smraw[];
    Bf16GemmSmem* sm = (Bf16GemmSmem*)smraw;
    const int did = blockIdx.z;
    const __nv_bfloat16* Ah = Ahb + (size_t)did * M * KPL;
    const __nv_bfloat16* Bh = Bhb + (size_t)did * N * KPL;
    const float* bias = did ? fcb1 : fcb0;
    const float* ref = did ? src : trg;
    float* lossOut = did ? (loss + 0) : (loss + 1);
    const int revT = did ? TSZ : 0;

    const int tid = threadIdx.x;
    const int lane = tid & 31;
    const int wid = tid >> 5;
    const int wy = wid & 3, wx = wid >> 2;
    const int g = lane >> 2, t = lane & 3;
    const int m0 = blockIdx.y * 128, n0 = blockIdx.x * 64;

    float d[2][4][4];
    #pragma unroll
    for (int mi = 0; mi < 2; ++mi)
        #pragma unroll
        for (int ni = 0; ni < 4; ++ni)
            #pragma unroll
            for (int e = 0; e < 4; ++e) d[mi][ni][e] = 0.f;

    bf16_mainloop_11(sm, d, Ah, KPL, Bh, KPL, m0, n0, M, N, KPL);

    float ls = 0.f;
    #pragma unroll
    for (int mi = 0; mi < 2; ++mi) {
        #pragma unroll
        for (int rr = 0; rr < 2; ++rr) {
            int m = m0 + wy * 32 + mi * 16 + rr * 8 + g;
            if (m >= M) continue;
            const float* rrow;
            if (revT > 0) {
                int b = m / revT, tt = m - b * revT;
                rrow = ref + ((size_t)b * revT + (revT - 1 - tt)) * N;
            } else {
                rrow = ref + (size_t)m * N;
            }
            #pragma unroll
            for (int ni = 0; ni < 4; ++ni) {
                int n = n0 + wx * 32 + ni * 8 + 2 * t;
                #pragma unroll
                for (int e = 0; e < 2; ++e) {
                    if (n + e < N) {
                        float v = d[mi][ni][rr * 2 + e] + bias[n + e];
                        float diff = v - rrow[n + e];
                        ls = fmaf(diff, diff, ls);
                    }
                }
            }
        }
    }
    sm->red[tid] = ls;
    __syncthreads();
    for (int s = 128; s > 0; s >>= 1) {
        if (tid < s) sm->red[tid] += sm->red[tid + s];
        __syncthreads();
    }
    if (tid == 0) atomicAdd(lossOut, sm->red[0]);
}

// ---- MMA recurrences: 16 batches/CTA, 320 threads, 10 warps ---------------
#define DNT 320
#define DNB 16
#define APW 120                   // A pitch (bf16)
#define GPW 404                   // sG pitch (fp32)
// smem: Wh 89600 | Wl 89600 | Ab 2*16*120*2=7680 | sG 16*404*4=25856
#define DEC_SMEM_B (89600 + 89600 + 7680 + 25856)

__device__ __forceinline__ void dec_copyW(
    char* smem, const __nv_bfloat16* gh, const __nv_bfloat16* gl, int tid)
{
    uint4* dh = (uint4*)smem;
    uint4* dl = (uint4*)(smem + 89600);
    const uint4* sh = (const uint4*)gh;
    const uint4* sl = (const uint4*)gl;
    for (int i = tid; i < 5600; i += DNT) { dh[i] = sh[i]; dl[i] = sl[i]; }
}

// ---- encoder MMA recurrence: per-step additive term = X[t] (incl. biases) --
__global__ __launch_bounds__(DNT, 1) void rnn_encm(
    const __nv_bfloat16* __restrict__ ewhh, const __nv_bfloat16* __restrict__ ewhl,
    const float* __restrict__ X,
    float* __restrict__ hf, float* __restrict__ cf)
{
    extern __shared__ char smem[];
    __nv_bfloat16* Ab = (__nv_bfloat16*)(smem + 179200);
    float* sG = (float*)(smem + 186880);
    const int tid = threadIdx.x;
    const int lane = tid & 31;
    const int wid = tid >> 5;
    const int b0 = blockIdx.x * DNB;

    dec_copyW(smem, ewhh, ewhl, tid);
    {
        const uint4 zv = make_uint4(0, 0, 0, 0);
        for (int i = tid; i < 480; i += DNT) ((uint4*)Ab)[i] = zv;  // h0 = 0
    }

    const int ngrp = (wid < 5) ? 3 : 2;
    int grp[3];
    #pragma unroll
    for (int gi = 0; gi < 3; ++gi) grp[gi] = wid + gi * 10;
    const int c2 = (lane & 3) * 2;
    const int r0w = lane >> 2;
    // X row pointers for the two output rows this lane covers
    int bbr0 = b0 + r0w;      if (bbr0 > BSZ - 1) bbr0 = BSZ - 1;
    int bbr8 = b0 + r0w + 8;  if (bbr8 > BSZ - 1) bbr8 = BSZ - 1;
    const float* Xr0 = X + (size_t)bbr0 * TSZ * G4;
    const float* Xr8 = X + (size_t)bbr8 * TSZ * G4;

    const unsigned aoff =
        ((unsigned)(((lane & 7) + ((lane >> 3) & 1) * 8) * APW)) * 2u
        + (unsigned)((lane >> 4) * 16);
    const unsigned boff =
        ((unsigned)((((lane >> 4) & 1) * 8 + (lane & 7)) * KPL)) * 2u
        + (unsigned)(((lane >> 3) & 1) * 16);
    const unsigned wbh = (unsigned)__cvta_generic_to_shared(smem);
    const unsigned abA = (unsigned)__cvta_generic_to_shared(Ab);
    const unsigned abufB = 16 * APW * 2;
    const unsigned grpstep = 16 * KPL * 2;
    const unsigned wlo = 89600;

    int ck[5], cb[5];
    bool cv[5], cw[5];
    float cc[5], hl[5];
    #pragma unroll
    for (int q = 0; q < 5; ++q) {
        int item = q * DNT + tid;
        bool v = item < DNB * 100;
        ck[q] = v ? (item % 100) : 0;
        cb[q] = v ? (item / 100) : 0;
        cv[q] = v;
        cw[q] = v && (b0 + cb[q] < BSZ);
        cc[q] = 0.f;
        hl[q] = 0.f;
    }
    __syncthreads();

    for (int t = 0; t < TSZ; ++t) {
        {
            // prefetch this step's X values (overlaps the MMA stream)
            float2 xv0[3][2], xv8[3][2];
            #pragma unroll
            for (int gi = 0; gi < 3; ++gi) {
                if (gi < ngrp) {
                    #pragma unroll
                    for (int st = 0; st < 2; ++st) {
                        int n = grp[gi] * 16 + st * 8 + c2;
                        xv0[gi][st] = *(const float2*)&Xr0[(size_t)t * G4 + n];
                        xv8[gi][st] = *(const float2*)&Xr8[(size_t)t * G4 + n];
                    }
                }
            }

            float d[3][2][4];
            #pragma unroll
            for (int gi = 0; gi < 3; ++gi)
                #pragma unroll
                for (int st = 0; st < 2; ++st)
                    #pragma unroll
                    for (int e = 0; e < 4; ++e) d[gi][st][e] = 0.f;

            const unsigned ab = abA + (unsigned)(t & 1) * abufB + aoff;
            #pragma unroll
            for (int k = 0; k < 7; ++k) {
                unsigned ah[4];
                ldsm_x4(ah, ab + k * 32);
                #pragma unroll
                for (int gi = 0; gi < 3; ++gi) {
                    if (gi < ngrp) {
                        unsigned bb = wbh + (unsigned)grp[gi] * grpstep + boff + k * 32;
                        unsigned bf[4];
                        ldsm_x4(bf, bb);
                        mma16816(d[gi][0], ah, bf + 0);
                        mma16816(d[gi][1], ah, bf + 2);
                        ldsm_x4(bf, bb + wlo);
                        mma16816(d[gi][0], ah, bf + 0);
                        mma16816(d[gi][1], ah, bf + 2);
                    }
                }
            }
            #pragma unroll
            for (int gi = 0; gi < 3; ++gi) {
                if (gi < ngrp) {
                    #pragma unroll
                    for (int st = 0; st < 2; ++st) {
                        int n = grp[gi] * 16 + st * 8 + c2;
                        *(float2*)&sG[r0w * GPW + n] =
                            make_float2(d[gi][st][0] + xv0[gi][st].x,
                                        d[gi][st][1] + xv0[gi][st].y);
                        *(float2*)&sG[(r0w + 8) * GPW + n] =
                            make_float2(d[gi][st][2] + xv8[gi][st].x,
                                        d[gi][st][3] + xv8[gi][st].y);
                    }
                }
            }
        }
        __syncthreads();
        {
            __nv_bfloat16* Adst = Ab + ((t + 1) & 1) * (16 * APW);
            #pragma unroll
            for (int q = 0; q < 5; ++q) {
                if (cv[q]) {
                    int k = ck[q], b = cb[q];
                    const float* gb = sG + b * GPW;
                    float gi = sigf(gb[k]);
                    float gf = sigf(gb[100 + k]);
                    float gg = tanhf_fast(gb[200 + k]);
                    float go = sigf(gb[300 + k]);
                    float c = fmaf(gf, cc[q], gi * gg);
                    cc[q] = c;
                    float h = go * tanhf_fast(c);
                    hl[q] = h;
                    Adst[b * APW + k] = __float2bfloat16(h);
                }
            }
        }
        __syncthreads();
    }

    #pragma unroll
    for (int q = 0; q < 5; ++q) {
        if (cw[q]) {
            hf[(b0 + cb[q]) * HSZ + ck[q]] = hl[q];
            cf[(b0 + cb[q]) * HSZ + ck[q]] = cc[q];
        }
    }
}

// ---- MMA decoders: grid (63,2) = 126 CTAs ----------------------------------
__global__ __launch_bounds__(DNT, 1) void rnn_dec2(
    const __nv_bfloat16* __restrict__ whhh, const __nv_bfloat16* __restrict__ whhl,
    const __nv_bfloat16* __restrict__ weffh, const __nv_bfloat16* __restrict__ weffl,
    const float* __restrict__ bih0, const float* __restrict__ bhh0,
    const float* __restrict__ bih1, const float* __restrict__ bhh1,
    const float* __restrict__ beffbase,
    const float* __restrict__ h0, const float* __restrict__ c0,
    __nv_bfloat16* __restrict__ hdhb)
{
    extern __shared__ char smem[];
    __nv_bfloat16* Ab = (__nv_bfloat16*)(smem + 179200);
    float* sG = (float*)(smem + 186880);
    const int tid = threadIdx.x;
    const int lane = tid & 31;
    const int wid = tid >> 5;
    const int b0 = blockIdx.x * DNB;
    const int did = blockIdx.y;

    const size_t woff = (size_t)did * G4 * KPL;
    const float* beff = beffbase + (size_t)did * G4;
    const float* bih = did ? bih1 : bih0;
    const float* bhh = did ? bhh1 : bhh0;
    __nv_bfloat16* hdh = hdhb + (size_t)did * BSZ * TSZ * KPL;

    dec_copyW(smem, whhh + woff, whhl + woff, tid);
    {
        const uint4 zv = make_uint4(0, 0, 0, 0);
        for (int i = tid; i < 480; i += DNT) ((uint4*)Ab)[i] = zv;
    }

    const int ngrp = (wid < 5) ? 3 : 2;
    int grp[3];
    #pragma unroll
    for (int gi = 0; gi < 3; ++gi) grp[gi] = wid + gi * 10;
    const int c2 = (lane & 3) * 2;
    const int r0w = lane >> 2;
    float bE[3][2][2], bZ[3][2][2];
    #pragma unroll
    for (int gi = 0; gi < 3; ++gi) {
        #pragma unroll
        for (int st = 0; st < 2; ++st) {
            bE[gi][st][0] = bE[gi][st][1] = 0.f;
            bZ[gi][st][0] = bZ[gi][st][1] = 0.f;
            if (gi < ngrp) {
                int n = grp[gi] * 16 + st * 8 + c2;
                bE[gi][st][0] = beff[n];
                bE[gi][st][1] = beff[n + 1];
                bZ[gi][st][0] = bih[n] + bhh[n];
                bZ[gi][st][1] = bih[n + 1] + bhh[n + 1];
            }
        }
    }
    const unsigned aoff =
        ((unsigned)(((lane & 7) + ((lane >> 3) & 1) * 8) * APW)) * 2u
        + (unsigned)((lane >> 4) * 16);
    const unsigned boff =
        ((unsigned)((((lane >> 4) & 1) * 8 + (lane & 7)) * KPL)) * 2u
        + (unsigned)(((lane >> 3) & 1) * 16);
    const unsigned wbh = (unsigned)__cvta_generic_to_shared(smem);
    const unsigned abA = (unsigned)__cvta_generic_to_shared(Ab);
    const unsigned abufB = 16 * APW * 2;
    const unsigned grpstep = 16 * KPL * 2;
    const unsigned wlo = 89600;

    int ck[5], cb[5];
    bool cv[5], cw[5];
    float cc[5];
    __nv_bfloat16* outh[5];
    #pragma unroll
    for (int q = 0; q < 5; ++q) {
        int item = q * DNT + tid;
        bool v = item < DNB * 100;
        int k = v ? (item % 100) : 0;
        int b = v ? (item / 100) : 0;
        ck[q] = k; cb[q] = b; cv[q] = v;
        cw[q] = v && (b0 + b < BSZ);
        cc[q] = 0.f;
        outh[q] = hdh + ((size_t)(b0 + b) * TSZ) * KPL + k;
    }
    #pragma unroll
    for (int q = 0; q < 5; ++q) {
        if (cv[q]) {
            int bb = b0 + cb[q]; if (bb > BSZ - 1) bb = BSZ - 1;
            Ab[cb[q] * APW + ck[q]] = __float2bfloat16(h0[bb * HSZ + ck[q]]);
            cc[q] = c0[bb * HSZ + ck[q]];
        }
    }
    __syncthreads();

    for (int t = 0; t < TSZ; ++t) {
        {
            float d[3][2][4];
            #pragma unroll
            for (int gi = 0; gi < 3; ++gi)
                #pragma unroll
                for (int st = 0; st < 2; ++st)
                    #pragma unroll
                    for (int e = 0; e < 4; ++e) d[gi][st][e] = 0.f;

            const unsigned ab = abA + (unsigned)(t & 1) * abufB + aoff;
            #pragma unroll
            for (int k = 0; k < 7; ++k) {
                unsigned ah[4];
                ldsm_x4(ah, ab + k * 32);
                #pragma unroll
                for (int gi = 0; gi < 3; ++gi) {
                    if (gi < ngrp) {
                        unsigned bb = wbh + (unsigned)grp[gi] * grpstep + boff + k * 32;
                        unsigned bf[4];
                        ldsm_x4(bf, bb);
                        mma16816(d[gi][0], ah, bf + 0);
                        mma16816(d[gi][1], ah, bf + 2);
                        ldsm_x4(bf, bb + wlo);
                        mma16816(d[gi][0], ah, bf + 0);
                        mma16816(d[gi][1], ah, bf + 2);
                    }
                }
            }
            #pragma unroll
            for (int gi = 0; gi < 3; ++gi) {
                if (gi < ngrp) {
                    #pragma unroll
                    for (int st = 0; st < 2; ++st) {
                        int n = grp[gi] * 16 + st * 8 + c2;
                        float ba = (t == 0) ? bZ[gi][st][0] : bE[gi][st][0];
                        float bb2 = (t == 0) ? bZ[gi][st][1] : bE[gi][st][1];
                        *(float2*)&sG[r0w * GPW + n] =
                            make_float2(d[gi][st][0] + ba, d[gi][st][1] + bb2);
                        *(float2*)&sG[(r0w + 8) * GPW + n] =
                            make_float2(d[gi][st][2] + ba, d[gi][st][3] + bb2);
                    }
                }
            }
        }
        __syncthreads();
        {
            __nv_bfloat16* Adst = Ab + ((t + 1) & 1) * (16 * APW);
            #pragma unroll
            for (int q = 0; q < 5; ++q) {
                if (cv[q]) {
                    int k = ck[q], b = cb[q];
                    const float* gb = sG + b * GPW;
                    float gi = sigf(gb[k]);
                    float gf = sigf(gb[100 + k]);
                    float gg = tanhf_fast(gb[200 + k]);
                    float go = sigf(gb[300 + k]);
                    float c = fmaf(gf, cc[q], gi * gg);
                    cc[q] = c;
                    float h = go * tanhf_fast(c);
                    __nv_bfloat16 hb = __float2bfloat16(h);
                    Adst[b * APW + k] = hb;
                    if (cw[q]) outh[q][(size_t)t * KPL] = hb;
                }
            }
        }
        if (t == 0)
            dec_copyW(smem, weffh + woff, weffl + woff, tid);
        __syncthreads();
    }
}

// ---------------- launch ----------------------------------------------------
extern "C" void kernel_launch(void* const* d_in, const int* in_sizes, int n_in,
                              void* d_out, int out_size)
{
    const float* src     = (const float*)d_in[0];
    const float* trg     = (const float*)d_in[1];
    const float* enc_Wih = (const float*)d_in[2];
    const float* enc_Whh = (const float*)d_in[3];
    const float* enc_bih = (const float*)d_in[4];
    const float* enc_bhh = (const float*)d_in[5];
    const float* pd_Wih  = (const float*)d_in[6];
    const float* pd_Whh  = (const float*)d_in[7];
    const float* pd_bih  = (const float*)d_in[8];
    const float* pd_bhh  = (const float*)d_in[9];
    const float* pd_fcW  = (const float*)d_in[10];
    const float* pd_fcb  = (const float*)d_in[11];
    const float* rd_Wih  = (const float*)d_in[12];
    const float* rd_Whh  = (const float*)d_in[13];
    const float* rd_bih  = (const float*)d_in[14];
    const float* rd_bhh  = (const float*)d_in[15];
    const float* rd_fcW  = (const float*)d_in[16];
    const float* rd_fcb  = (const float*)d_in[17];
    float* out = (float*)d_out;

    float *pX, *pHenc, *pCenc, *pBeff, *pLoss;
    __nv_bfloat16 *pSrch, *pWihh, *pWihl, *pFcwh, *pHdh;
    __nv_bfloat16 *pWeffh, *pWeffl, *pWhhh, *pWhhl, *pEwhh, *pEwhl;
    cudaGetSymbolAddress((void**)&pX,    g_X);
    cudaGetSymbolAddress((void**)&pHenc, g_henc);
    cudaGetSymbolAddress((void**)&pCenc, g_cenc);
    cudaGetSymbolAddress((void**)&pBeff, g_beff);
    cudaGetSymbolAddress((void**)&pLoss, g_loss);
    cudaGetSymbolAddress((void**)&pSrch, g_srch);
    cudaGetSymbolAddress((void**)&pWihh, g_wihh);
    cudaGetSymbolAddress((void**)&pWihl, g_wihl);
    cudaGetSymbolAddress((void**)&pFcwh, g_fcwh);
    cudaGetSymbolAddress((void**)&pHdh,  g_hdh);
    cudaGetSymbolAddress((void**)&pWeffh, g_weffh);
    cudaGetSymbolAddress((void**)&pWeffl, g_weffl);
    cudaGetSymbolAddress((void**)&pWhhh,  g_whhh);
    cudaGetSymbolAddress((void**)&pWhhl,  g_whhl);
    cudaGetSymbolAddress((void**)&pEwhh,  g_ewhh);
    cudaGetSymbolAddress((void**)&pEwhl,  g_ewhl);

    const int SMEM_GEMM = (int)sizeof(Bf16GemmSmem);
    cudaFuncSetAttribute(rnn_encm, cudaFuncAttributeMaxDynamicSharedMemorySize, DEC_SMEM_B);
    cudaFuncSetAttribute(rnn_dec2, cudaFuncAttributeMaxDynamicSharedMemorySize, DEC_SMEM_B);
    cudaFuncSetAttribute(gemm_bf16_store, cudaFuncAttributeMaxDynamicSharedMemorySize, SMEM_GEMM);
    cudaFuncSetAttribute(gemm_bf16_loss2, cudaFuncAttributeMaxDynamicSharedMemorySize, SMEM_GEMM);

    const int DEC_BLOCKS = (BSZ + DNB - 1) / DNB;   // 63
    const int MROWS = BSZ * TSZ;                    // 100000

    // prep (launch #4 = phase-A tensor GEMM, the profiled slot)
    cvt_hi_t<ISZ, KPA><<<(MROWS * (KPA / 4) + 255) / 256, 256>>>(src, pSrch, MROWS);
    cvt_split_t<ISZ, KPA><<<(G4 * (KPA / 4) + 255) / 256, 256>>>(enc_Wih, pWihh, pWihl, G4);
    {
        dim3 grid(G4, 2);
        fold2_kernel<<<grid, 128>>>(pd_Wih, pd_Whh, pd_fcW, pd_fcb, pd_bih, pd_bhh,
                                    rd_Wih, rd_Whh, rd_fcW, rd_fcb, rd_bih, rd_bhh,
                                    pWeffh, pWeffl, pBeff, pLoss);
    }

    // phase A (tensor cores)
    {
        dim3 grid((G4 + 63) / 64, (MROWS + 127) / 128);
        gemm_bf16_store<<<grid, 256, SMEM_GEMM>>>(pSrch, KPA, pWihh, pWihl, KPA,
                                                  enc_bih, enc_bhh, pX, MROWS, G4, KPA);
    }

    // encoder Whh split (needed by encoder MMA)
    cvt_split_t<HSZ, KPL><<<(G4 * (KPL / 4) + 255) / 256, 256>>>(enc_Whh, pEwhh, pEwhl, G4);

    // encoder MMA recurrence: 63 CTAs
    rnn_encm<<<DEC_BLOCKS, DNT, DEC_SMEM_B>>>(pEwhh, pEwhl, pX, pHenc, pCenc);

    // conversions for decoders + losses
    cvt_hi_t<HSZ, KPL><<<(ISZ * (KPL / 4) + 255) / 256, 256>>>(pd_fcW, pFcwh, ISZ);
    cvt_hi_t<HSZ, KPL><<<(ISZ * (KPL / 4) + 255) / 256, 256>>>(rd_fcW, pFcwh + ISZ * KPL, ISZ);
    cvt_split_t<HSZ, KPL><<<(G4 * (KPL / 4) + 255) / 256, 256>>>(pd_Whh, pWhhh, pWhhl, G4);
    cvt_split_t<HSZ, KPL><<<(G4 * (KPL / 4) + 255) / 256, 256>>>(rd_Whh, pWhhh + G4 * KPL,
                                                                 pWhhl + G4 * KPL, G4);

    // MMA decoders: 126 CTAs, one wave
    {
        dim3 grid(DEC_BLOCKS, 2);
        rnn_dec2<<<grid, DNT, DEC_SMEM_B>>>(pWhhh, pWhhl, pWeffh, pWeffl,
                                            pd_bih, pd_bhh, rd_bih, rd_bhh,
                                            pBeff, pHenc, pCenc, pHdh);
    }

    // merged losses
    {
        dim3 grid((ISZ + 63) / 64, (MROWS + 127) / 128, 2);
        gemm_bf16_loss2<<<grid, 256, SMEM_GEMM>>>(pHdh, pFcwh,
                                                  pd_fcb, rd_fcb, trg, src,
                                                  pLoss, MROWS, ISZ);
    }

    finalize_kernel<<<1, 1>>>(pLoss, out, 1.0f / (float)(BSZ * TSZ * ISZ));
}